// round 9
// baseline (speedup 1.0000x reference)
#include <cuda_runtime.h>
#include <cuda_bf16.h>
#include <math.h>
#include <stdint.h>

typedef unsigned int u32;
typedef unsigned long long u64;

#define BB 8
#define NN 256
#define DD 512
#define HH 16
#define KK 4
#define FFN 2048
#define ROWS (BB*NN)          // 2048
#define BH (BB*HH)            // 128

// ---------------- scratch globals --------------------------------------------
__device__ u32 g_xw_h[ROWS*256],  g_xw_l[ROWS*256];
__device__ u32 g_wqT_h[512*256],  g_wqT_l[512*256];
__device__ u32 g_wkT_h[512*256],  g_wkT_l[512*256];
__device__ u32 g_wvT_h[512*256],  g_wvT_l[512*256];
__device__ u32 g_w1T_h[512*1024], g_w1T_l[512*1024];
__device__ u32 g_w2T_h[512*256],  g_w2T_l[512*256];
__device__ u32 g_wf1T_h[2048*256], g_wf1T_l[2048*256];
__device__ u32 g_wf2T_h[512*1024], g_wf2T_l[512*1024];
__device__ u32 g_qp_h[BH*4096], g_qp_l[BH*4096];
__device__ u32 g_kp_h[BH*4096], g_kp_l[BH*4096];
__device__ u32 g_vp_h[BH*4096], g_vp_l[BH*4096];
__device__ u32 g_m2_h[ROWS*1024], g_m2_l[ROWS*1024];
__device__ u32 g_h1_h[ROWS*256],  g_h1_l[ROWS*256];
__device__ float g_t[ROWS*DD];
__device__ float g_t2[ROWS*DD];
__device__ float g_y[ROWS*DD];
__device__ u32 g_y_h[ROWS*256],   g_y_l[ROWS*256];
__device__ u32 g_f1_h[ROWS*1024], g_f1_l[ROWS*1024];
__device__ u32 g_allow[BB*KK*NN*8];

// ---------------- helpers ----------------------------------------------------
__device__ __forceinline__ u32 packbf(float a, float b) {
    __nv_bfloat16 ha = __float2bfloat16_rn(a);
    __nv_bfloat16 hb = __float2bfloat16_rn(b);
    return (u32)__bfloat16_as_ushort(ha) | ((u32)__bfloat16_as_ushort(hb) << 16);
}
__device__ __forceinline__ float bfval(float x) {
    return __bfloat162float(__float2bfloat16_rn(x));
}
__device__ __forceinline__ void split_pair(float a, float b, u32& hi, u32& lo) {
    float ah = bfval(a), bh_ = bfval(b);
    hi = packbf(a, b);
    lo = packbf(a - ah, b - bh_);
}

#define MMA16816(d, a, b) \
    asm volatile("mma.sync.aligned.m16n8k16.row.col.f32.bf16.bf16.f32 " \
        "{%0,%1,%2,%3},{%4,%5,%6,%7},{%8,%9},{%0,%1,%2,%3};" \
        : "+f"(d[0]), "+f"(d[1]), "+f"(d[2]), "+f"(d[3]) \
        : "r"(a[0]), "r"(a[1]), "r"(a[2]), "r"(a[3]), "r"(b[0]), "r"(b[1]))

__device__ __forceinline__ u32 smem_u32(const void* p) {
    u32 a;
    asm("{ .reg .u64 t; cvta.to.shared.u64 t, %1; cvt.u32.u64 %0, t; }"
        : "=r"(a) : "l"(p));
    return a;
}
__device__ __forceinline__ void cp16(u32 saddr, const void* gptr) {
    asm volatile("cp.async.cg.shared.global [%0], [%1], 16;"
                 :: "r"(saddr), "l"(gptr));
}

// ---------------- merged prep kernel -----------------------------------------
struct PrepArgs {
    const float* wsrc[7];
    u32* wdh[7];
    u32* wdl[7];
    int wK[7], wN[7];
    int tbase[8];
    const float* x; u32* xh; u32* xl;
    const int* mask; const float* dist; const float* dbar; u32* allow;
};

__global__ __launch_bounds__(256) void prep_all(PrepArgs pa)
{
    const int bx = blockIdx.x;
    const int tid = threadIdx.x;
    if (bx < 4096) {
        int task = 0;
        while (bx >= pa.tbase[task + 1]) task++;
        int tIdx = bx - pa.tbase[task];
        int K = pa.wK[task], N = pa.wN[task];
        int ntx = N >> 5;
        int n0 = (tIdx % ntx) * 32, k0 = (tIdx / ntx) * 32;
        __shared__ float tile[32][33];
        int tx = tid & 31, ty = tid >> 5;
        const float* src = pa.wsrc[task];
#pragma unroll
        for (int r = 0; r < 32; r += 8)
            tile[ty + r][tx] = src[(size_t)(k0 + ty + r) * N + n0 + tx];
        __syncthreads();
        int Kw = K >> 1;
        u32* dh = pa.wdh[task];
        u32* dl = pa.wdl[task];
#pragma unroll
        for (int r = 0; r < 32; r += 8) {
            int n = ty + r;
            if (tx < 16) {
                float a = tile[2 * tx][n], b = tile[2 * tx + 1][n];
                u32 h, l; split_pair(a, b, h, l);
                dh[(size_t)(n0 + n) * Kw + (k0 >> 1) + tx] = h;
                dl[(size_t)(n0 + n) * Kw + (k0 >> 1) + tx] = l;
            }
        }
    } else if (bx < 6144) {
        int idx = (bx - 4096) * 256 + tid;
        float2 v = ((const float2*)pa.x)[idx];
        u32 h, l; split_pair(v.x, v.y, h, l);
        pa.xh[idx] = h; pa.xl[idx] = l;
    } else {
        int idx = (bx - 6144) * 256 + tid;            // [b][row][ww]
        int ww = idx & 7, row = (idx >> 3) & 255, b = idx >> 11;
        float d0 = pa.dbar[0], d1 = pa.dbar[1], d2 = pa.dbar[2], d3 = pa.dbar[3];
        u32 w0 = 0, w1 = 0, w2 = 0, w3 = 0;
        for (int bit = 0; bit < 32; bit++) {
            int col = ww * 32 + bit;
            bool pad = pa.mask[((size_t)b * 256 + row) * 256 + col] != 0;
            float nd = 0.f;
            if (row > 0 && col > 0)
                nd = pa.dist[((size_t)b * 255 + row - 1) * 255 + col - 1];
            if (pad) {
                if (nd < d0) w0 |= 1u << bit;
                if (nd < d1) w1 |= 1u << bit;
                if (nd < d2) w2 |= 1u << bit;
                if (nd < d3) w3 |= 1u << bit;
            }
        }
        size_t base = ((size_t)b * 4 * 256 + row) * 8 + ww;
        pa.allow[base] = w0;
        pa.allow[base + 2048] = w1;
        pa.allow[base + 4096] = w2;
        pa.allow[base + 6144] = w3;
    }
}

// ---------------- GEMM: 128x64 tile, BK=32, 3-stage cp.async pipeline --------
#define ASTR 20
#define A_PL (128*ASTR)                    // 2560 words per A plane
#define B_PL (64*ASTR)                     // 1280 words per B plane
#define STG_W (2*A_PL + 2*B_PL)            // 7680 words per stage
#define NSTG 3
#define GEMM_SMEM (NSTG * STG_W * 4)       // 92160 B

struct GemmOp {
    const u32 *Ah, *Al;
    const u32 *Bh[3], *Bl[3];
    const float* bias[3];
    float* Cf[3];
    u32 *Ch[3], *Cl[3];
    int N, K, act, mode, ksplit;           // mode: 0 f32+bias, 1 planes, 2 head planes, 3 raw f32
};

__global__ __launch_bounds__(256, 2) void gemm_mma2(GemmOp op)
{
    extern __shared__ u32 sm[];
    const u32 smb = smem_u32(sm);
    const int z = blockIdx.z;
    const int zb = op.ksplit ? 0 : z;
    const u32* __restrict__ Ah = op.Ah;
    const u32* __restrict__ Al = op.Al;
    const u32* __restrict__ Bh = op.Bh[zb];
    const u32* __restrict__ Bl = op.Bl[zb];
    const int N = op.N, K = op.K, act = op.act, mode = op.mode;
    const int Kw = K >> 1;
    const int Keff = op.ksplit ? (K >> 1) : K;
    const int koffw = op.ksplit ? z * (K >> 2) : 0;
    const int nkt = Keff >> 5;

    const int tid = threadIdx.x;
    const int lane = tid & 31, wid = tid >> 5;
    const int wm = wid & 3, wn = wid >> 2;
    const int g = lane >> 2, t = lane & 3;
    const int m0 = blockIdx.y * 128, n0 = blockIdx.x * 64;

    float acc[2][4][4];
#pragma unroll
    for (int mt = 0; mt < 2; mt++)
#pragma unroll
        for (int nt = 0; nt < 4; nt++)
#pragma unroll
            for (int i = 0; i < 4; i++) acc[mt][nt][i] = 0.f;

    // A: u = tid*2 + j -> row u>>2, quad u&3 (2 uint4 per plane per thread)
    // B: row tid>>2, quad tid&3 (1 uint4 per plane per thread)
    const int ar0 = (tid * 2) >> 2, aq0 = (tid * 2) & 3;
    const int ar1 = (tid * 2 + 1) >> 2, aq1 = (tid * 2 + 1) & 3;
    const int bn = tid >> 2, bq = tid & 3;

    auto issue = [&](int s, int kt) {
        const u32 st = smb + s * (STG_W * 4);
        const int ktw = koffw + kt * 16;
        size_t g0 = (size_t)(m0 + ar0) * Kw + ktw + aq0 * 4;
        size_t g1 = (size_t)(m0 + ar1) * Kw + ktw + aq1 * 4;
        u32 s0a = st + (ar0 * ASTR + aq0 * 4) * 4;
        u32 s1a = st + (ar1 * ASTR + aq1 * 4) * 4;
        cp16(s0a, Ah + g0);
        cp16(s1a, Ah + g1);
        cp16(s0a + A_PL * 4, Al + g0);
        cp16(s1a + A_PL * 4, Al + g1);
        size_t gb = (size_t)(n0 + bn) * Kw + ktw + bq * 4;
        u32 sb = st + (2 * A_PL + bn * ASTR + bq * 4) * 4;
        cp16(sb, Bh + gb);
        cp16(sb + B_PL * 4, Bl + gb);
        asm volatile("cp.async.commit_group;");
    };

    issue(0, 0);
    if (nkt > 1) issue(1, 1);

    for (int kt = 0; kt < nkt; kt++) {
        if (kt + 1 < nkt) {
            asm volatile("cp.async.wait_group 1;");
        } else {
            asm volatile("cp.async.wait_group 0;");
        }
        __syncthreads();

        const u32* As_h = sm + (kt % NSTG) * STG_W;
        const u32* As_l = As_h + A_PL;
        const u32* Bs_h = As_h + 2 * A_PL;
        const u32* Bs_l = Bs_h + B_PL;
#pragma unroll
        for (int sel = 0; sel < 2; sel++) {
            const int ko = sel * 8;
            u32 ah[2][4], al[2][4];
#pragma unroll
            for (int mt = 0; mt < 2; mt++) {
                int row = wm * 32 + mt * 16 + g;
                int b0 = row * ASTR + ko + t;
                int b8 = (row + 8) * ASTR + ko + t;
                ah[mt][0] = As_h[b0];     ah[mt][1] = As_h[b8];
                ah[mt][2] = As_h[b0 + 4]; ah[mt][3] = As_h[b8 + 4];
                al[mt][0] = As_l[b0];     al[mt][1] = As_l[b8];
                al[mt][2] = As_l[b0 + 4]; al[mt][3] = As_l[b8 + 4];
            }
#pragma unroll
            for (int nt = 0; nt < 4; nt++) {
                int n = wn * 32 + nt * 8 + g;
                int bb = n * ASTR + ko + t;
                u32 bhf[2] = {Bs_h[bb], Bs_h[bb + 4]};
                u32 blf[2] = {Bs_l[bb], Bs_l[bb + 4]};
#pragma unroll
                for (int mt = 0; mt < 2; mt++) {
                    MMA16816(acc[mt][nt], ah[mt], bhf);
                    MMA16816(acc[mt][nt], ah[mt], blf);
                    MMA16816(acc[mt][nt], al[mt], bhf);
                }
            }
        }

        if (kt + 2 < nkt) issue((kt + 2) % NSTG, kt + 2);
    }

    // epilogue
    const float* bias = op.bias[zb];
    float* Cf = op.Cf[z];
    u32* Ch = op.Ch[z];
    u32* Cl = op.Cl[z];
#pragma unroll
    for (int mt = 0; mt < 2; mt++) {
#pragma unroll
        for (int nt = 0; nt < 4; nt++) {
            int col = n0 + wn * 32 + nt * 8 + 2 * t;
            float bia0 = 0.f, bia1 = 0.f;
            if (mode != 3) { bia0 = bias[col]; bia1 = bias[col + 1]; }
#pragma unroll
            for (int half = 0; half < 2; half++) {
                int row = m0 + wm * 32 + mt * 16 + g + half * 8;
                float c0 = acc[mt][nt][half * 2 + 0] + bia0;
                float c1 = acc[mt][nt][half * 2 + 1] + bia1;
                if (act == 1 && mode != 3) {
                    c0 = c0 / (1.f + expf(-c0)); c1 = c1 / (1.f + expf(-c1));
                } else if (act == 2 && mode != 3) {
                    c0 = c0 * normcdff(c0); c1 = c1 * normcdff(c1);
                }
                if (mode == 0 || mode == 3) {
                    *(float2*)(Cf + (size_t)row * N + col) = make_float2(c0, c1);
                } else {
                    u32 h, l; split_pair(c0, c1, h, l);
                    size_t w;
                    if (mode == 2)
                        w = (size_t)((row >> 8) * 16 + (col >> 5)) * 4096
                          + (size_t)(row & 255) * 16 + ((col & 31) >> 1);
                    else
                        w = ((size_t)row * N + col) >> 1;
                    Ch[w] = h; Cl[w] = l;
                }
            }
        }
    }
}

// ---------------- combine split-K partials + bias + silu -> planes -----------
__global__ __launch_bounds__(256) void combine_silu(
    const float* __restrict__ p0, const float* __restrict__ p1,
    const float* __restrict__ bias, u32* __restrict__ oh, u32* __restrict__ ol)
{
    int i = blockIdx.x * 256 + threadIdx.x;       // word over [ROWS][256]
    int col = (i & 255) * 2;
    float2 a = ((const float2*)p0)[i];
    float2 b = ((const float2*)p1)[i];
    float c0 = a.x + b.x + bias[col];
    float c1 = a.y + b.y + bias[col + 1];
    c0 = c0 / (1.f + expf(-c0));
    c1 = c1 / (1.f + expf(-c1));
    u32 h, l; split_pair(c0, c1, h, l);
    oh[i] = h; ol[i] = l;
}

// ---------------- fused multi-scale attention via HMMA -----------------------
__global__ __launch_bounds__(256) void attn_mma(
    const u32* __restrict__ qh, const u32* __restrict__ ql,
    const u32* __restrict__ kh, const u32* __restrict__ kl,
    const u32* __restrict__ vh, const u32* __restrict__ vl,
    const float* __restrict__ bias, const u32* __restrict__ allow,
    u32* __restrict__ m2h, u32* __restrict__ m2l)
{
    extern __shared__ u32 smemU[];
    u32* Ksh = smemU;
    u32* Ksl = Ksh + 256 * 17;
    u32* vTh = Ksl + 256 * 17;
    u32* vTl = vTh + 32 * 129;
    float* comb = (float*)(vTl + 32 * 129);
    float* psum = comb + 2 * 64 * 33;

    const int bh = blockIdx.x;
    const int b = bh >> 4;
    const int hh = bh & 15;
    const int tid = threadIdx.x;
    const int lane = tid & 31;
    const int w = tid >> 5;
    const int g = lane >> 2, t = lane & 3;
    const int wm = w >> 1, wn = w & 1;
    const size_t base = (size_t)bh * 4096;

#pragma unroll
    for (int it = 0; it < 16; it++) {
        int idx = tid + 256 * it;
        int row = idx >> 4, wd = idx & 15;
        Ksh[row * 17 + wd] = kh[base + idx];
        Ksl[row * 17 + wd] = kl[base + idx];
    }
    {
        const unsigned short* vhp = (const unsigned short*)vh + base * 2;
        const unsigned short* vlp = (const unsigned short*)vl + base * 2;
#pragma unroll
        for (int it = 0; it < 16; it++) {
            int idx = tid + 256 * it;
            int n = idx & 31, wk = idx >> 5;
            vTh[n * 129 + wk] = (u32)vhp[(2 * wk) * 32 + n]
                              | ((u32)vhp[(2 * wk + 1) * 32 + n] << 16);
            vTl[n * 129 + wk] = (u32)vlp[(2 * wk) * 32 + n]
                              | ((u32)vlp[(2 * wk + 1) * 32 + n] << 16);
        }
    }
    __syncthreads();

    const float scale = 0.17677669529663687f;

    for (int tile = 2 * blockIdx.y; tile < 2 * blockIdx.y + 2; tile++) {
        const int r0 = tile * 64 + wm * 16 + g;

        float acc[16][4];
#pragma unroll
        for (int nt = 0; nt < 16; nt++)
#pragma unroll
            for (int i = 0; i < 4; i++) acc[nt][i] = 0.f;

#pragma unroll
        for (int kc = 0; kc < 2; kc++) {
            int w0 = kc * 8 + t;
            u32 ah[4], al[4];
            ah[0] = qh[base + (size_t)r0 * 16 + w0];
            ah[1] = qh[base + (size_t)(r0 + 8) * 16 + w0];
            ah[2] = qh[base + (size_t)r0 * 16 + w0 + 4];
            ah[3] = qh[base + (size_t)(r0 + 8) * 16 + w0 + 4];
            al[0] = ql[base + (size_t)r0 * 16 + w0];
            al[1] = ql[base + (size_t)(r0 + 8) * 16 + w0];
            al[2] = ql[base + (size_t)r0 * 16 + w0 + 4];
            al[3] = ql[base + (size_t)(r0 + 8) * 16 + w0 + 4];
#pragma unroll
            for (int nt = 0; nt < 16; nt++) {
                int n = wn * 128 + nt * 8 + g;
                int bb = n * 17 + kc * 8 + t;
                u32 bhf[2] = {Ksh[bb], Ksh[bb + 4]};
                u32 blf[2] = {Ksl[bb], Ksl[bb + 4]};
                MMA16816(acc[nt], ah, bhf);
                MMA16816(acc[nt], ah, blf);
                MMA16816(acc[nt], al, bhf);
            }
        }

        for (int ks = 0; ks < 4; ks++) {
            float acc2[4][4];
#pragma unroll
            for (int vn = 0; vn < 4; vn++)
#pragma unroll
                for (int i = 0; i < 4; i++) acc2[vn][i] = 0.f;
            float s0 = 0.f, s1 = 0.f;

            const size_t abase = ((size_t)(b * 4 + ks) * 256);
            u32 aw0[4], aw1[4];
#pragma unroll
            for (int ww = 0; ww < 4; ww++) {
                aw0[ww] = allow[(abase + r0) * 8 + wn * 4 + ww];
                aw1[ww] = allow[(abase + r0 + 8) * 8 + wn * 4 + ww];
            }
            const float* bp0 = bias + (abase + r0) * 256 + wn * 128;
            const float* bp1 = bias + (abase + r0 + 8) * 256 + wn * 128;

#pragma unroll
            for (int kc = 0; kc < 8; kc++) {
                u32 pa_h[4], pa_l[4];
#pragma unroll
                for (int sub = 0; sub < 2; sub++) {
                    int nt = 2 * kc + sub;
                    int coff = nt * 8 + 2 * t;
                    float2 bv0 = *(const float2*)(bp0 + coff);
                    float2 bv1 = *(const float2*)(bp1 + coff);
                    int wi = kc >> 1;
                    int bit = (nt & 3) * 8 + 2 * t;
                    float p00 = 0.f, p01 = 0.f, p10 = 0.f, p11 = 0.f;
                    if ((aw0[wi] >> bit) & 1)
                        p00 = __expf(fmaf(acc[nt][0], scale, bv0.x));
                    if ((aw0[wi] >> (bit + 1)) & 1)
                        p01 = __expf(fmaf(acc[nt][1], scale, bv0.y));
                    if ((aw1[wi] >> bit) & 1)
                        p10 = __expf(fmaf(acc[nt][2], scale, bv1.x));
                    if ((aw1[wi] >> (bit + 1)) & 1)
                        p11 = __expf(fmaf(acc[nt][3], scale, bv1.y));
                    s0 += p00 + p01;
                    s1 += p10 + p11;
                    split_pair(p00, p01, pa_h[sub * 2], pa_l[sub * 2]);
                    split_pair(p10, p11, pa_h[sub * 2 + 1], pa_l[sub * 2 + 1]);
                }
                int kcg = wn * 8 + kc;
#pragma unroll
                for (int vn = 0; vn < 4; vn++) {
                    int n = vn * 8 + g;
                    int vb = n * 129 + kcg * 8 + t;
                    u32 bhf[2] = {vTh[vb], vTh[vb + 4]};
                    u32 blf[2] = {vTl[vb], vTl[vb + 4]};
                    MMA16816(acc2[vn], pa_h, bhf);
                    MMA16816(acc2[vn], pa_h, blf);
                    MMA16816(acc2[vn], pa_l, bhf);
                }
            }

            s0 += __shfl_xor_sync(0xffffffffu, s0, 1);
            s0 += __shfl_xor_sync(0xffffffffu, s0, 2);
            s1 += __shfl_xor_sync(0xffffffffu, s1, 1);
            s1 += __shfl_xor_sync(0xffffffffu, s1, 2);
            if (t == 0) {
                psum[(wm * 16 + g) * 2 + wn] = s0;
                psum[(wm * 16 + g + 8) * 2 + wn] = s1;
            }
            float* cw = comb + wn * 64 * 33;
#pragma unroll
            for (int vn = 0; vn < 4; vn++) {
                int c = vn * 8 + 2 * t;
                cw[(wm * 16 + g) * 33 + c]     = acc2[vn][0];
                cw[(wm * 16 + g) * 33 + c + 1] = acc2[vn][1];
                cw[(wm * 16 + g + 8) * 33 + c]     = acc2[vn][2];
                cw[(wm * 16 + g + 8) * 33 + c + 1] = acc2[vn][3];
            }
            __syncthreads();
            // msg2 row = b*256 + np, np = (ks*16+h)*4 + (d>>3); col = (d&7)*256 + n
            for (int i = tid; i < 1024; i += 256) {
                int pr = i >> 5;
                int c = i & 31;
                int rl0 = 2 * pr, rl1 = rl0 + 1;
                float v0 = (comb[rl0 * 33 + c] + comb[64 * 33 + rl0 * 33 + c])
                         / (psum[rl0 * 2] + psum[rl0 * 2 + 1]);
                float v1 = (comb[rl1 * 33 + c] + comb[64 * 33 + rl1 * 33 + c])
                         / (psum[rl1 * 2] + psum[rl1 * 2 + 1]);
                int row0 = tile * 64 + rl0;
                int np = (((ks << 4) | hh) << 2) | (c >> 3);
                size_t wI = ((size_t)b * 256 + np) * 1024
                          + ((c & 7) << 7) + (row0 >> 1);
                u32 hw, lw; split_pair(v0, v1, hw, lw);
                m2h[wI] = hw; m2l[wI] = lw;
            }
            __syncthreads();
        }
    }
}

// ---------------- residual + LayerNorm (2 partials + bias) -------------------
__global__ __launch_bounds__(256) void ln_kernel2(
    const float* __restrict__ a0, const float* __restrict__ a1,
    const float* __restrict__ bb, const float* __restrict__ res,
    const float* __restrict__ g, const float* __restrict__ be,
    float* __restrict__ out, u32* __restrict__ oh, u32* __restrict__ ol)
{
    const int row = blockIdx.x, tid = threadIdx.x;
    __shared__ float sred[8];
    float2 av = ((const float2*)(a0 + (size_t)row * 512))[tid];
    float2 a2 = ((const float2*)(a1 + (size_t)row * 512))[tid];
    float2 rv = ((const float2*)(res + (size_t)row * 512))[tid];
    float b0 = bb[2 * tid], b1 = bb[2 * tid + 1];
    float v0 = av.x + a2.x + b0 + rv.x;
    float v1 = av.y + a2.y + b1 + rv.y;

    float s = v0 + v1;
#pragma unroll
    for (int o = 16; o > 0; o >>= 1) s += __shfl_xor_sync(0xffffffffu, s, o);
    if ((tid & 31) == 0) sred[tid >> 5] = s;
    __syncthreads();
    float mean = 0.f;
#pragma unroll
    for (int i = 0; i < 8; i++) mean += sred[i];
    mean *= (1.f / 512.f);
    __syncthreads();

    float d0 = v0 - mean, d1 = v1 - mean;
    float vs = d0 * d0 + d1 * d1;
#pragma unroll
    for (int o = 16; o > 0; o >>= 1) vs += __shfl_xor_sync(0xffffffffu, vs, o);
    if ((tid & 31) == 0) sred[tid >> 5] = vs;
    __syncthreads();
    float var = 0.f;
#pragma unroll
    for (int i = 0; i < 8; i++) var += sred[i];
    var *= (1.f / 512.f);
    float inv = rsqrtf(var + 1e-6f);

    float2 gv = ((const float2*)g)[tid];
    float2 bv = ((const float2*)be)[tid];
    float o0 = d0 * inv * gv.x + bv.x;
    float o1 = d1 * inv * gv.y + bv.y;
    ((float2*)(out + (size_t)row * 512))[tid] = make_float2(o0, o1);
    if (oh) {
        u32 h, l; split_pair(o0, o1, h, l);
        oh[(size_t)row * 256 + tid] = h;
        ol[(size_t)row * 256 + tid] = l;
    }
}

// ---------------- launch ------------------------------------------------------
extern "C" void kernel_launch(void* const* d_in, const int* in_sizes, int n_in,
                              void* d_out, int out_size)
{
    const float* x         = (const float*)d_in[0];
    const float* dist      = (const float*)d_in[1];
    const float* dist_bar  = (const float*)d_in[2];
    const float* attn_bias = (const float*)d_in[3];
    const int*   mask      = (const int*)d_in[4];
    int wo = (n_in >= 24 && in_sizes[5] == 1) ? 6 : 5;
    const float* Wq  = (const float*)d_in[wo + 0];
    const float* bq  = (const float*)d_in[wo + 1];
    const float* Wk  = (const float*)d_in[wo + 2];
    const float* bk  = (const float*)d_in[wo + 3];
    const float* Wv  = (const float*)d_in[wo + 4];
    const float* bv  = (const float*)d_in[wo + 5];
    const float* W1  = (const float*)d_in[wo + 6];
    const float* b1  = (const float*)d_in[wo + 7];
    const float* W2  = (const float*)d_in[wo + 8];
    const float* b2  = (const float*)d_in[wo + 9];
    const float* g1  = (const float*)d_in[wo + 10];
    const float* be1 = (const float*)d_in[wo + 11];
    const float* Wf1 = (const float*)d_in[wo + 12];
    const float* bf1 = (const float*)d_in[wo + 13];
    const float* Wf2 = (const float*)d_in[wo + 14];
    const float* bf2 = (const float*)d_in[wo + 15];
    const float* g2  = (const float*)d_in[wo + 16];
    const float* be2 = (const float*)d_in[wo + 17];
    float* out = (float*)d_out;

#define SYM(p, s) cudaGetSymbolAddress((void**)&p, s)
    u32 *xw_h, *xw_l, *wqT_h, *wqT_l, *wkT_h, *wkT_l, *wvT_h, *wvT_l;
    u32 *w1T_h, *w1T_l, *w2T_h, *w2T_l, *wf1T_h, *wf1T_l, *wf2T_h, *wf2T_l;
    u32 *qp_h, *qp_l, *kp_h, *kp_l, *vp_h, *vp_l;
    u32 *m2_h, *m2_l, *h1_h, *h1_l, *y_h, *y_l, *f1_h, *f1_l, *allow;
    float *t, *t2, *y;
    SYM(xw_h, g_xw_h); SYM(xw_l, g_xw_l);
    SYM(wqT_h, g_wqT_h); SYM(wqT_l, g_wqT_l);
    SYM(wkT_h, g_wkT_h); SYM(wkT_l, g_wkT_l);
    SYM(wvT_h, g_wvT_h); SYM(wvT_l, g_wvT_l);
    SYM(w1T_h, g_w1T_h); SYM(w1T_l, g_w1T_l);
    SYM(w2T_h, g_w2T_h); SYM(w2T_l, g_w2T_l);
    SYM(wf1T_h, g_wf1T_h); SYM(wf1T_l, g_wf1T_l);
    SYM(wf2T_h, g_wf2T_h); SYM(wf2T_l, g_wf2T_l);
    SYM(qp_h, g_qp_h); SYM(qp_l, g_qp_l);
    SYM(kp_h, g_kp_h); SYM(kp_l, g_kp_l);
    SYM(vp_h, g_vp_h); SYM(vp_l, g_vp_l);
    SYM(m2_h, g_m2_h); SYM(m2_l, g_m2_l);
    SYM(h1_h, g_h1_h); SYM(h1_l, g_h1_l);
    SYM(y_h, g_y_h); SYM(y_l, g_y_l);
    SYM(f1_h, g_f1_h); SYM(f1_l, g_f1_l);
    SYM(allow, g_allow);
    SYM(t, g_t); SYM(t2, g_t2); SYM(y, g_y);

    const int smem_attn = (256 * 17 + 32 * 129) * 2 * 4 + (2 * 64 * 33 + 128) * 4;
    static int attrSet = 0;
    if (!attrSet) {
        cudaFuncSetAttribute(attn_mma,
                             cudaFuncAttributeMaxDynamicSharedMemorySize, smem_attn);
        cudaFuncSetAttribute(gemm_mma2,
                             cudaFuncAttributeMaxDynamicSharedMemorySize, GEMM_SMEM);
        attrSet = 1;
    }

    dim3 blk(256);

    // merged prep
    PrepArgs pa;
    const float* wsrc[7] = {Wq, Wk, Wv, W1, W2, Wf1, Wf2};
    u32* wdh[7] = {wqT_h, wkT_h, wvT_h, w1T_h, w2T_h, wf1T_h, wf2T_h};
    u32* wdl[7] = {wqT_l, wkT_l, wvT_l, w1T_l, w2T_l, wf1T_l, wf2T_l};
    int wK[7] = {512, 512, 512, 2048, 512, 512, 2048};
    int wN[7] = {512, 512, 512, 512, 512, 2048, 512};
    int tbase[8] = {0, 256, 512, 768, 1792, 2048, 3072, 4096};
    for (int i = 0; i < 7; i++) {
        pa.wsrc[i] = wsrc[i]; pa.wdh[i] = wdh[i]; pa.wdl[i] = wdl[i];
        pa.wK[i] = wK[i]; pa.wN[i] = wN[i];
    }
    for (int i = 0; i < 8; i++) pa.tbase[i] = tbase[i];
    pa.x = x; pa.xh = xw_h; pa.xl = xw_l;
    pa.mask = mask; pa.dist = dist; pa.dbar = dist_bar; pa.allow = allow;
    prep_all<<<6208, blk>>>(pa);

    auto mkop = [](const u32* Ah, const u32* Al, int N, int K, int act,
                   int mode, int ksplit) {
        GemmOp o;
        o.Ah = Ah; o.Al = Al; o.N = N; o.K = K; o.act = act;
        o.mode = mode; o.ksplit = ksplit;
        for (int i = 0; i < 3; i++) {
            o.Bh[i] = nullptr; o.Bl[i] = nullptr; o.bias[i] = nullptr;
            o.Cf[i] = nullptr; o.Ch[i] = nullptr; o.Cl[i] = nullptr;
        }
        return o;
    };

    // QKV fused: z = {q,k,v}
    {
        GemmOp o = mkop(xw_h, xw_l, 512, 512, 0, 2, 0);
        o.Bh[0] = wqT_h; o.Bl[0] = wqT_l; o.bias[0] = bq; o.Ch[0] = qp_h; o.Cl[0] = qp_l;
        o.Bh[1] = wkT_h; o.Bl[1] = wkT_l; o.bias[1] = bk; o.Ch[1] = kp_h; o.Cl[1] = kp_l;
        o.Bh[2] = wvT_h; o.Bl[2] = wvT_l; o.bias[2] = bv; o.Ch[2] = vp_h; o.Cl[2] = vp_l;
        gemm_mma2<<<dim3(8, 16, 3), blk, GEMM_SMEM>>>(o);
    }

    attn_mma<<<dim3(BH, 2), blk, smem_attn>>>(qp_h, qp_l, kp_h, kp_l, vp_h, vp_l,
                                              attn_bias, allow, m2_h, m2_l);

    // W1 split-K=2 -> raw partials -> combine(silu) -> h1 planes
    {
        GemmOp o = mkop(m2_h, m2_l, 512, 2048, 1, 3, 1);
        o.Bh[0] = w1T_h; o.Bl[0] = w1T_l;
        o.Cf[0] = t; o.Cf[1] = t2;
        gemm_mma2<<<dim3(8, 16, 2), blk, GEMM_SMEM>>>(o);
    }
    combine_silu<<<(ROWS * 256) / 256, blk>>>(t, t2, b1, h1_h, h1_l);

    // W2 split-K=2 -> raw partials -> ln2
    {
        GemmOp o = mkop(h1_h, h1_l, 512, 512, 0, 3, 1);
        o.Bh[0] = w2T_h; o.Bl[0] = w2T_l;
        o.Cf[0] = t; o.Cf[1] = t2;
        gemm_mma2<<<dim3(8, 16, 2), blk, GEMM_SMEM>>>(o);
    }
    ln_kernel2<<<ROWS, blk>>>(t, t2, b2, x, g1, be1, y, y_h, y_l);

    // FFN1 (N=2048, 512 blocks) -> gelu planes
    {
        GemmOp o = mkop(y_h, y_l, FFN, 512, 2, 1, 0);
        o.Bh[0] = wf1T_h; o.Bl[0] = wf1T_l; o.bias[0] = bf1;
        o.Ch[0] = f1_h; o.Cl[0] = f1_l;
        gemm_mma2<<<dim3(32, 16, 1), blk, GEMM_SMEM>>>(o);
    }

    // FFN2 split-K=2 -> raw partials -> ln2
    {
        GemmOp o = mkop(f1_h, f1_l, 512, 2048, 0, 3, 1);
        o.Bh[0] = wf2T_h; o.Bl[0] = wf2T_l;
        o.Cf[0] = t; o.Cf[1] = t2;
        gemm_mma2<<<dim3(8, 16, 2), blk, GEMM_SMEM>>>(o);
    }
    ln_kernel2<<<ROWS, blk>>>(t, t2, bf2, y, g2, be2, out, nullptr, nullptr);
}

// round 10
// speedup vs baseline: 1.2034x; 1.2034x over previous
#include <cuda_runtime.h>
#include <cuda_bf16.h>
#include <math.h>
#include <stdint.h>

typedef unsigned int u32;
typedef unsigned long long u64;

#define BB 8
#define NN 256
#define DD 512
#define HH 16
#define KK 4
#define FFN 2048
#define ROWS (BB*NN)          // 2048
#define BH (BB*HH)            // 128

// ---------------- scratch globals --------------------------------------------
__device__ u32 g_xw_h[ROWS*256],  g_xw_l[ROWS*256];
__device__ u32 g_wqT_h[512*256],  g_wqT_l[512*256];
__device__ u32 g_wkT_h[512*256],  g_wkT_l[512*256];
__device__ u32 g_wvT_h[512*256],  g_wvT_l[512*256];
__device__ u32 g_w1T_h[512*1024], g_w1T_l[512*1024];
__device__ u32 g_w2T_h[512*256],  g_w2T_l[512*256];
__device__ u32 g_wf1T_h[2048*256], g_wf1T_l[2048*256];
__device__ u32 g_wf2T_h[512*1024], g_wf2T_l[512*1024];
__device__ u32 g_qp_h[BH*4096], g_qp_l[BH*4096];
__device__ u32 g_kp_h[BH*4096], g_kp_l[BH*4096];
__device__ u32 g_vp_h[BH*4096], g_vp_l[BH*4096];
__device__ u32 g_m2_h[ROWS*1024], g_m2_l[ROWS*1024];
__device__ u32 g_h1_h[ROWS*256],  g_h1_l[ROWS*256];
__device__ float g_t[ROWS*DD];
__device__ float g_t2[ROWS*DD];
__device__ float g_y[ROWS*DD];
__device__ u32 g_y_h[ROWS*256],   g_y_l[ROWS*256];
__device__ u32 g_f1_h[ROWS*1024], g_f1_l[ROWS*1024];
__device__ u32 g_allow[BB*KK*NN*8];

// ---------------- helpers ----------------------------------------------------
__device__ __forceinline__ u32 packbf(float a, float b) {
    __nv_bfloat16 ha = __float2bfloat16_rn(a);
    __nv_bfloat16 hb = __float2bfloat16_rn(b);
    return (u32)__bfloat16_as_ushort(ha) | ((u32)__bfloat16_as_ushort(hb) << 16);
}
__device__ __forceinline__ float bfval(float x) {
    return __bfloat162float(__float2bfloat16_rn(x));
}
__device__ __forceinline__ void split_pair(float a, float b, u32& hi, u32& lo) {
    float ah = bfval(a), bh_ = bfval(b);
    hi = packbf(a, b);
    lo = packbf(a - ah, b - bh_);
}

#define MMA16816(d, a, b) \
    asm volatile("mma.sync.aligned.m16n8k16.row.col.f32.bf16.bf16.f32 " \
        "{%0,%1,%2,%3},{%4,%5,%6,%7},{%8,%9},{%0,%1,%2,%3};" \
        : "+f"(d[0]), "+f"(d[1]), "+f"(d[2]), "+f"(d[3]) \
        : "r"(a[0]), "r"(a[1]), "r"(a[2]), "r"(a[3]), "r"(b[0]), "r"(b[1]))

__device__ __forceinline__ u32 smem_u32(const void* p) {
    u32 a;
    asm("{ .reg .u64 t; cvta.to.shared.u64 t, %1; cvt.u32.u64 %0, t; }"
        : "=r"(a) : "l"(p));
    return a;
}
__device__ __forceinline__ void cp16(u32 saddr, const void* gptr) {
    asm volatile("cp.async.cg.shared.global [%0], [%1], 16;"
                 :: "r"(saddr), "l"(gptr));
}

// ---------------- merged prep kernel -----------------------------------------
struct PrepArgs {
    const float* wsrc[7];
    u32* wdh[7];
    u32* wdl[7];
    int wK[7], wN[7];
    int tbase[8];
    const float* x; u32* xh; u32* xl;
    const int* mask; const float* dist; const float* dbar; u32* allow;
};

__global__ __launch_bounds__(256) void prep_all(PrepArgs pa)
{
    const int bx = blockIdx.x;
    const int tid = threadIdx.x;
    if (bx < 4096) {
        int task = 0;
        while (bx >= pa.tbase[task + 1]) task++;
        int tIdx = bx - pa.tbase[task];
        int K = pa.wK[task], N = pa.wN[task];
        int ntx = N >> 5;
        int n0 = (tIdx % ntx) * 32, k0 = (tIdx / ntx) * 32;
        __shared__ float tile[32][33];
        int tx = tid & 31, ty = tid >> 5;
        const float* src = pa.wsrc[task];
#pragma unroll
        for (int r = 0; r < 32; r += 8)
            tile[ty + r][tx] = src[(size_t)(k0 + ty + r) * N + n0 + tx];
        __syncthreads();
        int Kw = K >> 1;
        u32* dh = pa.wdh[task];
        u32* dl = pa.wdl[task];
#pragma unroll
        for (int r = 0; r < 32; r += 8) {
            int n = ty + r;
            if (tx < 16) {
                float a = tile[2 * tx][n], b = tile[2 * tx + 1][n];
                u32 h, l; split_pair(a, b, h, l);
                dh[(size_t)(n0 + n) * Kw + (k0 >> 1) + tx] = h;
                dl[(size_t)(n0 + n) * Kw + (k0 >> 1) + tx] = l;
            }
        }
    } else if (bx < 6144) {
        int idx = (bx - 4096) * 256 + tid;
        float2 v = ((const float2*)pa.x)[idx];
        u32 h, l; split_pair(v.x, v.y, h, l);
        pa.xh[idx] = h; pa.xl[idx] = l;
    } else {
        int idx = (bx - 6144) * 256 + tid;            // [b][row][ww]
        int ww = idx & 7, row = (idx >> 3) & 255, b = idx >> 11;
        float d0 = pa.dbar[0], d1 = pa.dbar[1], d2 = pa.dbar[2], d3 = pa.dbar[3];
        u32 w0 = 0, w1 = 0, w2 = 0, w3 = 0;
        for (int bit = 0; bit < 32; bit++) {
            int col = ww * 32 + bit;
            bool pad = pa.mask[((size_t)b * 256 + row) * 256 + col] != 0;
            float nd = 0.f;
            if (row > 0 && col > 0)
                nd = pa.dist[((size_t)b * 255 + row - 1) * 255 + col - 1];
            if (pad) {
                if (nd < d0) w0 |= 1u << bit;
                if (nd < d1) w1 |= 1u << bit;
                if (nd < d2) w2 |= 1u << bit;
                if (nd < d3) w3 |= 1u << bit;
            }
        }
        size_t base = ((size_t)b * 4 * 256 + row) * 8 + ww;
        pa.allow[base] = w0;
        pa.allow[base + 2048] = w1;
        pa.allow[base + 4096] = w2;
        pa.allow[base + 6144] = w3;
    }
}

// ---------------- GEMM: 128x64 tile, BK=64, cp.async 2-stage (R8 config) -----
#define ASTR 36
#define A_PL (128*ASTR)                    // 4608 words per A plane
#define B_PL (64*ASTR)                     // 2304 words per B plane
#define STG_W (2*A_PL + 2*B_PL)            // 13824 words per stage
#define GEMM_SMEM (2 * STG_W * 4)          // 110592 B

struct GemmOp {
    const u32 *Ah, *Al;
    const u32 *Bh[3], *Bl[3];
    const float* bias[3];
    float* Cf[3];
    u32 *Ch[3], *Cl[3];
    int N, K, act, mode, ksplit;           // mode: 0 f32+bias, 1 planes, 2 head planes, 3 raw f32
};

__global__ __launch_bounds__(256, 2) void gemm_mma2(GemmOp op)
{
    extern __shared__ u32 sm[];
    const u32 smb = smem_u32(sm);
    const int z = blockIdx.z;
    const int zb = op.ksplit ? 0 : z;
    const u32* __restrict__ Ah = op.Ah;
    const u32* __restrict__ Al = op.Al;
    const u32* __restrict__ Bh = op.Bh[zb];
    const u32* __restrict__ Bl = op.Bl[zb];
    const int N = op.N, K = op.K, act = op.act, mode = op.mode;
    const int Kw = K >> 1;
    const int Keff = op.ksplit ? (K >> 1) : K;
    const int koffw = op.ksplit ? z * (K >> 2) : 0;
    const int nkt = Keff >> 6;

    const int tid = threadIdx.x;
    const int lane = tid & 31, wid = tid >> 5;
    const int wm = wid & 3, wn = wid >> 2;
    const int g = lane >> 2, t = lane & 3;
    const int m0 = blockIdx.y * 128, n0 = blockIdx.x * 64;

    float acc[2][4][4];
#pragma unroll
    for (int mt = 0; mt < 2; mt++)
#pragma unroll
        for (int nt = 0; nt < 4; nt++)
#pragma unroll
            for (int i = 0; i < 4; i++) acc[mt][nt][i] = 0.f;

    const int srow = tid >> 3, sq = tid & 7;   // base row/quad for async copies

    auto issue = [&](int s, int kt) {
        const u32 st = smb + s * (STG_W * 4);
        const int ktw = koffw + kt * 32;
#pragma unroll
        for (int i = 0; i < 4; i++) {
            int row = srow + 32 * i;
            size_t gs = (size_t)(m0 + row) * Kw + ktw + sq * 4;
            u32 sa = st + (row * ASTR + sq * 4) * 4;
            cp16(sa, Ah + gs);
            cp16(sa + A_PL * 4, Al + gs);
        }
#pragma unroll
        for (int i = 0; i < 2; i++) {
            int row = srow + 32 * i;
            size_t gs = (size_t)(n0 + row) * Kw + ktw + sq * 4;
            u32 sa = st + (2 * A_PL + row * ASTR + sq * 4) * 4;
            cp16(sa, Bh + gs);
            cp16(sa + B_PL * 4, Bl + gs);
        }
        asm volatile("cp.async.commit_group;");
    };

    issue(0, 0);
    for (int kt = 0; kt < nkt; kt++) {
        if (kt + 1 < nkt) {
            issue((kt + 1) & 1, kt + 1);
            asm volatile("cp.async.wait_group 1;");
        } else {
            asm volatile("cp.async.wait_group 0;");
        }
        __syncthreads();
        const u32* As_h = sm + (kt & 1) * STG_W;
        const u32* As_l = As_h + A_PL;
        const u32* Bs_h = As_h + 2 * A_PL;
        const u32* Bs_l = Bs_h + B_PL;
#pragma unroll
        for (int sel = 0; sel < 4; sel++) {
            const int ko = sel * 8;
            u32 ah[2][4], al[2][4];
#pragma unroll
            for (int mt = 0; mt < 2; mt++) {
                int row = wm * 32 + mt * 16 + g;
                int b0 = row * ASTR + ko + t;
                int b8 = (row + 8) * ASTR + ko + t;
                ah[mt][0] = As_h[b0];     ah[mt][1] = As_h[b8];
                ah[mt][2] = As_h[b0 + 4]; ah[mt][3] = As_h[b8 + 4];
                al[mt][0] = As_l[b0];     al[mt][1] = As_l[b8];
                al[mt][2] = As_l[b0 + 4]; al[mt][3] = As_l[b8 + 4];
            }
#pragma unroll
            for (int nt = 0; nt < 4; nt++) {
                int n = wn * 32 + nt * 8 + g;
                int bb = n * ASTR + ko + t;
                u32 bhf[2] = {Bs_h[bb], Bs_h[bb + 4]};
                u32 blf[2] = {Bs_l[bb], Bs_l[bb + 4]};
#pragma unroll
                for (int mt = 0; mt < 2; mt++) {
                    MMA16816(acc[mt][nt], ah[mt], bhf);
                    MMA16816(acc[mt][nt], ah[mt], blf);
                    MMA16816(acc[mt][nt], al[mt], bhf);
                }
            }
        }
        __syncthreads();
    }

    // epilogue
    const float* bias = op.bias[zb];
    float* Cf = op.Cf[z];
    u32* Ch = op.Ch[z];
    u32* Cl = op.Cl[z];
#pragma unroll
    for (int mt = 0; mt < 2; mt++) {
#pragma unroll
        for (int nt = 0; nt < 4; nt++) {
            int col = n0 + wn * 32 + nt * 8 + 2 * t;
            float bia0 = 0.f, bia1 = 0.f;
            if (mode != 3) { bia0 = bias[col]; bia1 = bias[col + 1]; }
#pragma unroll
            for (int half = 0; half < 2; half++) {
                int row = m0 + wm * 32 + mt * 16 + g + half * 8;
                float c0 = acc[mt][nt][half * 2 + 0] + bia0;
                float c1 = acc[mt][nt][half * 2 + 1] + bia1;
                if (act == 1 && mode != 3) {
                    c0 = c0 / (1.f + expf(-c0)); c1 = c1 / (1.f + expf(-c1));
                } else if (act == 2 && mode != 3) {
                    c0 = c0 * normcdff(c0); c1 = c1 * normcdff(c1);
                }
                if (mode == 0 || mode == 3) {
                    *(float2*)(Cf + (size_t)row * N + col) = make_float2(c0, c1);
                } else {
                    u32 h, l; split_pair(c0, c1, h, l);
                    size_t w;
                    if (mode == 2)
                        w = (size_t)((row >> 8) * 16 + (col >> 5)) * 4096
                          + (size_t)(row & 255) * 16 + ((col & 31) >> 1);
                    else
                        w = ((size_t)row * N + col) >> 1;
                    Ch[w] = h; Cl[w] = l;
                }
            }
        }
    }
}

// ---------------- combine split-K partials + bias + silu -> planes -----------
__global__ __launch_bounds__(256) void combine_silu(
    const float* __restrict__ p0, const float* __restrict__ p1,
    const float* __restrict__ bias, u32* __restrict__ oh, u32* __restrict__ ol)
{
    int i = blockIdx.x * 256 + threadIdx.x;       // word over [ROWS][256]
    int col = (i & 255) * 2;
    float2 a = ((const float2*)p0)[i];
    float2 b = ((const float2*)p1)[i];
    float c0 = a.x + b.x + bias[col];
    float c1 = a.y + b.y + bias[col + 1];
    c0 = c0 / (1.f + expf(-c0));
    c1 = c1 / (1.f + expf(-c1));
    u32 h, l; split_pair(c0, c1, h, l);
    oh[i] = h; ol[i] = l;
}

// ---------------- fused multi-scale attention via HMMA -----------------------
// Grid (bh, tile): one 64-row q-tile per block, 512 blocks.
__global__ __launch_bounds__(256) void attn_mma(
    const u32* __restrict__ qh, const u32* __restrict__ ql,
    const u32* __restrict__ kh, const u32* __restrict__ kl,
    const u32* __restrict__ vh, const u32* __restrict__ vl,
    const float* __restrict__ bias, const u32* __restrict__ allow,
    u32* __restrict__ m2h, u32* __restrict__ m2l)
{
    extern __shared__ u32 smemU[];
    u32* Ksh = smemU;
    u32* Ksl = Ksh + 256 * 17;
    u32* vTh = Ksl + 256 * 17;
    u32* vTl = vTh + 32 * 129;
    float* comb = (float*)(vTl + 32 * 129);
    float* psum = comb + 2 * 64 * 33;

    const int bh = blockIdx.x;
    const int b = bh >> 4;
    const int hh = bh & 15;
    const int tid = threadIdx.x;
    const int lane = tid & 31;
    const int w = tid >> 5;
    const int g = lane >> 2, t = lane & 3;
    const int wm = w >> 1, wn = w & 1;
    const size_t base = (size_t)bh * 4096;

#pragma unroll
    for (int it = 0; it < 16; it++) {
        int idx = tid + 256 * it;
        int row = idx >> 4, wd = idx & 15;
        Ksh[row * 17 + wd] = kh[base + idx];
        Ksl[row * 17 + wd] = kl[base + idx];
    }
    {
        const unsigned short* vhp = (const unsigned short*)vh + base * 2;
        const unsigned short* vlp = (const unsigned short*)vl + base * 2;
#pragma unroll
        for (int it = 0; it < 16; it++) {
            int idx = tid + 256 * it;
            int n = idx & 31, wk = idx >> 5;
            vTh[n * 129 + wk] = (u32)vhp[(2 * wk) * 32 + n]
                              | ((u32)vhp[(2 * wk + 1) * 32 + n] << 16);
            vTl[n * 129 + wk] = (u32)vlp[(2 * wk) * 32 + n]
                              | ((u32)vlp[(2 * wk + 1) * 32 + n] << 16);
        }
    }
    __syncthreads();

    const float scale = 0.17677669529663687f;
    const int tile = blockIdx.y;
    {
        const int r0 = tile * 64 + wm * 16 + g;

        float acc[16][4];
#pragma unroll
        for (int nt = 0; nt < 16; nt++)
#pragma unroll
            for (int i = 0; i < 4; i++) acc[nt][i] = 0.f;

#pragma unroll
        for (int kc = 0; kc < 2; kc++) {
            int w0 = kc * 8 + t;
            u32 ah[4], al[4];
            ah[0] = qh[base + (size_t)r0 * 16 + w0];
            ah[1] = qh[base + (size_t)(r0 + 8) * 16 + w0];
            ah[2] = qh[base + (size_t)r0 * 16 + w0 + 4];
            ah[3] = qh[base + (size_t)(r0 + 8) * 16 + w0 + 4];
            al[0] = ql[base + (size_t)r0 * 16 + w0];
            al[1] = ql[base + (size_t)(r0 + 8) * 16 + w0];
            al[2] = ql[base + (size_t)r0 * 16 + w0 + 4];
            al[3] = ql[base + (size_t)(r0 + 8) * 16 + w0 + 4];
#pragma unroll
            for (int nt = 0; nt < 16; nt++) {
                int n = wn * 128 + nt * 8 + g;
                int bb = n * 17 + kc * 8 + t;
                u32 bhf[2] = {Ksh[bb], Ksh[bb + 4]};
                u32 blf[2] = {Ksl[bb], Ksl[bb + 4]};
                MMA16816(acc[nt], ah, bhf);
                MMA16816(acc[nt], ah, blf);
                MMA16816(acc[nt], al, bhf);
            }
        }

        for (int ks = 0; ks < 4; ks++) {
            float acc2[4][4];
#pragma unroll
            for (int vn = 0; vn < 4; vn++)
#pragma unroll
                for (int i = 0; i < 4; i++) acc2[vn][i] = 0.f;
            float s0 = 0.f, s1 = 0.f;

            const size_t abase = ((size_t)(b * 4 + ks) * 256);
            u32 aw0[4], aw1[4];
#pragma unroll
            for (int ww = 0; ww < 4; ww++) {
                aw0[ww] = allow[(abase + r0) * 8 + wn * 4 + ww];
                aw1[ww] = allow[(abase + r0 + 8) * 8 + wn * 4 + ww];
            }
            const float* bp0 = bias + (abase + r0) * 256 + wn * 128;
            const float* bp1 = bias + (abase + r0 + 8) * 256 + wn * 128;

#pragma unroll
            for (int kc = 0; kc < 8; kc++) {
                u32 pa_h[4], pa_l[4];
#pragma unroll
                for (int sub = 0; sub < 2; sub++) {
                    int nt = 2 * kc + sub;
                    int coff = nt * 8 + 2 * t;
                    float2 bv0 = *(const float2*)(bp0 + coff);
                    float2 bv1 = *(const float2*)(bp1 + coff);
                    int wi = kc >> 1;
                    int bit = (nt & 3) * 8 + 2 * t;
                    float p00 = 0.f, p01 = 0.f, p10 = 0.f, p11 = 0.f;
                    if ((aw0[wi] >> bit) & 1)
                        p00 = __expf(fmaf(acc[nt][0], scale, bv0.x));
                    if ((aw0[wi] >> (bit + 1)) & 1)
                        p01 = __expf(fmaf(acc[nt][1], scale, bv0.y));
                    if ((aw1[wi] >> bit) & 1)
                        p10 = __expf(fmaf(acc[nt][2], scale, bv1.x));
                    if ((aw1[wi] >> (bit + 1)) & 1)
                        p11 = __expf(fmaf(acc[nt][3], scale, bv1.y));
                    s0 += p00 + p01;
                    s1 += p10 + p11;
                    split_pair(p00, p01, pa_h[sub * 2], pa_l[sub * 2]);
                    split_pair(p10, p11, pa_h[sub * 2 + 1], pa_l[sub * 2 + 1]);
                }
                int kcg = wn * 8 + kc;
#pragma unroll
                for (int vn = 0; vn < 4; vn++) {
                    int n = vn * 8 + g;
                    int vb = n * 129 + kcg * 8 + t;
                    u32 bhf[2] = {vTh[vb], vTh[vb + 4]};
                    u32 blf[2] = {vTl[vb], vTl[vb + 4]};
                    MMA16816(acc2[vn], pa_h, bhf);
                    MMA16816(acc2[vn], pa_h, blf);
                    MMA16816(acc2[vn], pa_l, bhf);
                }
            }

            s0 += __shfl_xor_sync(0xffffffffu, s0, 1);
            s0 += __shfl_xor_sync(0xffffffffu, s0, 2);
            s1 += __shfl_xor_sync(0xffffffffu, s1, 1);
            s1 += __shfl_xor_sync(0xffffffffu, s1, 2);
            if (t == 0) {
                psum[(wm * 16 + g) * 2 + wn] = s0;
                psum[(wm * 16 + g + 8) * 2 + wn] = s1;
            }
            float* cw = comb + wn * 64 * 33;
#pragma unroll
            for (int vn = 0; vn < 4; vn++) {
                int c = vn * 8 + 2 * t;
                cw[(wm * 16 + g) * 33 + c]     = acc2[vn][0];
                cw[(wm * 16 + g) * 33 + c + 1] = acc2[vn][1];
                cw[(wm * 16 + g + 8) * 33 + c]     = acc2[vn][2];
                cw[(wm * 16 + g + 8) * 33 + c + 1] = acc2[vn][3];
            }
            __syncthreads();
            // msg2 row = b*256 + np, np = (ks*16+h)*4 + (d>>3); col = (d&7)*256 + n
            for (int i = tid; i < 1024; i += 256) {
                int pr = i >> 5;
                int c = i & 31;
                int rl0 = 2 * pr, rl1 = rl0 + 1;
                float v0 = (comb[rl0 * 33 + c] + comb[64 * 33 + rl0 * 33 + c])
                         / (psum[rl0 * 2] + psum[rl0 * 2 + 1]);
                float v1 = (comb[rl1 * 33 + c] + comb[64 * 33 + rl1 * 33 + c])
                         / (psum[rl1 * 2] + psum[rl1 * 2 + 1]);
                int row0 = tile * 64 + rl0;
                int np = (((ks << 4) | hh) << 2) | (c >> 3);
                size_t wI = ((size_t)b * 256 + np) * 1024
                          + ((c & 7) << 7) + (row0 >> 1);
                u32 hw, lw; split_pair(v0, v1, hw, lw);
                m2h[wI] = hw; m2l[wI] = lw;
            }
            __syncthreads();
        }
    }
}

// ---------------- residual + LayerNorm (2 partials + bias) -------------------
__global__ __launch_bounds__(256) void ln_kernel2(
    const float* __restrict__ a0, const float* __restrict__ a1,
    const float* __restrict__ bb, const float* __restrict__ res,
    const float* __restrict__ g, const float* __restrict__ be,
    float* __restrict__ out, u32* __restrict__ oh, u32* __restrict__ ol)
{
    const int row = blockIdx.x, tid = threadIdx.x;
    __shared__ float sred[8];
    float2 av = ((const float2*)(a0 + (size_t)row * 512))[tid];
    float2 a2 = ((const float2*)(a1 + (size_t)row * 512))[tid];
    float2 rv = ((const float2*)(res + (size_t)row * 512))[tid];
    float b0 = bb[2 * tid], b1 = bb[2 * tid + 1];
    float v0 = av.x + a2.x + b0 + rv.x;
    float v1 = av.y + a2.y + b1 + rv.y;

    float s = v0 + v1;
#pragma unroll
    for (int o = 16; o > 0; o >>= 1) s += __shfl_xor_sync(0xffffffffu, s, o);
    if ((tid & 31) == 0) sred[tid >> 5] = s;
    __syncthreads();
    float mean = 0.f;
#pragma unroll
    for (int i = 0; i < 8; i++) mean += sred[i];
    mean *= (1.f / 512.f);
    __syncthreads();

    float d0 = v0 - mean, d1 = v1 - mean;
    float vs = d0 * d0 + d1 * d1;
#pragma unroll
    for (int o = 16; o > 0; o >>= 1) vs += __shfl_xor_sync(0xffffffffu, vs, o);
    if ((tid & 31) == 0) sred[tid >> 5] = vs;
    __syncthreads();
    float var = 0.f;
#pragma unroll
    for (int i = 0; i < 8; i++) var += sred[i];
    var *= (1.f / 512.f);
    float inv = rsqrtf(var + 1e-6f);

    float2 gv = ((const float2*)g)[tid];
    float2 bv = ((const float2*)be)[tid];
    float o0 = d0 * inv * gv.x + bv.x;
    float o1 = d1 * inv * gv.y + bv.y;
    ((float2*)(out + (size_t)row * 512))[tid] = make_float2(o0, o1);
    if (oh) {
        u32 h, l; split_pair(o0, o1, h, l);
        oh[(size_t)row * 256 + tid] = h;
        ol[(size_t)row * 256 + tid] = l;
    }
}

// ---------------- launch ------------------------------------------------------
extern "C" void kernel_launch(void* const* d_in, const int* in_sizes, int n_in,
                              void* d_out, int out_size)
{
    const float* x         = (const float*)d_in[0];
    const float* dist      = (const float*)d_in[1];
    const float* dist_bar  = (const float*)d_in[2];
    const float* attn_bias = (const float*)d_in[3];
    const int*   mask      = (const int*)d_in[4];
    int wo = (n_in >= 24 && in_sizes[5] == 1) ? 6 : 5;
    const float* Wq  = (const float*)d_in[wo + 0];
    const float* bq  = (const float*)d_in[wo + 1];
    const float* Wk  = (const float*)d_in[wo + 2];
    const float* bk  = (const float*)d_in[wo + 3];
    const float* Wv  = (const float*)d_in[wo + 4];
    const float* bv  = (const float*)d_in[wo + 5];
    const float* W1  = (const float*)d_in[wo + 6];
    const float* b1  = (const float*)d_in[wo + 7];
    const float* W2  = (const float*)d_in[wo + 8];
    const float* b2  = (const float*)d_in[wo + 9];
    const float* g1  = (const float*)d_in[wo + 10];
    const float* be1 = (const float*)d_in[wo + 11];
    const float* Wf1 = (const float*)d_in[wo + 12];
    const float* bf1 = (const float*)d_in[wo + 13];
    const float* Wf2 = (const float*)d_in[wo + 14];
    const float* bf2 = (const float*)d_in[wo + 15];
    const float* g2  = (const float*)d_in[wo + 16];
    const float* be2 = (const float*)d_in[wo + 17];
    float* out = (float*)d_out;

#define SYM(p, s) cudaGetSymbolAddress((void**)&p, s)
    u32 *xw_h, *xw_l, *wqT_h, *wqT_l, *wkT_h, *wkT_l, *wvT_h, *wvT_l;
    u32 *w1T_h, *w1T_l, *w2T_h, *w2T_l, *wf1T_h, *wf1T_l, *wf2T_h, *wf2T_l;
    u32 *qp_h, *qp_l, *kp_h, *kp_l, *vp_h, *vp_l;
    u32 *m2_h, *m2_l, *h1_h, *h1_l, *y_h, *y_l, *f1_h, *f1_l, *allow;
    float *t, *t2, *y;
    SYM(xw_h, g_xw_h); SYM(xw_l, g_xw_l);
    SYM(wqT_h, g_wqT_h); SYM(wqT_l, g_wqT_l);
    SYM(wkT_h, g_wkT_h); SYM(wkT_l, g_wkT_l);
    SYM(wvT_h, g_wvT_h); SYM(wvT_l, g_wvT_l);
    SYM(w1T_h, g_w1T_h); SYM(w1T_l, g_w1T_l);
    SYM(w2T_h, g_w2T_h); SYM(w2T_l, g_w2T_l);
    SYM(wf1T_h, g_wf1T_h); SYM(wf1T_l, g_wf1T_l);
    SYM(wf2T_h, g_wf2T_h); SYM(wf2T_l, g_wf2T_l);
    SYM(qp_h, g_qp_h); SYM(qp_l, g_qp_l);
    SYM(kp_h, g_kp_h); SYM(kp_l, g_kp_l);
    SYM(vp_h, g_vp_h); SYM(vp_l, g_vp_l);
    SYM(m2_h, g_m2_h); SYM(m2_l, g_m2_l);
    SYM(h1_h, g_h1_h); SYM(h1_l, g_h1_l);
    SYM(y_h, g_y_h); SYM(y_l, g_y_l);
    SYM(f1_h, g_f1_h); SYM(f1_l, g_f1_l);
    SYM(allow, g_allow);
    SYM(t, g_t); SYM(t2, g_t2); SYM(y, g_y);

    const int smem_attn = (256 * 17 + 32 * 129) * 2 * 4 + (2 * 64 * 33 + 128) * 4;
    static int attrSet = 0;
    if (!attrSet) {
        cudaFuncSetAttribute(attn_mma,
                             cudaFuncAttributeMaxDynamicSharedMemorySize, smem_attn);
        cudaFuncSetAttribute(gemm_mma2,
                             cudaFuncAttributeMaxDynamicSharedMemorySize, GEMM_SMEM);
        attrSet = 1;
    }

    dim3 blk(256);

    // merged prep
    PrepArgs pa;
    const float* wsrc[7] = {Wq, Wk, Wv, W1, W2, Wf1, Wf2};
    u32* wdh[7] = {wqT_h, wkT_h, wvT_h, w1T_h, w2T_h, wf1T_h, wf2T_h};
    u32* wdl[7] = {wqT_l, wkT_l, wvT_l, w1T_l, w2T_l, wf1T_l, wf2T_l};
    int wK[7] = {512, 512, 512, 2048, 512, 512, 2048};
    int wN[7] = {512, 512, 512, 512, 512, 2048, 512};
    int tbase[8] = {0, 256, 512, 768, 1792, 2048, 3072, 4096};
    for (int i = 0; i < 7; i++) {
        pa.wsrc[i] = wsrc[i]; pa.wdh[i] = wdh[i]; pa.wdl[i] = wdl[i];
        pa.wK[i] = wK[i]; pa.wN[i] = wN[i];
    }
    for (int i = 0; i < 8; i++) pa.tbase[i] = tbase[i];
    pa.x = x; pa.xh = xw_h; pa.xl = xw_l;
    pa.mask = mask; pa.dist = dist; pa.dbar = dist_bar; pa.allow = allow;
    prep_all<<<6208, blk>>>(pa);

    auto mkop = [](const u32* Ah, const u32* Al, int N, int K, int act,
                   int mode, int ksplit) {
        GemmOp o;
        o.Ah = Ah; o.Al = Al; o.N = N; o.K = K; o.act = act;
        o.mode = mode; o.ksplit = ksplit;
        for (int i = 0; i < 3; i++) {
            o.Bh[i] = nullptr; o.Bl[i] = nullptr; o.bias[i] = nullptr;
            o.Cf[i] = nullptr; o.Ch[i] = nullptr; o.Cl[i] = nullptr;
        }
        return o;
    };

    // QKV fused: z = {q,k,v}
    {
        GemmOp o = mkop(xw_h, xw_l, 512, 512, 0, 2, 0);
        o.Bh[0] = wqT_h; o.Bl[0] = wqT_l; o.bias[0] = bq; o.Ch[0] = qp_h; o.Cl[0] = qp_l;
        o.Bh[1] = wkT_h; o.Bl[1] = wkT_l; o.bias[1] = bk; o.Ch[1] = kp_h; o.Cl[1] = kp_l;
        o.Bh[2] = wvT_h; o.Bl[2] = wvT_l; o.bias[2] = bv; o.Ch[2] = vp_h; o.Cl[2] = vp_l;
        gemm_mma2<<<dim3(8, 16, 3), blk, GEMM_SMEM>>>(o);
    }

    attn_mma<<<dim3(BH, 4), blk, smem_attn>>>(qp_h, qp_l, kp_h, kp_l, vp_h, vp_l,
                                              attn_bias, allow, m2_h, m2_l);

    // W1 split-K=2 -> raw partials -> combine(silu) -> h1 planes
    {
        GemmOp o = mkop(m2_h, m2_l, 512, 2048, 1, 3, 1);
        o.Bh[0] = w1T_h; o.Bl[0] = w1T_l;
        o.Cf[0] = t; o.Cf[1] = t2;
        gemm_mma2<<<dim3(8, 16, 2), blk, GEMM_SMEM>>>(o);
    }
    combine_silu<<<(ROWS * 256) / 256, blk>>>(t, t2, b1, h1_h, h1_l);

    // W2 split-K=2 -> raw partials -> ln2
    {
        GemmOp o = mkop(h1_h, h1_l, 512, 512, 0, 3, 1);
        o.Bh[0] = w2T_h; o.Bl[0] = w2T_l;
        o.Cf[0] = t; o.Cf[1] = t2;
        gemm_mma2<<<dim3(8, 16, 2), blk, GEMM_SMEM>>>(o);
    }
    ln_kernel2<<<ROWS, blk>>>(t, t2, b2, x, g1, be1, y, y_h, y_l);

    // FFN1 (N=2048, 512 blocks) -> gelu planes
    {
        GemmOp o = mkop(y_h, y_l, FFN, 512, 2, 1, 0);
        o.Bh[0] = wf1T_h; o.Bl[0] = wf1T_l; o.bias[0] = bf1;
        o.Ch[0] = f1_h; o.Cl[0] = f1_l;
        gemm_mma2<<<dim3(32, 16, 1), blk, GEMM_SMEM>>>(o);
    }

    // FFN2 split-K=2 -> raw partials -> ln2
    {
        GemmOp o = mkop(f1_h, f1_l, 512, 2048, 0, 3, 1);
        o.Bh[0] = wf2T_h; o.Bl[0] = wf2T_l;
        o.Cf[0] = t; o.Cf[1] = t2;
        gemm_mma2<<<dim3(8, 16, 2), blk, GEMM_SMEM>>>(o);
    }
    ln_kernel2<<<ROWS, blk>>>(t, t2, bf2, y, g2, be2, out, nullptr, nullptr);
}

// round 11
// speedup vs baseline: 1.2179x; 1.0121x over previous
#include <cuda_runtime.h>
#include <cuda_bf16.h>
#include <math.h>
#include <stdint.h>

typedef unsigned int u32;
typedef unsigned long long u64;

#define BB 8
#define NN 256
#define DD 512
#define HH 16
#define KK 4
#define FFN 2048
#define ROWS (BB*NN)          // 2048
#define BH (BB*HH)            // 128

// ---------------- scratch globals --------------------------------------------
__device__ u32 g_xw_h[ROWS*256],  g_xw_l[ROWS*256];
__device__ u32 g_wqT_h[512*256],  g_wqT_l[512*256];
__device__ u32 g_wkT_h[512*256],  g_wkT_l[512*256];
__device__ u32 g_wvT_h[512*256],  g_wvT_l[512*256];
__device__ u32 g_w1T_h[512*1024], g_w1T_l[512*1024];
__device__ u32 g_w2T_h[512*256],  g_w2T_l[512*256];
__device__ u32 g_wf1T_h[2048*256], g_wf1T_l[2048*256];
__device__ u32 g_wf2T_h[512*1024], g_wf2T_l[512*1024];
__device__ u32 g_qp_h[BH*4096], g_qp_l[BH*4096];
__device__ u32 g_kp_h[BH*4096], g_kp_l[BH*4096];
__device__ u32 g_vp_h[BH*4096], g_vp_l[BH*4096];
__device__ u32 g_m2_h[ROWS*1024], g_m2_l[ROWS*1024];
__device__ u32 g_h1_h[ROWS*256],  g_h1_l[ROWS*256];
__device__ float g_t[ROWS*DD];
__device__ float g_t2[ROWS*DD];
__device__ float g_y[ROWS*DD];
__device__ u32 g_y_h[ROWS*256],   g_y_l[ROWS*256];
__device__ u32 g_f1_h[ROWS*1024], g_f1_l[ROWS*1024];
__device__ u32 g_allow[BB*KK*NN*8];

// ---------------- helpers ----------------------------------------------------
__device__ __forceinline__ u32 packbf(float a, float b) {
    __nv_bfloat16 ha = __float2bfloat16_rn(a);
    __nv_bfloat16 hb = __float2bfloat16_rn(b);
    return (u32)__bfloat16_as_ushort(ha) | ((u32)__bfloat16_as_ushort(hb) << 16);
}
__device__ __forceinline__ float bfval(float x) {
    return __bfloat162float(__float2bfloat16_rn(x));
}
__device__ __forceinline__ void split_pair(float a, float b, u32& hi, u32& lo) {
    float ah = bfval(a), bh_ = bfval(b);
    hi = packbf(a, b);
    lo = packbf(a - ah, b - bh_);
}

#define MMA16816(d, a, b) \
    asm volatile("mma.sync.aligned.m16n8k16.row.col.f32.bf16.bf16.f32 " \
        "{%0,%1,%2,%3},{%4,%5,%6,%7},{%8,%9},{%0,%1,%2,%3};" \
        : "+f"(d[0]), "+f"(d[1]), "+f"(d[2]), "+f"(d[3]) \
        : "r"(a[0]), "r"(a[1]), "r"(a[2]), "r"(a[3]), "r"(b[0]), "r"(b[1]))

__device__ __forceinline__ u32 smem_u32(const void* p) {
    u32 a;
    asm("{ .reg .u64 t; cvta.to.shared.u64 t, %1; cvt.u32.u64 %0, t; }"
        : "=r"(a) : "l"(p));
    return a;
}
__device__ __forceinline__ void cp16(u32 saddr, const void* gptr) {
    asm volatile("cp.async.cg.shared.global [%0], [%1], 16;"
                 :: "r"(saddr), "l"(gptr));
}

// ---------------- merged prep kernel -----------------------------------------
struct PrepArgs {
    const float* wsrc[7];
    u32* wdh[7];
    u32* wdl[7];
    int wK[7], wN[7];
    int tbase[8];
    const float* x; u32* xh; u32* xl;
    const int* mask; const float* dist; const float* dbar; u32* allow;
};

__global__ __launch_bounds__(256) void prep_all(PrepArgs pa)
{
    const int bx = blockIdx.x;
    const int tid = threadIdx.x;
    if (bx < 4096) {
        int task = 0;
        while (bx >= pa.tbase[task + 1]) task++;
        int tIdx = bx - pa.tbase[task];
        int K = pa.wK[task], N = pa.wN[task];
        int ntx = N >> 5;
        int n0 = (tIdx % ntx) * 32, k0 = (tIdx / ntx) * 32;
        __shared__ float tile[32][33];
        int tx = tid & 31, ty = tid >> 5;
        const float* src = pa.wsrc[task];
#pragma unroll
        for (int r = 0; r < 32; r += 8)
            tile[ty + r][tx] = src[(size_t)(k0 + ty + r) * N + n0 + tx];
        __syncthreads();
        int Kw = K >> 1;
        u32* dh = pa.wdh[task];
        u32* dl = pa.wdl[task];
#pragma unroll
        for (int r = 0; r < 32; r += 8) {
            int n = ty + r;
            if (tx < 16) {
                float a = tile[2 * tx][n], b = tile[2 * tx + 1][n];
                u32 h, l; split_pair(a, b, h, l);
                dh[(size_t)(n0 + n) * Kw + (k0 >> 1) + tx] = h;
                dl[(size_t)(n0 + n) * Kw + (k0 >> 1) + tx] = l;
            }
        }
    } else if (bx < 6144) {
        int idx = (bx - 4096) * 256 + tid;
        float2 v = ((const float2*)pa.x)[idx];
        u32 h, l; split_pair(v.x, v.y, h, l);
        pa.xh[idx] = h; pa.xl[idx] = l;
    } else {
        int idx = (bx - 6144) * 256 + tid;            // [b][row][ww]
        int ww = idx & 7, row = (idx >> 3) & 255, b = idx >> 11;
        float d0 = pa.dbar[0], d1 = pa.dbar[1], d2 = pa.dbar[2], d3 = pa.dbar[3];
        u32 w0 = 0, w1 = 0, w2 = 0, w3 = 0;
        for (int bit = 0; bit < 32; bit++) {
            int col = ww * 32 + bit;
            bool pad = pa.mask[((size_t)b * 256 + row) * 256 + col] != 0;
            float nd = 0.f;
            if (row > 0 && col > 0)
                nd = pa.dist[((size_t)b * 255 + row - 1) * 255 + col - 1];
            if (pad) {
                if (nd < d0) w0 |= 1u << bit;
                if (nd < d1) w1 |= 1u << bit;
                if (nd < d2) w2 |= 1u << bit;
                if (nd < d3) w3 |= 1u << bit;
            }
        }
        size_t base = ((size_t)b * 4 * 256 + row) * 8 + ww;
        pa.allow[base] = w0;
        pa.allow[base + 2048] = w1;
        pa.allow[base + 4096] = w2;
        pa.allow[base + 6144] = w3;
    }
}

// ---------------- GEMM: 128x64 tile, BK=64, cp.async 2-stage, 1 sync/ktile ---
#define ASTR 36
#define A_PL (128*ASTR)                    // 4608 words per A plane
#define B_PL (64*ASTR)                     // 2304 words per B plane
#define STG_W (2*A_PL + 2*B_PL)            // 13824 words per stage
#define GEMM_SMEM (2 * STG_W * 4)          // 110592 B

struct GemmOp {
    const u32 *Ah, *Al;
    const u32 *Bh[3], *Bl[3];
    const float* bias[3];
    float* Cf[3];
    u32 *Ch[3], *Cl[3];
    int N, K, act, mode, ksplit;           // mode: 0 f32+bias, 1 planes, 2 head planes, 3 raw f32
};

__global__ __launch_bounds__(256, 2) void gemm_mma2(GemmOp op)
{
    extern __shared__ u32 sm[];
    const u32 smb = smem_u32(sm);
    const int z = blockIdx.z;
    const int zb = op.ksplit ? 0 : z;
    const u32* __restrict__ Ah = op.Ah;
    const u32* __restrict__ Al = op.Al;
    const u32* __restrict__ Bh = op.Bh[zb];
    const u32* __restrict__ Bl = op.Bl[zb];
    const int N = op.N, K = op.K, act = op.act, mode = op.mode;
    const int Kw = K >> 1;
    const int Keff = op.ksplit ? (K >> 1) : K;
    const int koffw = op.ksplit ? z * (K >> 2) : 0;
    const int nkt = Keff >> 6;

    const int tid = threadIdx.x;
    const int lane = tid & 31, wid = tid >> 5;
    const int wm = wid & 3, wn = wid >> 2;
    const int g = lane >> 2, t = lane & 3;
    const int m0 = blockIdx.y * 128, n0 = blockIdx.x * 64;

    float acc[2][4][4];
#pragma unroll
    for (int mt = 0; mt < 2; mt++)
#pragma unroll
        for (int nt = 0; nt < 4; nt++)
#pragma unroll
            for (int i = 0; i < 4; i++) acc[mt][nt][i] = 0.f;

    const int srow = tid >> 3, sq = tid & 7;   // base row/quad for async copies

    auto issue = [&](int s, int kt) {
        const u32 st = smb + s * (STG_W * 4);
        const int ktw = koffw + kt * 32;
#pragma unroll
        for (int i = 0; i < 4; i++) {
            int row = srow + 32 * i;
            size_t gs = (size_t)(m0 + row) * Kw + ktw + sq * 4;
            u32 sa = st + (row * ASTR + sq * 4) * 4;
            cp16(sa, Ah + gs);
            cp16(sa + A_PL * 4, Al + gs);
        }
#pragma unroll
        for (int i = 0; i < 2; i++) {
            int row = srow + 32 * i;
            size_t gs = (size_t)(n0 + row) * Kw + ktw + sq * 4;
            u32 sa = st + (2 * A_PL + row * ASTR + sq * 4) * 4;
            cp16(sa, Bh + gs);
            cp16(sa + B_PL * 4, Bl + gs);
        }
        asm volatile("cp.async.commit_group;");
    };

    issue(0, 0);
    for (int kt = 0; kt < nkt; kt++) {
        // stage kt is the only pending group -> drain it
        asm volatile("cp.async.wait_group 0;");
        __syncthreads();
        // buffer (kt+1)&1 was last read in iteration kt-1; the barrier above
        // proves all warps are past it, so it's free to overwrite now.
        if (kt + 1 < nkt) issue((kt + 1) & 1, kt + 1);

        const u32* As_h = sm + (kt & 1) * STG_W;
        const u32* As_l = As_h + A_PL;
        const u32* Bs_h = As_h + 2 * A_PL;
        const u32* Bs_l = Bs_h + B_PL;
#pragma unroll
        for (int sel = 0; sel < 4; sel++) {
            const int ko = sel * 8;
            u32 ah[2][4], al[2][4];
#pragma unroll
            for (int mt = 0; mt < 2; mt++) {
                int row = wm * 32 + mt * 16 + g;
                int b0 = row * ASTR + ko + t;
                int b8 = (row + 8) * ASTR + ko + t;
                ah[mt][0] = As_h[b0];     ah[mt][1] = As_h[b8];
                ah[mt][2] = As_h[b0 + 4]; ah[mt][3] = As_h[b8 + 4];
                al[mt][0] = As_l[b0];     al[mt][1] = As_l[b8];
                al[mt][2] = As_l[b0 + 4]; al[mt][3] = As_l[b8 + 4];
            }
#pragma unroll
            for (int nt = 0; nt < 4; nt++) {
                int n = wn * 32 + nt * 8 + g;
                int bb = n * ASTR + ko + t;
                u32 bhf[2] = {Bs_h[bb], Bs_h[bb + 4]};
                u32 blf[2] = {Bs_l[bb], Bs_l[bb + 4]};
#pragma unroll
                for (int mt = 0; mt < 2; mt++) {
                    MMA16816(acc[mt][nt], ah[mt], bhf);
                    MMA16816(acc[mt][nt], ah[mt], blf);
                    MMA16816(acc[mt][nt], al[mt], bhf);
                }
            }
        }
    }

    // epilogue
    const float* bias = op.bias[zb];
    float* Cf = op.Cf[z];
    u32* Ch = op.Ch[z];
    u32* Cl = op.Cl[z];
#pragma unroll
    for (int mt = 0; mt < 2; mt++) {
#pragma unroll
        for (int nt = 0; nt < 4; nt++) {
            int col = n0 + wn * 32 + nt * 8 + 2 * t;
            float bia0 = 0.f, bia1 = 0.f;
            if (mode != 3) { bia0 = bias[col]; bia1 = bias[col + 1]; }
#pragma unroll
            for (int half = 0; half < 2; half++) {
                int row = m0 + wm * 32 + mt * 16 + g + half * 8;
                float c0 = acc[mt][nt][half * 2 + 0] + bia0;
                float c1 = acc[mt][nt][half * 2 + 1] + bia1;
                if (act == 1 && mode != 3) {
                    c0 = c0 / (1.f + expf(-c0)); c1 = c1 / (1.f + expf(-c1));
                } else if (act == 2 && mode != 3) {
                    c0 = c0 * normcdff(c0); c1 = c1 * normcdff(c1);
                }
                if (mode == 0 || mode == 3) {
                    *(float2*)(Cf + (size_t)row * N + col) = make_float2(c0, c1);
                } else {
                    u32 h, l; split_pair(c0, c1, h, l);
                    size_t w;
                    if (mode == 2)
                        w = (size_t)((row >> 8) * 16 + (col >> 5)) * 4096
                          + (size_t)(row & 255) * 16 + ((col & 31) >> 1);
                    else
                        w = ((size_t)row * N + col) >> 1;
                    Ch[w] = h; Cl[w] = l;
                }
            }
        }
    }
}

// ---------------- combine split-K partials + bias + silu -> planes -----------
__global__ __launch_bounds__(256) void combine_silu(
    const float* __restrict__ p0, const float* __restrict__ p1,
    const float* __restrict__ bias, u32* __restrict__ oh, u32* __restrict__ ol)
{
    int i = blockIdx.x * 256 + threadIdx.x;       // word over [ROWS][256]
    int col = (i & 255) * 2;
    float2 a = ((const float2*)p0)[i];
    float2 b = ((const float2*)p1)[i];
    float c0 = a.x + b.x + bias[col];
    float c1 = a.y + b.y + bias[col + 1];
    c0 = c0 / (1.f + expf(-c0));
    c1 = c1 / (1.f + expf(-c1));
    u32 h, l; split_pair(c0, c1, h, l);
    oh[i] = h; ol[i] = l;
}

// ---------------- fused multi-scale attention via HMMA -----------------------
// Grid (bh, tile): one 64-row q-tile per block, 512 blocks.
__global__ __launch_bounds__(256) void attn_mma(
    const u32* __restrict__ qh, const u32* __restrict__ ql,
    const u32* __restrict__ kh, const u32* __restrict__ kl,
    const u32* __restrict__ vh, const u32* __restrict__ vl,
    const float* __restrict__ bias, const u32* __restrict__ allow,
    u32* __restrict__ m2h, u32* __restrict__ m2l)
{
    extern __shared__ u32 smemU[];
    u32* Ksh = smemU;
    u32* Ksl = Ksh + 256 * 17;
    u32* vTh = Ksl + 256 * 17;
    u32* vTl = vTh + 32 * 129;
    float* comb = (float*)(vTl + 32 * 129);
    float* psum = comb + 2 * 64 * 33;

    const int bh = blockIdx.x;
    const int b = bh >> 4;
    const int hh = bh & 15;
    const int tid = threadIdx.x;
    const int lane = tid & 31;
    const int w = tid >> 5;
    const int g = lane >> 2, t = lane & 3;
    const int wm = w >> 1, wn = w & 1;
    const size_t base = (size_t)bh * 4096;

#pragma unroll
    for (int it = 0; it < 16; it++) {
        int idx = tid + 256 * it;
        int row = idx >> 4, wd = idx & 15;
        Ksh[row * 17 + wd] = kh[base + idx];
        Ksl[row * 17 + wd] = kl[base + idx];
    }
    {
        const unsigned short* vhp = (const unsigned short*)vh + base * 2;
        const unsigned short* vlp = (const unsigned short*)vl + base * 2;
#pragma unroll
        for (int it = 0; it < 16; it++) {
            int idx = tid + 256 * it;
            int n = idx & 31, wk = idx >> 5;
            vTh[n * 129 + wk] = (u32)vhp[(2 * wk) * 32 + n]
                              | ((u32)vhp[(2 * wk + 1) * 32 + n] << 16);
            vTl[n * 129 + wk] = (u32)vlp[(2 * wk) * 32 + n]
                              | ((u32)vlp[(2 * wk + 1) * 32 + n] << 16);
        }
    }
    __syncthreads();

    const float scale = 0.17677669529663687f;
    const int tile = blockIdx.y;
    {
        const int r0 = tile * 64 + wm * 16 + g;

        float acc[16][4];
#pragma unroll
        for (int nt = 0; nt < 16; nt++)
#pragma unroll
            for (int i = 0; i < 4; i++) acc[nt][i] = 0.f;

#pragma unroll
        for (int kc = 0; kc < 2; kc++) {
            int w0 = kc * 8 + t;
            u32 ah[4], al[4];
            ah[0] = qh[base + (size_t)r0 * 16 + w0];
            ah[1] = qh[base + (size_t)(r0 + 8) * 16 + w0];
            ah[2] = qh[base + (size_t)r0 * 16 + w0 + 4];
            ah[3] = qh[base + (size_t)(r0 + 8) * 16 + w0 + 4];
            al[0] = ql[base + (size_t)r0 * 16 + w0];
            al[1] = ql[base + (size_t)(r0 + 8) * 16 + w0];
            al[2] = ql[base + (size_t)r0 * 16 + w0 + 4];
            al[3] = ql[base + (size_t)(r0 + 8) * 16 + w0 + 4];
#pragma unroll
            for (int nt = 0; nt < 16; nt++) {
                int n = wn * 128 + nt * 8 + g;
                int bb = n * 17 + kc * 8 + t;
                u32 bhf[2] = {Ksh[bb], Ksh[bb + 4]};
                u32 blf[2] = {Ksl[bb], Ksl[bb + 4]};
                MMA16816(acc[nt], ah, bhf);
                MMA16816(acc[nt], ah, blf);
                MMA16816(acc[nt], al, bhf);
            }
        }

        for (int ks = 0; ks < 4; ks++) {
            float acc2[4][4];
#pragma unroll
            for (int vn = 0; vn < 4; vn++)
#pragma unroll
                for (int i = 0; i < 4; i++) acc2[vn][i] = 0.f;
            float s0 = 0.f, s1 = 0.f;

            const size_t abase = ((size_t)(b * 4 + ks) * 256);
            u32 aw0[4], aw1[4];
#pragma unroll
            for (int ww = 0; ww < 4; ww++) {
                aw0[ww] = allow[(abase + r0) * 8 + wn * 4 + ww];
                aw1[ww] = allow[(abase + r0 + 8) * 8 + wn * 4 + ww];
            }
            const float* bp0 = bias + (abase + r0) * 256 + wn * 128;
            const float* bp1 = bias + (abase + r0 + 8) * 256 + wn * 128;

#pragma unroll
            for (int kc = 0; kc < 8; kc++) {
                u32 pa_h[4], pa_l[4];
#pragma unroll
                for (int sub = 0; sub < 2; sub++) {
                    int nt = 2 * kc + sub;
                    int coff = nt * 8 + 2 * t;
                    float2 bv0 = *(const float2*)(bp0 + coff);
                    float2 bv1 = *(const float2*)(bp1 + coff);
                    int wi = kc >> 1;
                    int bit = (nt & 3) * 8 + 2 * t;
                    float p00 = 0.f, p01 = 0.f, p10 = 0.f, p11 = 0.f;
                    if ((aw0[wi] >> bit) & 1)
                        p00 = __expf(fmaf(acc[nt][0], scale, bv0.x));
                    if ((aw0[wi] >> (bit + 1)) & 1)
                        p01 = __expf(fmaf(acc[nt][1], scale, bv0.y));
                    if ((aw1[wi] >> bit) & 1)
                        p10 = __expf(fmaf(acc[nt][2], scale, bv1.x));
                    if ((aw1[wi] >> (bit + 1)) & 1)
                        p11 = __expf(fmaf(acc[nt][3], scale, bv1.y));
                    s0 += p00 + p01;
                    s1 += p10 + p11;
                    split_pair(p00, p01, pa_h[sub * 2], pa_l[sub * 2]);
                    split_pair(p10, p11, pa_h[sub * 2 + 1], pa_l[sub * 2 + 1]);
                }
                int kcg = wn * 8 + kc;
#pragma unroll
                for (int vn = 0; vn < 4; vn++) {
                    int n = vn * 8 + g;
                    int vb = n * 129 + kcg * 8 + t;
                    u32 bhf[2] = {vTh[vb], vTh[vb + 4]};
                    u32 blf[2] = {vTl[vb], vTl[vb + 4]};
                    MMA16816(acc2[vn], pa_h, bhf);
                    MMA16816(acc2[vn], pa_h, blf);
                    MMA16816(acc2[vn], pa_l, bhf);
                }
            }

            s0 += __shfl_xor_sync(0xffffffffu, s0, 1);
            s0 += __shfl_xor_sync(0xffffffffu, s0, 2);
            s1 += __shfl_xor_sync(0xffffffffu, s1, 1);
            s1 += __shfl_xor_sync(0xffffffffu, s1, 2);
            if (t == 0) {
                psum[(wm * 16 + g) * 2 + wn] = s0;
                psum[(wm * 16 + g + 8) * 2 + wn] = s1;
            }
            float* cw = comb + wn * 64 * 33;
#pragma unroll
            for (int vn = 0; vn < 4; vn++) {
                int c = vn * 8 + 2 * t;
                cw[(wm * 16 + g) * 33 + c]     = acc2[vn][0];
                cw[(wm * 16 + g) * 33 + c + 1] = acc2[vn][1];
                cw[(wm * 16 + g + 8) * 33 + c]     = acc2[vn][2];
                cw[(wm * 16 + g + 8) * 33 + c + 1] = acc2[vn][3];
            }
            __syncthreads();
            // msg2 row = b*256 + np, np = (ks*16+h)*4 + (d>>3); col = (d&7)*256 + n
            for (int i = tid; i < 1024; i += 256) {
                int pr = i >> 5;
                int c = i & 31;
                int rl0 = 2 * pr, rl1 = rl0 + 1;
                float v0 = (comb[rl0 * 33 + c] + comb[64 * 33 + rl0 * 33 + c])
                         / (psum[rl0 * 2] + psum[rl0 * 2 + 1]);
                float v1 = (comb[rl1 * 33 + c] + comb[64 * 33 + rl1 * 33 + c])
                         / (psum[rl1 * 2] + psum[rl1 * 2 + 1]);
                int row0 = tile * 64 + rl0;
                int np = (((ks << 4) | hh) << 2) | (c >> 3);
                size_t wI = ((size_t)b * 256 + np) * 1024
                          + ((c & 7) << 7) + (row0 >> 1);
                u32 hw, lw; split_pair(v0, v1, hw, lw);
                m2h[wI] = hw; m2l[wI] = lw;
            }
            __syncthreads();
        }
    }
}

// ---------------- residual + LayerNorm (2 partials + bias) -------------------
__global__ __launch_bounds__(256) void ln_kernel2(
    const float* __restrict__ a0, const float* __restrict__ a1,
    const float* __restrict__ bb, const float* __restrict__ res,
    const float* __restrict__ g, const float* __restrict__ be,
    float* __restrict__ out, u32* __restrict__ oh, u32* __restrict__ ol)
{
    const int row = blockIdx.x, tid = threadIdx.x;
    __shared__ float sred[8];
    float2 av = ((const float2*)(a0 + (size_t)row * 512))[tid];
    float2 a2 = ((const float2*)(a1 + (size_t)row * 512))[tid];
    float2 rv = ((const float2*)(res + (size_t)row * 512))[tid];
    float b0 = bb[2 * tid], b1 = bb[2 * tid + 1];
    float v0 = av.x + a2.x + b0 + rv.x;
    float v1 = av.y + a2.y + b1 + rv.y;

    float s = v0 + v1;
#pragma unroll
    for (int o = 16; o > 0; o >>= 1) s += __shfl_xor_sync(0xffffffffu, s, o);
    if ((tid & 31) == 0) sred[tid >> 5] = s;
    __syncthreads();
    float mean = 0.f;
#pragma unroll
    for (int i = 0; i < 8; i++) mean += sred[i];
    mean *= (1.f / 512.f);
    __syncthreads();

    float d0 = v0 - mean, d1 = v1 - mean;
    float vs = d0 * d0 + d1 * d1;
#pragma unroll
    for (int o = 16; o > 0; o >>= 1) vs += __shfl_xor_sync(0xffffffffu, vs, o);
    if ((tid & 31) == 0) sred[tid >> 5] = vs;
    __syncthreads();
    float var = 0.f;
#pragma unroll
    for (int i = 0; i < 8; i++) var += sred[i];
    var *= (1.f / 512.f);
    float inv = rsqrtf(var + 1e-6f);

    float2 gv = ((const float2*)g)[tid];
    float2 bv = ((const float2*)be)[tid];
    float o0 = d0 * inv * gv.x + bv.x;
    float o1 = d1 * inv * gv.y + bv.y;
    ((float2*)(out + (size_t)row * 512))[tid] = make_float2(o0, o1);
    if (oh) {
        u32 h, l; split_pair(o0, o1, h, l);
        oh[(size_t)row * 256 + tid] = h;
        ol[(size_t)row * 256 + tid] = l;
    }
}

// ---------------- launch ------------------------------------------------------
extern "C" void kernel_launch(void* const* d_in, const int* in_sizes, int n_in,
                              void* d_out, int out_size)
{
    const float* x         = (const float*)d_in[0];
    const float* dist      = (const float*)d_in[1];
    const float* dist_bar  = (const float*)d_in[2];
    const float* attn_bias = (const float*)d_in[3];
    const int*   mask      = (const int*)d_in[4];
    int wo = (n_in >= 24 && in_sizes[5] == 1) ? 6 : 5;
    const float* Wq  = (const float*)d_in[wo + 0];
    const float* bq  = (const float*)d_in[wo + 1];
    const float* Wk  = (const float*)d_in[wo + 2];
    const float* bk  = (const float*)d_in[wo + 3];
    const float* Wv  = (const float*)d_in[wo + 4];
    const float* bv  = (const float*)d_in[wo + 5];
    const float* W1  = (const float*)d_in[wo + 6];
    const float* b1  = (const float*)d_in[wo + 7];
    const float* W2  = (const float*)d_in[wo + 8];
    const float* b2  = (const float*)d_in[wo + 9];
    const float* g1  = (const float*)d_in[wo + 10];
    const float* be1 = (const float*)d_in[wo + 11];
    const float* Wf1 = (const float*)d_in[wo + 12];
    const float* bf1 = (const float*)d_in[wo + 13];
    const float* Wf2 = (const float*)d_in[wo + 14];
    const float* bf2 = (const float*)d_in[wo + 15];
    const float* g2  = (const float*)d_in[wo + 16];
    const float* be2 = (const float*)d_in[wo + 17];
    float* out = (float*)d_out;

#define SYM(p, s) cudaGetSymbolAddress((void**)&p, s)
    u32 *xw_h, *xw_l, *wqT_h, *wqT_l, *wkT_h, *wkT_l, *wvT_h, *wvT_l;
    u32 *w1T_h, *w1T_l, *w2T_h, *w2T_l, *wf1T_h, *wf1T_l, *wf2T_h, *wf2T_l;
    u32 *qp_h, *qp_l, *kp_h, *kp_l, *vp_h, *vp_l;
    u32 *m2_h, *m2_l, *h1_h, *h1_l, *y_h, *y_l, *f1_h, *f1_l, *allow;
    float *t, *t2, *y;
    SYM(xw_h, g_xw_h); SYM(xw_l, g_xw_l);
    SYM(wqT_h, g_wqT_h); SYM(wqT_l, g_wqT_l);
    SYM(wkT_h, g_wkT_h); SYM(wkT_l, g_wkT_l);
    SYM(wvT_h, g_wvT_h); SYM(wvT_l, g_wvT_l);
    SYM(w1T_h, g_w1T_h); SYM(w1T_l, g_w1T_l);
    SYM(w2T_h, g_w2T_h); SYM(w2T_l, g_w2T_l);
    SYM(wf1T_h, g_wf1T_h); SYM(wf1T_l, g_wf1T_l);
    SYM(wf2T_h, g_wf2T_h); SYM(wf2T_l, g_wf2T_l);
    SYM(qp_h, g_qp_h); SYM(qp_l, g_qp_l);
    SYM(kp_h, g_kp_h); SYM(kp_l, g_kp_l);
    SYM(vp_h, g_vp_h); SYM(vp_l, g_vp_l);
    SYM(m2_h, g_m2_h); SYM(m2_l, g_m2_l);
    SYM(h1_h, g_h1_h); SYM(h1_l, g_h1_l);
    SYM(y_h, g_y_h); SYM(y_l, g_y_l);
    SYM(f1_h, g_f1_h); SYM(f1_l, g_f1_l);
    SYM(allow, g_allow);
    SYM(t, g_t); SYM(t2, g_t2); SYM(y, g_y);

    const int smem_attn = (256 * 17 + 32 * 129) * 2 * 4 + (2 * 64 * 33 + 128) * 4;
    static int attrSet = 0;
    if (!attrSet) {
        cudaFuncSetAttribute(attn_mma,
                             cudaFuncAttributeMaxDynamicSharedMemorySize, smem_attn);
        cudaFuncSetAttribute(gemm_mma2,
                             cudaFuncAttributeMaxDynamicSharedMemorySize, GEMM_SMEM);
        attrSet = 1;
    }

    dim3 blk(256);

    // merged prep
    PrepArgs pa;
    const float* wsrc[7] = {Wq, Wk, Wv, W1, W2, Wf1, Wf2};
    u32* wdh[7] = {wqT_h, wkT_h, wvT_h, w1T_h, w2T_h, wf1T_h, wf2T_h};
    u32* wdl[7] = {wqT_l, wkT_l, wvT_l, w1T_l, w2T_l, wf1T_l, wf2T_l};
    int wK[7] = {512, 512, 512, 2048, 512, 512, 2048};
    int wN[7] = {512, 512, 512, 512, 512, 2048, 512};
    int tbase[8] = {0, 256, 512, 768, 1792, 2048, 3072, 4096};
    for (int i = 0; i < 7; i++) {
        pa.wsrc[i] = wsrc[i]; pa.wdh[i] = wdh[i]; pa.wdl[i] = wdl[i];
        pa.wK[i] = wK[i]; pa.wN[i] = wN[i];
    }
    for (int i = 0; i < 8; i++) pa.tbase[i] = tbase[i];
    pa.x = x; pa.xh = xw_h; pa.xl = xw_l;
    pa.mask = mask; pa.dist = dist; pa.dbar = dist_bar; pa.allow = allow;
    prep_all<<<6208, blk>>>(pa);

    auto mkop = [](const u32* Ah, const u32* Al, int N, int K, int act,
                   int mode, int ksplit) {
        GemmOp o;
        o.Ah = Ah; o.Al = Al; o.N = N; o.K = K; o.act = act;
        o.mode = mode; o.ksplit = ksplit;
        for (int i = 0; i < 3; i++) {
            o.Bh[i] = nullptr; o.Bl[i] = nullptr; o.bias[i] = nullptr;
            o.Cf[i] = nullptr; o.Ch[i] = nullptr; o.Cl[i] = nullptr;
        }
        return o;
    };

    // QKV fused: z = {q,k,v}
    {
        GemmOp o = mkop(xw_h, xw_l, 512, 512, 0, 2, 0);
        o.Bh[0] = wqT_h; o.Bl[0] = wqT_l; o.bias[0] = bq; o.Ch[0] = qp_h; o.Cl[0] = qp_l;
        o.Bh[1] = wkT_h; o.Bl[1] = wkT_l; o.bias[1] = bk; o.Ch[1] = kp_h; o.Cl[1] = kp_l;
        o.Bh[2] = wvT_h; o.Bl[2] = wvT_l; o.bias[2] = bv; o.Ch[2] = vp_h; o.Cl[2] = vp_l;
        gemm_mma2<<<dim3(8, 16, 3), blk, GEMM_SMEM>>>(o);
    }

    attn_mma<<<dim3(BH, 4), blk, smem_attn>>>(qp_h, qp_l, kp_h, kp_l, vp_h, vp_l,
                                              attn_bias, allow, m2_h, m2_l);

    // W1 split-K=2 -> raw partials -> combine(silu) -> h1 planes
    {
        GemmOp o = mkop(m2_h, m2_l, 512, 2048, 1, 3, 1);
        o.Bh[0] = w1T_h; o.Bl[0] = w1T_l;
        o.Cf[0] = t; o.Cf[1] = t2;
        gemm_mma2<<<dim3(8, 16, 2), blk, GEMM_SMEM>>>(o);
    }
    combine_silu<<<(ROWS * 256) / 256, blk>>>(t, t2, b1, h1_h, h1_l);

    // W2 split-K=2 -> raw partials -> ln2
    {
        GemmOp o = mkop(h1_h, h1_l, 512, 512, 0, 3, 1);
        o.Bh[0] = w2T_h; o.Bl[0] = w2T_l;
        o.Cf[0] = t; o.Cf[1] = t2;
        gemm_mma2<<<dim3(8, 16, 2), blk, GEMM_SMEM>>>(o);
    }
    ln_kernel2<<<ROWS, blk>>>(t, t2, b2, x, g1, be1, y, y_h, y_l);

    // FFN1 (N=2048, 512 blocks) -> gelu planes
    {
        GemmOp o = mkop(y_h, y_l, FFN, 512, 2, 1, 0);
        o.Bh[0] = wf1T_h; o.Bl[0] = wf1T_l; o.bias[0] = bf1;
        o.Ch[0] = f1_h; o.Cl[0] = f1_l;
        gemm_mma2<<<dim3(32, 16, 1), blk, GEMM_SMEM>>>(o);
    }

    // FFN2 split-K=2 -> raw partials -> ln2
    {
        GemmOp o = mkop(f1_h, f1_l, 512, 2048, 0, 3, 1);
        o.Bh[0] = wf2T_h; o.Bl[0] = wf2T_l;
        o.Cf[0] = t; o.Cf[1] = t2;
        gemm_mma2<<<dim3(8, 16, 2), blk, GEMM_SMEM>>>(o);
    }
    ln_kernel2<<<ROWS, blk>>>(t, t2, bf2, y, g2, be2, out, nullptr, nullptr);
}

// round 12
// speedup vs baseline: 1.2474x; 1.0242x over previous
#include <cuda_runtime.h>
#include <cuda_bf16.h>
#include <math.h>
#include <stdint.h>

typedef unsigned int u32;
typedef unsigned long long u64;

#define BB 8
#define NN 256
#define DD 512
#define HH 16
#define KK 4
#define FFN 2048
#define ROWS (BB*NN)          // 2048
#define BH (BB*HH)            // 128

// ---------------- scratch globals --------------------------------------------
__device__ u32 g_xw_h[ROWS*256],  g_xw_l[ROWS*256];
__device__ u32 g_wqT_h[512*256],  g_wqT_l[512*256];
__device__ u32 g_wkT_h[512*256],  g_wkT_l[512*256];
__device__ u32 g_wvT_h[512*256],  g_wvT_l[512*256];
__device__ u32 g_w1T_h[512*1024], g_w1T_l[512*1024];
__device__ u32 g_w2T_h[512*256],  g_w2T_l[512*256];
__device__ u32 g_wf1T_h[2048*256], g_wf1T_l[2048*256];
__device__ u32 g_wf2T_h[512*1024], g_wf2T_l[512*1024];
__device__ u32 g_qp_h[BH*4096], g_qp_l[BH*4096];
__device__ u32 g_kp_h[BH*4096], g_kp_l[BH*4096];
__device__ u32 g_vp_h[BH*4096], g_vp_l[BH*4096];
__device__ u32 g_m2_h[ROWS*1024], g_m2_l[ROWS*1024];
__device__ u32 g_h1_h[ROWS*256],  g_h1_l[ROWS*256];
__device__ float g_t[ROWS*DD];
__device__ float g_t2[ROWS*DD];
__device__ float g_y[ROWS*DD];
__device__ u32 g_y_h[ROWS*256],   g_y_l[ROWS*256];
__device__ u32 g_f1_h[ROWS*1024], g_f1_l[ROWS*1024];
__device__ u32 g_allow[BB*KK*NN*8];

// ---------------- helpers ----------------------------------------------------
__device__ __forceinline__ u32 packbf(float a, float b) {
    __nv_bfloat16 ha = __float2bfloat16_rn(a);
    __nv_bfloat16 hb = __float2bfloat16_rn(b);
    return (u32)__bfloat16_as_ushort(ha) | ((u32)__bfloat16_as_ushort(hb) << 16);
}
__device__ __forceinline__ float bfval(float x) {
    return __bfloat162float(__float2bfloat16_rn(x));
}
__device__ __forceinline__ void split_pair(float a, float b, u32& hi, u32& lo) {
    float ah = bfval(a), bh_ = bfval(b);
    hi = packbf(a, b);
    lo = packbf(a - ah, b - bh_);
}

#define MMA16816(d, a, b) \
    asm volatile("mma.sync.aligned.m16n8k16.row.col.f32.bf16.bf16.f32 " \
        "{%0,%1,%2,%3},{%4,%5,%6,%7},{%8,%9},{%0,%1,%2,%3};" \
        : "+f"(d[0]), "+f"(d[1]), "+f"(d[2]), "+f"(d[3]) \
        : "r"(a[0]), "r"(a[1]), "r"(a[2]), "r"(a[3]), "r"(b[0]), "r"(b[1]))

__device__ __forceinline__ void ldm4(u32* r, u32 saddr) {
    asm volatile("ldmatrix.sync.aligned.m8n8.x4.shared.b16 {%0,%1,%2,%3}, [%4];"
        : "=r"(r[0]), "=r"(r[1]), "=r"(r[2]), "=r"(r[3]) : "r"(saddr));
}

__device__ __forceinline__ u32 smem_u32(const void* p) {
    u32 a;
    asm("{ .reg .u64 t; cvta.to.shared.u64 t, %1; cvt.u32.u64 %0, t; }"
        : "=r"(a) : "l"(p));
    return a;
}
__device__ __forceinline__ void cp16(u32 saddr, const void* gptr) {
    asm volatile("cp.async.cg.shared.global [%0], [%1], 16;"
                 :: "r"(saddr), "l"(gptr));
}

// ---------------- merged prep kernel -----------------------------------------
struct PrepArgs {
    const float* wsrc[7];
    u32* wdh[7];
    u32* wdl[7];
    int wK[7], wN[7];
    int tbase[8];
    const float* x; u32* xh; u32* xl;
    const int* mask; const float* dist; const float* dbar; u32* allow;
};

__global__ __launch_bounds__(256) void prep_all(PrepArgs pa)
{
    const int bx = blockIdx.x;
    const int tid = threadIdx.x;
    if (bx < 4096) {
        int task = 0;
        while (bx >= pa.tbase[task + 1]) task++;
        int tIdx = bx - pa.tbase[task];
        int K = pa.wK[task], N = pa.wN[task];
        int ntx = N >> 5;
        int n0 = (tIdx % ntx) * 32, k0 = (tIdx / ntx) * 32;
        __shared__ float tile[32][33];
        int tx = tid & 31, ty = tid >> 5;
        const float* src = pa.wsrc[task];
#pragma unroll
        for (int r = 0; r < 32; r += 8)
            tile[ty + r][tx] = src[(size_t)(k0 + ty + r) * N + n0 + tx];
        __syncthreads();
        int Kw = K >> 1;
        u32* dh = pa.wdh[task];
        u32* dl = pa.wdl[task];
#pragma unroll
        for (int r = 0; r < 32; r += 8) {
            int n = ty + r;
            if (tx < 16) {
                float a = tile[2 * tx][n], b = tile[2 * tx + 1][n];
                u32 h, l; split_pair(a, b, h, l);
                dh[(size_t)(n0 + n) * Kw + (k0 >> 1) + tx] = h;
                dl[(size_t)(n0 + n) * Kw + (k0 >> 1) + tx] = l;
            }
        }
    } else if (bx < 6144) {
        int idx = (bx - 4096) * 256 + tid;
        float2 v = ((const float2*)pa.x)[idx];
        u32 h, l; split_pair(v.x, v.y, h, l);
        pa.xh[idx] = h; pa.xl[idx] = l;
    } else {
        int idx = (bx - 6144) * 256 + tid;            // [b][row][ww]
        int ww = idx & 7, row = (idx >> 3) & 255, b = idx >> 11;
        float d0 = pa.dbar[0], d1 = pa.dbar[1], d2 = pa.dbar[2], d3 = pa.dbar[3];
        u32 w0 = 0, w1 = 0, w2 = 0, w3 = 0;
        for (int bit = 0; bit < 32; bit++) {
            int col = ww * 32 + bit;
            bool pad = pa.mask[((size_t)b * 256 + row) * 256 + col] != 0;
            float nd = 0.f;
            if (row > 0 && col > 0)
                nd = pa.dist[((size_t)b * 255 + row - 1) * 255 + col - 1];
            if (pad) {
                if (nd < d0) w0 |= 1u << bit;
                if (nd < d1) w1 |= 1u << bit;
                if (nd < d2) w2 |= 1u << bit;
                if (nd < d3) w3 |= 1u << bit;
            }
        }
        size_t base = ((size_t)b * 4 * 256 + row) * 8 + ww;
        pa.allow[base] = w0;
        pa.allow[base + 2048] = w1;
        pa.allow[base + 4096] = w2;
        pa.allow[base + 6144] = w3;
    }
}

// ---------------- GEMM: 128x64, BK=64, cp.async 2-stage, ldmatrix frags ------
#define ASTR 36
#define A_PL (128*ASTR)                    // 4608 words per A plane
#define B_PL (64*ASTR)                     // 2304 words per B plane
#define STG_W (2*A_PL + 2*B_PL)            // 13824 words per stage
#define GEMM_SMEM (2 * STG_W * 4)          // 110592 B

struct GemmOp {
    const u32 *Ah, *Al;
    const u32 *Bh[3], *Bl[3];
    const float* bias[3];
    float* Cf[3];
    u32 *Ch[3], *Cl[3];
    int N, K, act, mode, ksplit;           // mode: 0 f32+bias, 1 planes, 2 head planes, 3 raw f32
};

__global__ __launch_bounds__(256, 2) void gemm_mma2(GemmOp op)
{
    extern __shared__ u32 sm[];
    const u32 smb = smem_u32(sm);
    const int z = blockIdx.z;
    const int zb = op.ksplit ? 0 : z;
    const u32* __restrict__ Ah = op.Ah;
    const u32* __restrict__ Al = op.Al;
    const u32* __restrict__ Bh = op.Bh[zb];
    const u32* __restrict__ Bl = op.Bl[zb];
    const int N = op.N, K = op.K, act = op.act, mode = op.mode;
    const int Kw = K >> 1;
    const int Keff = op.ksplit ? (K >> 1) : K;
    const int koffw = op.ksplit ? z * (K >> 2) : 0;
    const int nkt = Keff >> 6;

    const int tid = threadIdx.x;
    const int lane = tid & 31, wid = tid >> 5;
    const int wm = wid & 3, wn = wid >> 2;
    const int g = lane >> 2, t = lane & 3;
    const int m0 = blockIdx.y * 128, n0 = blockIdx.x * 64;

    float acc[2][4][4];
#pragma unroll
    for (int mt = 0; mt < 2; mt++)
#pragma unroll
        for (int nt = 0; nt < 4; nt++)
#pragma unroll
            for (int i = 0; i < 4; i++) acc[mt][nt][i] = 0.f;

    const int srow = tid >> 3, sq = tid & 7;   // base row/quad for async copies

    auto issue = [&](int s, int kt) {
        const u32 st = smb + s * (STG_W * 4);
        const int ktw = koffw + kt * 32;
#pragma unroll
        for (int i = 0; i < 4; i++) {
            int row = srow + 32 * i;
            size_t gs = (size_t)(m0 + row) * Kw + ktw + sq * 4;
            u32 sa = st + (row * ASTR + sq * 4) * 4;
            cp16(sa, Ah + gs);
            cp16(sa + A_PL * 4, Al + gs);
        }
#pragma unroll
        for (int i = 0; i < 2; i++) {
            int row = srow + 32 * i;
            size_t gs = (size_t)(n0 + row) * Kw + ktw + sq * 4;
            u32 sa = st + (2 * A_PL + row * ASTR + sq * 4) * 4;
            cp16(sa, Bh + gs);
            cp16(sa + B_PL * 4, Bl + gs);
        }
        asm volatile("cp.async.commit_group;");
    };

    // ldmatrix lane-address offsets (bytes, relative to stage base)
    // A x4: lanes 0-15 -> rows (warp row base + lane&15) @ word 0,
    //       lanes 16-31 -> same rows @ word 4.
    const int lrow = lane & 15, lhalf = lane >> 4;
    u32 aOff[2];
#pragma unroll
    for (int mt = 0; mt < 2; mt++) {
        int row = wm * 32 + mt * 16 + lrow;
        aOff[mt] = (u32)((row * ASTR + lhalf * 4) * 4);
    }
    // B x4 (covers nt pair p: nt=2p, 2p+1):
    //   lane group 0 (0-7):   row = n0w + 2p*8 + lr     @ word 0
    //   group 1 (8-15):       same rows                 @ word 4
    //   group 2 (16-23):      row = n0w + (2p+1)*8 + lr @ word 0
    //   group 3 (24-31):      same rows                 @ word 4
    const int lr = lane & 7, lgr = lane >> 3;
    u32 bOff[2];
#pragma unroll
    for (int p = 0; p < 2; p++) {
        int nrow = wn * 32 + (2 * p + (lgr >> 1)) * 8 + lr;
        bOff[p] = (u32)((2 * A_PL + nrow * ASTR + (lgr & 1) * 4) * 4);
    }

    issue(0, 0);
    for (int kt = 0; kt < nkt; kt++) {
        asm volatile("cp.async.wait_group 0;");
        __syncthreads();
        if (kt + 1 < nkt) issue((kt + 1) & 1, kt + 1);

        const u32 st = smb + (kt & 1) * (STG_W * 4);
#pragma unroll
        for (int sel = 0; sel < 4; sel++) {
            const u32 kb = sel * 32;                  // 8 words = 32 bytes
            u32 ah[2][4], al[2][4], bhq[2][4], blq[2][4];
#pragma unroll
            for (int mt = 0; mt < 2; mt++) {
                ldm4(ah[mt], st + aOff[mt] + kb);
                ldm4(al[mt], st + aOff[mt] + A_PL * 4 + kb);
            }
#pragma unroll
            for (int p = 0; p < 2; p++) {
                ldm4(bhq[p], st + bOff[p] + kb);
                ldm4(blq[p], st + bOff[p] + B_PL * 4 + kb);
            }
#pragma unroll
            for (int p = 0; p < 2; p++) {
#pragma unroll
                for (int sub = 0; sub < 2; sub++) {
                    int nt = 2 * p + sub;
                    u32 bhf[2] = {bhq[p][2 * sub], bhq[p][2 * sub + 1]};
                    u32 blf[2] = {blq[p][2 * sub], blq[p][2 * sub + 1]};
#pragma unroll
                    for (int mt = 0; mt < 2; mt++) {
                        MMA16816(acc[mt][nt], ah[mt], bhf);
                        MMA16816(acc[mt][nt], ah[mt], blf);
                        MMA16816(acc[mt][nt], al[mt], bhf);
                    }
                }
            }
        }
    }

    // epilogue
    const float* bias = op.bias[zb];
    float* Cf = op.Cf[z];
    u32* Ch = op.Ch[z];
    u32* Cl = op.Cl[z];
#pragma unroll
    for (int mt = 0; mt < 2; mt++) {
#pragma unroll
        for (int nt = 0; nt < 4; nt++) {
            int col = n0 + wn * 32 + nt * 8 + 2 * t;
            float bia0 = 0.f, bia1 = 0.f;
            if (mode != 3) { bia0 = bias[col]; bia1 = bias[col + 1]; }
#pragma unroll
            for (int half = 0; half < 2; half++) {
                int row = m0 + wm * 32 + mt * 16 + g + half * 8;
                float c0 = acc[mt][nt][half * 2 + 0] + bia0;
                float c1 = acc[mt][nt][half * 2 + 1] + bia1;
                if (act == 1 && mode != 3) {
                    c0 = c0 / (1.f + expf(-c0)); c1 = c1 / (1.f + expf(-c1));
                } else if (act == 2 && mode != 3) {
                    c0 = c0 * normcdff(c0); c1 = c1 * normcdff(c1);
                }
                if (mode == 0 || mode == 3) {
                    *(float2*)(Cf + (size_t)row * N + col) = make_float2(c0, c1);
                } else {
                    u32 h, l; split_pair(c0, c1, h, l);
                    size_t w;
                    if (mode == 2)
                        w = (size_t)((row >> 8) * 16 + (col >> 5)) * 4096
                          + (size_t)(row & 255) * 16 + ((col & 31) >> 1);
                    else
                        w = ((size_t)row * N + col) >> 1;
                    Ch[w] = h; Cl[w] = l;
                }
            }
        }
    }
}

// ---------------- combine split-K partials + bias + silu -> planes -----------
__global__ __launch_bounds__(256) void combine_silu(
    const float* __restrict__ p0, const float* __restrict__ p1,
    const float* __restrict__ bias, u32* __restrict__ oh, u32* __restrict__ ol)
{
    int i = blockIdx.x * 256 + threadIdx.x;       // word over [ROWS][256]
    int col = (i & 255) * 2;
    float2 a = ((const float2*)p0)[i];
    float2 b = ((const float2*)p1)[i];
    float c0 = a.x + b.x + bias[col];
    float c1 = a.y + b.y + bias[col + 1];
    c0 = c0 / (1.f + expf(-c0));
    c1 = c1 / (1.f + expf(-c1));
    u32 h, l; split_pair(c0, c1, h, l);
    oh[i] = h; ol[i] = l;
}

// ---------------- fused multi-scale attention via HMMA -----------------------
// Grid (bh, tile): one 64-row q-tile per block, 512 blocks.
__global__ __launch_bounds__(256) void attn_mma(
    const u32* __restrict__ qh, const u32* __restrict__ ql,
    const u32* __restrict__ kh, const u32* __restrict__ kl,
    const u32* __restrict__ vh, const u32* __restrict__ vl,
    const float* __restrict__ bias, const u32* __restrict__ allow,
    u32* __restrict__ m2h, u32* __restrict__ m2l)
{
    extern __shared__ u32 smemU[];
    u32* Ksh = smemU;
    u32* Ksl = Ksh + 256 * 17;
    u32* vTh = Ksl + 256 * 17;
    u32* vTl = vTh + 32 * 129;
    float* comb = (float*)(vTl + 32 * 129);
    float* psum = comb + 2 * 64 * 33;

    const int bh = blockIdx.x;
    const int b = bh >> 4;
    const int hh = bh & 15;
    const int tid = threadIdx.x;
    const int lane = tid & 31;
    const int w = tid >> 5;
    const int g = lane >> 2, t = lane & 3;
    const int wm = w >> 1, wn = w & 1;
    const size_t base = (size_t)bh * 4096;

#pragma unroll
    for (int it = 0; it < 16; it++) {
        int idx = tid + 256 * it;
        int row = idx >> 4, wd = idx & 15;
        Ksh[row * 17 + wd] = kh[base + idx];
        Ksl[row * 17 + wd] = kl[base + idx];
    }
    {
        const unsigned short* vhp = (const unsigned short*)vh + base * 2;
        const unsigned short* vlp = (const unsigned short*)vl + base * 2;
#pragma unroll
        for (int it = 0; it < 16; it++) {
            int idx = tid + 256 * it;
            int n = idx & 31, wk = idx >> 5;
            vTh[n * 129 + wk] = (u32)vhp[(2 * wk) * 32 + n]
                              | ((u32)vhp[(2 * wk + 1) * 32 + n] << 16);
            vTl[n * 129 + wk] = (u32)vlp[(2 * wk) * 32 + n]
                              | ((u32)vlp[(2 * wk + 1) * 32 + n] << 16);
        }
    }
    __syncthreads();

    const float scale = 0.17677669529663687f;
    const int tile = blockIdx.y;
    {
        const int r0 = tile * 64 + wm * 16 + g;

        float acc[16][4];
#pragma unroll
        for (int nt = 0; nt < 16; nt++)
#pragma unroll
            for (int i = 0; i < 4; i++) acc[nt][i] = 0.f;

#pragma unroll
        for (int kc = 0; kc < 2; kc++) {
            int w0 = kc * 8 + t;
            u32 ah[4], al[4];
            ah[0] = qh[base + (size_t)r0 * 16 + w0];
            ah[1] = qh[base + (size_t)(r0 + 8) * 16 + w0];
            ah[2] = qh[base + (size_t)r0 * 16 + w0 + 4];
            ah[3] = qh[base + (size_t)(r0 + 8) * 16 + w0 + 4];
            al[0] = ql[base + (size_t)r0 * 16 + w0];
            al[1] = ql[base + (size_t)(r0 + 8) * 16 + w0];
            al[2] = ql[base + (size_t)r0 * 16 + w0 + 4];
            al[3] = ql[base + (size_t)(r0 + 8) * 16 + w0 + 4];
#pragma unroll
            for (int nt = 0; nt < 16; nt++) {
                int n = wn * 128 + nt * 8 + g;
                int bb = n * 17 + kc * 8 + t;
                u32 bhf[2] = {Ksh[bb], Ksh[bb + 4]};
                u32 blf[2] = {Ksl[bb], Ksl[bb + 4]};
                MMA16816(acc[nt], ah, bhf);
                MMA16816(acc[nt], ah, blf);
                MMA16816(acc[nt], al, bhf);
            }
        }

        for (int ks = 0; ks < 4; ks++) {
            float acc2[4][4];
#pragma unroll
            for (int vn = 0; vn < 4; vn++)
#pragma unroll
                for (int i = 0; i < 4; i++) acc2[vn][i] = 0.f;
            float s0 = 0.f, s1 = 0.f;

            const size_t abase = ((size_t)(b * 4 + ks) * 256);
            u32 aw0[4], aw1[4];
#pragma unroll
            for (int ww = 0; ww < 4; ww++) {
                aw0[ww] = allow[(abase + r0) * 8 + wn * 4 + ww];
                aw1[ww] = allow[(abase + r0 + 8) * 8 + wn * 4 + ww];
            }
            const float* bp0 = bias + (abase + r0) * 256 + wn * 128;
            const float* bp1 = bias + (abase + r0 + 8) * 256 + wn * 128;

#pragma unroll
            for (int kc = 0; kc < 8; kc++) {
                u32 pa_h[4], pa_l[4];
#pragma unroll
                for (int sub = 0; sub < 2; sub++) {
                    int nt = 2 * kc + sub;
                    int coff = nt * 8 + 2 * t;
                    float2 bv0 = *(const float2*)(bp0 + coff);
                    float2 bv1 = *(const float2*)(bp1 + coff);
                    int wi = kc >> 1;
                    int bit = (nt & 3) * 8 + 2 * t;
                    float p00 = 0.f, p01 = 0.f, p10 = 0.f, p11 = 0.f;
                    if ((aw0[wi] >> bit) & 1)
                        p00 = __expf(fmaf(acc[nt][0], scale, bv0.x));
                    if ((aw0[wi] >> (bit + 1)) & 1)
                        p01 = __expf(fmaf(acc[nt][1], scale, bv0.y));
                    if ((aw1[wi] >> bit) & 1)
                        p10 = __expf(fmaf(acc[nt][2], scale, bv1.x));
                    if ((aw1[wi] >> (bit + 1)) & 1)
                        p11 = __expf(fmaf(acc[nt][3], scale, bv1.y));
                    s0 += p00 + p01;
                    s1 += p10 + p11;
                    split_pair(p00, p01, pa_h[sub * 2], pa_l[sub * 2]);
                    split_pair(p10, p11, pa_h[sub * 2 + 1], pa_l[sub * 2 + 1]);
                }
                int kcg = wn * 8 + kc;
#pragma unroll
                for (int vn = 0; vn < 4; vn++) {
                    int n = vn * 8 + g;
                    int vb = n * 129 + kcg * 8 + t;
                    u32 bhf[2] = {vTh[vb], vTh[vb + 4]};
                    u32 blf[2] = {vTl[vb], vTl[vb + 4]};
                    MMA16816(acc2[vn], pa_h, bhf);
                    MMA16816(acc2[vn], pa_h, blf);
                    MMA16816(acc2[vn], pa_l, bhf);
                }
            }

            s0 += __shfl_xor_sync(0xffffffffu, s0, 1);
            s0 += __shfl_xor_sync(0xffffffffu, s0, 2);
            s1 += __shfl_xor_sync(0xffffffffu, s1, 1);
            s1 += __shfl_xor_sync(0xffffffffu, s1, 2);
            if (t == 0) {
                psum[(wm * 16 + g) * 2 + wn] = s0;
                psum[(wm * 16 + g + 8) * 2 + wn] = s1;
            }
            float* cw = comb + wn * 64 * 33;
#pragma unroll
            for (int vn = 0; vn < 4; vn++) {
                int c = vn * 8 + 2 * t;
                cw[(wm * 16 + g) * 33 + c]     = acc2[vn][0];
                cw[(wm * 16 + g) * 33 + c + 1] = acc2[vn][1];
                cw[(wm * 16 + g + 8) * 33 + c]     = acc2[vn][2];
                cw[(wm * 16 + g + 8) * 33 + c + 1] = acc2[vn][3];
            }
            __syncthreads();
            // msg2 row = b*256 + np, np = (ks*16+h)*4 + (d>>3); col = (d&7)*256 + n
            for (int i = tid; i < 1024; i += 256) {
                int pr = i >> 5;
                int c = i & 31;
                int rl0 = 2 * pr, rl1 = rl0 + 1;
                float v0 = (comb[rl0 * 33 + c] + comb[64 * 33 + rl0 * 33 + c])
                         / (psum[rl0 * 2] + psum[rl0 * 2 + 1]);
                float v1 = (comb[rl1 * 33 + c] + comb[64 * 33 + rl1 * 33 + c])
                         / (psum[rl1 * 2] + psum[rl1 * 2 + 1]);
                int row0 = tile * 64 + rl0;
                int np = (((ks << 4) | hh) << 2) | (c >> 3);
                size_t wI = ((size_t)b * 256 + np) * 1024
                          + ((c & 7) << 7) + (row0 >> 1);
                u32 hw, lw; split_pair(v0, v1, hw, lw);
                m2h[wI] = hw; m2l[wI] = lw;
            }
            __syncthreads();
        }
    }
}

// ---------------- residual + LayerNorm (2 partials + bias) -------------------
__global__ __launch_bounds__(256) void ln_kernel2(
    const float* __restrict__ a0, const float* __restrict__ a1,
    const float* __restrict__ bb, const float* __restrict__ res,
    const float* __restrict__ g, const float* __restrict__ be,
    float* __restrict__ out, u32* __restrict__ oh, u32* __restrict__ ol)
{
    const int row = blockIdx.x, tid = threadIdx.x;
    __shared__ float sred[8];
    float2 av = ((const float2*)(a0 + (size_t)row * 512))[tid];
    float2 a2 = ((const float2*)(a1 + (size_t)row * 512))[tid];
    float2 rv = ((const float2*)(res + (size_t)row * 512))[tid];
    float b0 = bb[2 * tid], b1 = bb[2 * tid + 1];
    float v0 = av.x + a2.x + b0 + rv.x;
    float v1 = av.y + a2.y + b1 + rv.y;

    float s = v0 + v1;
#pragma unroll
    for (int o = 16; o > 0; o >>= 1) s += __shfl_xor_sync(0xffffffffu, s, o);
    if ((tid & 31) == 0) sred[tid >> 5] = s;
    __syncthreads();
    float mean = 0.f;
#pragma unroll
    for (int i = 0; i < 8; i++) mean += sred[i];
    mean *= (1.f / 512.f);
    __syncthreads();

    float d0 = v0 - mean, d1 = v1 - mean;
    float vs = d0 * d0 + d1 * d1;
#pragma unroll
    for (int o = 16; o > 0; o >>= 1) vs += __shfl_xor_sync(0xffffffffu, vs, o);
    if ((tid & 31) == 0) sred[tid >> 5] = vs;
    __syncthreads();
    float var = 0.f;
#pragma unroll
    for (int i = 0; i < 8; i++) var += sred[i];
    var *= (1.f / 512.f);
    float inv = rsqrtf(var + 1e-6f);

    float2 gv = ((const float2*)g)[tid];
    float2 bv = ((const float2*)be)[tid];
    float o0 = d0 * inv * gv.x + bv.x;
    float o1 = d1 * inv * gv.y + bv.y;
    ((float2*)(out + (size_t)row * 512))[tid] = make_float2(o0, o1);
    if (oh) {
        u32 h, l; split_pair(o0, o1, h, l);
        oh[(size_t)row * 256 + tid] = h;
        ol[(size_t)row * 256 + tid] = l;
    }
}

// ---------------- launch ------------------------------------------------------
extern "C" void kernel_launch(void* const* d_in, const int* in_sizes, int n_in,
                              void* d_out, int out_size)
{
    const float* x         = (const float*)d_in[0];
    const float* dist      = (const float*)d_in[1];
    const float* dist_bar  = (const float*)d_in[2];
    const float* attn_bias = (const float*)d_in[3];
    const int*   mask      = (const int*)d_in[4];
    int wo = (n_in >= 24 && in_sizes[5] == 1) ? 6 : 5;
    const float* Wq  = (const float*)d_in[wo + 0];
    const float* bq  = (const float*)d_in[wo + 1];
    const float* Wk  = (const float*)d_in[wo + 2];
    const float* bk  = (const float*)d_in[wo + 3];
    const float* Wv  = (const float*)d_in[wo + 4];
    const float* bv  = (const float*)d_in[wo + 5];
    const float* W1  = (const float*)d_in[wo + 6];
    const float* b1  = (const float*)d_in[wo + 7];
    const float* W2  = (const float*)d_in[wo + 8];
    const float* b2  = (const float*)d_in[wo + 9];
    const float* g1  = (const float*)d_in[wo + 10];
    const float* be1 = (const float*)d_in[wo + 11];
    const float* Wf1 = (const float*)d_in[wo + 12];
    const float* bf1 = (const float*)d_in[wo + 13];
    const float* Wf2 = (const float*)d_in[wo + 14];
    const float* bf2 = (const float*)d_in[wo + 15];
    const float* g2  = (const float*)d_in[wo + 16];
    const float* be2 = (const float*)d_in[wo + 17];
    float* out = (float*)d_out;

#define SYM(p, s) cudaGetSymbolAddress((void**)&p, s)
    u32 *xw_h, *xw_l, *wqT_h, *wqT_l, *wkT_h, *wkT_l, *wvT_h, *wvT_l;
    u32 *w1T_h, *w1T_l, *w2T_h, *w2T_l, *wf1T_h, *wf1T_l, *wf2T_h, *wf2T_l;
    u32 *qp_h, *qp_l, *kp_h, *kp_l, *vp_h, *vp_l;
    u32 *m2_h, *m2_l, *h1_h, *h1_l, *y_h, *y_l, *f1_h, *f1_l, *allow;
    float *t, *t2, *y;
    SYM(xw_h, g_xw_h); SYM(xw_l, g_xw_l);
    SYM(wqT_h, g_wqT_h); SYM(wqT_l, g_wqT_l);
    SYM(wkT_h, g_wkT_h); SYM(wkT_l, g_wkT_l);
    SYM(wvT_h, g_wvT_h); SYM(wvT_l, g_wvT_l);
    SYM(w1T_h, g_w1T_h); SYM(w1T_l, g_w1T_l);
    SYM(w2T_h, g_w2T_h); SYM(w2T_l, g_w2T_l);
    SYM(wf1T_h, g_wf1T_h); SYM(wf1T_l, g_wf1T_l);
    SYM(wf2T_h, g_wf2T_h); SYM(wf2T_l, g_wf2T_l);
    SYM(qp_h, g_qp_h); SYM(qp_l, g_qp_l);
    SYM(kp_h, g_kp_h); SYM(kp_l, g_kp_l);
    SYM(vp_h, g_vp_h); SYM(vp_l, g_vp_l);
    SYM(m2_h, g_m2_h); SYM(m2_l, g_m2_l);
    SYM(h1_h, g_h1_h); SYM(h1_l, g_h1_l);
    SYM(y_h, g_y_h); SYM(y_l, g_y_l);
    SYM(f1_h, g_f1_h); SYM(f1_l, g_f1_l);
    SYM(allow, g_allow);
    SYM(t, g_t); SYM(t2, g_t2); SYM(y, g_y);

    const int smem_attn = (256 * 17 + 32 * 129) * 2 * 4 + (2 * 64 * 33 + 128) * 4;
    static int attrSet = 0;
    if (!attrSet) {
        cudaFuncSetAttribute(attn_mma,
                             cudaFuncAttributeMaxDynamicSharedMemorySize, smem_attn);
        cudaFuncSetAttribute(gemm_mma2,
                             cudaFuncAttributeMaxDynamicSharedMemorySize, GEMM_SMEM);
        attrSet = 1;
    }

    dim3 blk(256);

    // merged prep
    PrepArgs pa;
    const float* wsrc[7] = {Wq, Wk, Wv, W1, W2, Wf1, Wf2};
    u32* wdh[7] = {wqT_h, wkT_h, wvT_h, w1T_h, w2T_h, wf1T_h, wf2T_h};
    u32* wdl[7] = {wqT_l, wkT_l, wvT_l, w1T_l, w2T_l, wf1T_l, wf2T_l};
    int wK[7] = {512, 512, 512, 2048, 512, 512, 2048};
    int wN[7] = {512, 512, 512, 512, 512, 2048, 512};
    int tbase[8] = {0, 256, 512, 768, 1792, 2048, 3072, 4096};
    for (int i = 0; i < 7; i++) {
        pa.wsrc[i] = wsrc[i]; pa.wdh[i] = wdh[i]; pa.wdl[i] = wdl[i];
        pa.wK[i] = wK[i]; pa.wN[i] = wN[i];
    }
    for (int i = 0; i < 8; i++) pa.tbase[i] = tbase[i];
    pa.x = x; pa.xh = xw_h; pa.xl = xw_l;
    pa.mask = mask; pa.dist = dist; pa.dbar = dist_bar; pa.allow = allow;
    prep_all<<<6208, blk>>>(pa);

    auto mkop = [](const u32* Ah, const u32* Al, int N, int K, int act,
                   int mode, int ksplit) {
        GemmOp o;
        o.Ah = Ah; o.Al = Al; o.N = N; o.K = K; o.act = act;
        o.mode = mode; o.ksplit = ksplit;
        for (int i = 0; i < 3; i++) {
            o.Bh[i] = nullptr; o.Bl[i] = nullptr; o.bias[i] = nullptr;
            o.Cf[i] = nullptr; o.Ch[i] = nullptr; o.Cl[i] = nullptr;
        }
        return o;
    };

    // QKV fused: z = {q,k,v}
    {
        GemmOp o = mkop(xw_h, xw_l, 512, 512, 0, 2, 0);
        o.Bh[0] = wqT_h; o.Bl[0] = wqT_l; o.bias[0] = bq; o.Ch[0] = qp_h; o.Cl[0] = qp_l;
        o.Bh[1] = wkT_h; o.Bl[1] = wkT_l; o.bias[1] = bk; o.Ch[1] = kp_h; o.Cl[1] = kp_l;
        o.Bh[2] = wvT_h; o.Bl[2] = wvT_l; o.bias[2] = bv; o.Ch[2] = vp_h; o.Cl[2] = vp_l;
        gemm_mma2<<<dim3(8, 16, 3), blk, GEMM_SMEM>>>(o);
    }

    attn_mma<<<dim3(BH, 4), blk, smem_attn>>>(qp_h, qp_l, kp_h, kp_l, vp_h, vp_l,
                                              attn_bias, allow, m2_h, m2_l);

    // W1 split-K=2 -> raw partials -> combine(silu) -> h1 planes
    {
        GemmOp o = mkop(m2_h, m2_l, 512, 2048, 1, 3, 1);
        o.Bh[0] = w1T_h; o.Bl[0] = w1T_l;
        o.Cf[0] = t; o.Cf[1] = t2;
        gemm_mma2<<<dim3(8, 16, 2), blk, GEMM_SMEM>>>(o);
    }
    combine_silu<<<(ROWS * 256) / 256, blk>>>(t, t2, b1, h1_h, h1_l);

    // W2 split-K=2 -> raw partials -> ln2
    {
        GemmOp o = mkop(h1_h, h1_l, 512, 512, 0, 3, 1);
        o.Bh[0] = w2T_h; o.Bl[0] = w2T_l;
        o.Cf[0] = t; o.Cf[1] = t2;
        gemm_mma2<<<dim3(8, 16, 2), blk, GEMM_SMEM>>>(o);
    }
    ln_kernel2<<<ROWS, blk>>>(t, t2, b2, x, g1, be1, y, y_h, y_l);

    // FFN1 (N=2048, 512 blocks) -> gelu planes
    {
        GemmOp o = mkop(y_h, y_l, FFN, 512, 2, 1, 0);
        o.Bh[0] = wf1T_h; o.Bl[0] = wf1T_l; o.bias[0] = bf1;
        o.Ch[0] = f1_h; o.Cl[0] = f1_l;
        gemm_mma2<<<dim3(32, 16, 1), blk, GEMM_SMEM>>>(o);
    }

    // FFN2 split-K=2 -> raw partials -> ln2
    {
        GemmOp o = mkop(f1_h, f1_l, 512, 2048, 0, 3, 1);
        o.Bh[0] = wf2T_h; o.Bl[0] = wf2T_l;
        o.Cf[0] = t; o.Cf[1] = t2;
        gemm_mma2<<<dim3(8, 16, 2), blk, GEMM_SMEM>>>(o);
    }
    ln_kernel2<<<ROWS, blk>>>(t, t2, bf2, y, g2, be2, out, nullptr, nullptr);
}

// round 13
// speedup vs baseline: 1.2623x; 1.0120x over previous
#include <cuda_runtime.h>
#include <cuda_bf16.h>
#include <math.h>
#include <stdint.h>

typedef unsigned int u32;
typedef unsigned long long u64;

#define BB 8
#define NN 256
#define DD 512
#define HH 16
#define KK 4
#define FFN 2048
#define ROWS (BB*NN)          // 2048
#define BH (BB*HH)            // 128

// ---------------- scratch globals --------------------------------------------
__device__ u32 g_xw_h[ROWS*256],  g_xw_l[ROWS*256];
__device__ u32 g_wqT_h[512*256],  g_wqT_l[512*256];
__device__ u32 g_wkT_h[512*256],  g_wkT_l[512*256];
__device__ u32 g_wvT_h[512*256],  g_wvT_l[512*256];
__device__ u32 g_w1T_h[512*1024], g_w1T_l[512*1024];
__device__ u32 g_w2T_h[512*256],  g_w2T_l[512*256];
__device__ u32 g_wf1T_h[2048*256], g_wf1T_l[2048*256];
__device__ u32 g_wf2T_h[512*1024], g_wf2T_l[512*1024];
__device__ u32 g_qp_h[BH*4096], g_qp_l[BH*4096];
__device__ u32 g_kp_h[BH*4096], g_kp_l[BH*4096];
__device__ u32 g_vp_h[BH*4096], g_vp_l[BH*4096];
__device__ u32 g_m2_h[ROWS*1024], g_m2_l[ROWS*1024];
__device__ u32 g_h1_h[ROWS*256],  g_h1_l[ROWS*256];
__device__ float g_t[ROWS*DD];
__device__ float g_t2[ROWS*DD];
__device__ float g_y[ROWS*DD];
__device__ u32 g_y_h[ROWS*256],   g_y_l[ROWS*256];
__device__ u32 g_f1_h[ROWS*1024], g_f1_l[ROWS*1024];
__device__ u32 g_allow[BB*KK*NN*8];

// ---------------- helpers ----------------------------------------------------
__device__ __forceinline__ u32 packbf(float a, float b) {
    __nv_bfloat16 ha = __float2bfloat16_rn(a);
    __nv_bfloat16 hb = __float2bfloat16_rn(b);
    return (u32)__bfloat16_as_ushort(ha) | ((u32)__bfloat16_as_ushort(hb) << 16);
}
__device__ __forceinline__ float bfval(float x) {
    return __bfloat162float(__float2bfloat16_rn(x));
}
__device__ __forceinline__ void split_pair(float a, float b, u32& hi, u32& lo) {
    float ah = bfval(a), bh_ = bfval(b);
    hi = packbf(a, b);
    lo = packbf(a - ah, b - bh_);
}

#define MMA16816(d, a, b) \
    asm volatile("mma.sync.aligned.m16n8k16.row.col.f32.bf16.bf16.f32 " \
        "{%0,%1,%2,%3},{%4,%5,%6,%7},{%8,%9},{%0,%1,%2,%3};" \
        : "+f"(d[0]), "+f"(d[1]), "+f"(d[2]), "+f"(d[3]) \
        : "r"(a[0]), "r"(a[1]), "r"(a[2]), "r"(a[3]), "r"(b[0]), "r"(b[1]))

__device__ __forceinline__ void ldm4(u32* r, u32 saddr) {
    asm volatile("ldmatrix.sync.aligned.m8n8.x4.shared.b16 {%0,%1,%2,%3}, [%4];"
        : "=r"(r[0]), "=r"(r[1]), "=r"(r[2]), "=r"(r[3]) : "r"(saddr));
}

__device__ __forceinline__ u32 smem_u32(const void* p) {
    u32 a;
    asm("{ .reg .u64 t; cvta.to.shared.u64 t, %1; cvt.u32.u64 %0, t; }"
        : "=r"(a) : "l"(p));
    return a;
}
__device__ __forceinline__ void cp16(u32 saddr, const void* gptr) {
    asm volatile("cp.async.cg.shared.global [%0], [%1], 16;"
                 :: "r"(saddr), "l"(gptr));
}

// ---------------- merged prep kernel -----------------------------------------
struct PrepArgs {
    const float* wsrc[7];
    u32* wdh[7];
    u32* wdl[7];
    int wK[7], wN[7];
    int tbase[8];
    const float* x; u32* xh; u32* xl;
    const int* mask; const float* dist; const float* dbar; u32* allow;
};

__global__ __launch_bounds__(256) void prep_all(PrepArgs pa)
{
    const int bx = blockIdx.x;
    const int tid = threadIdx.x;
    if (bx < 4096) {
        int task = 0;
        while (bx >= pa.tbase[task + 1]) task++;
        int tIdx = bx - pa.tbase[task];
        int K = pa.wK[task], N = pa.wN[task];
        int ntx = N >> 5;
        int n0 = (tIdx % ntx) * 32, k0 = (tIdx / ntx) * 32;
        __shared__ float tile[32][33];
        int tx = tid & 31, ty = tid >> 5;
        const float* src = pa.wsrc[task];
#pragma unroll
        for (int r = 0; r < 32; r += 8)
            tile[ty + r][tx] = src[(size_t)(k0 + ty + r) * N + n0 + tx];
        __syncthreads();
        int Kw = K >> 1;
        u32* dh = pa.wdh[task];
        u32* dl = pa.wdl[task];
#pragma unroll
        for (int r = 0; r < 32; r += 8) {
            int n = ty + r;
            if (tx < 16) {
                float a = tile[2 * tx][n], b = tile[2 * tx + 1][n];
                u32 h, l; split_pair(a, b, h, l);
                dh[(size_t)(n0 + n) * Kw + (k0 >> 1) + tx] = h;
                dl[(size_t)(n0 + n) * Kw + (k0 >> 1) + tx] = l;
            }
        }
    } else if (bx < 6144) {
        int idx = (bx - 4096) * 256 + tid;
        float2 v = ((const float2*)pa.x)[idx];
        u32 h, l; split_pair(v.x, v.y, h, l);
        pa.xh[idx] = h; pa.xl[idx] = l;
    } else {
        int idx = (bx - 6144) * 256 + tid;            // [b][row][ww]
        int ww = idx & 7, row = (idx >> 3) & 255, b = idx >> 11;
        float d0 = pa.dbar[0], d1 = pa.dbar[1], d2 = pa.dbar[2], d3 = pa.dbar[3];
        u32 w0 = 0, w1 = 0, w2 = 0, w3 = 0;
        for (int bit = 0; bit < 32; bit++) {
            int col = ww * 32 + bit;
            bool pad = pa.mask[((size_t)b * 256 + row) * 256 + col] != 0;
            float nd = 0.f;
            if (row > 0 && col > 0)
                nd = pa.dist[((size_t)b * 255 + row - 1) * 255 + col - 1];
            if (pad) {
                if (nd < d0) w0 |= 1u << bit;
                if (nd < d1) w1 |= 1u << bit;
                if (nd < d2) w2 |= 1u << bit;
                if (nd < d3) w3 |= 1u << bit;
            }
        }
        size_t base = ((size_t)b * 4 * 256 + row) * 8 + ww;
        pa.allow[base] = w0;
        pa.allow[base + 2048] = w1;
        pa.allow[base + 4096] = w2;
        pa.allow[base + 6144] = w3;
    }
}

// ---------------- GEMM: 128x64, BK=64, cp.async 2-stage, ldmatrix frags ------
#define ASTR 36
#define A_PL (128*ASTR)                    // 4608 words per A plane
#define B_PL (64*ASTR)                     // 2304 words per B plane
#define STG_W (2*A_PL + 2*B_PL)            // 13824 words per stage
#define GEMM_SMEM (2 * STG_W * 4)          // 110592 B

struct GemmOp {
    const u32 *Ah, *Al;
    const u32 *Bh[3], *Bl[3];
    const float* bias[3];
    float* Cf[3];
    u32 *Ch[3], *Cl[3];
    int N, K, act, mode, ksplit;           // mode: 0 f32+bias, 1 planes, 2 head planes, 3 raw f32
};

__global__ __launch_bounds__(256, 2) void gemm_mma2(GemmOp op)
{
    extern __shared__ u32 sm[];
    const u32 smb = smem_u32(sm);
    const int z = blockIdx.z;
    const int zb = op.ksplit ? 0 : z;
    const u32* __restrict__ Ah = op.Ah;
    const u32* __restrict__ Al = op.Al;
    const u32* __restrict__ Bh = op.Bh[zb];
    const u32* __restrict__ Bl = op.Bl[zb];
    const int N = op.N, K = op.K, act = op.act, mode = op.mode;
    const int Kw = K >> 1;
    const int Keff = op.ksplit ? (K >> 1) : K;
    const int koffw = op.ksplit ? z * (K >> 2) : 0;
    const int nkt = Keff >> 6;

    const int tid = threadIdx.x;
    const int lane = tid & 31, wid = tid >> 5;
    const int wm = wid & 3, wn = wid >> 2;
    const int g = lane >> 2, t = lane & 3;
    const int m0 = blockIdx.y * 128, n0 = blockIdx.x * 64;

    float acc[2][4][4];
#pragma unroll
    for (int mt = 0; mt < 2; mt++)
#pragma unroll
        for (int nt = 0; nt < 4; nt++)
#pragma unroll
            for (int i = 0; i < 4; i++) acc[mt][nt][i] = 0.f;

    const int srow = tid >> 3, sq = tid & 7;   // base row/quad for async copies

    auto issue = [&](int s, int kt) {
        const u32 st = smb + s * (STG_W * 4);
        const int ktw = koffw + kt * 32;
#pragma unroll
        for (int i = 0; i < 4; i++) {
            int row = srow + 32 * i;
            size_t gs = (size_t)(m0 + row) * Kw + ktw + sq * 4;
            u32 sa = st + (row * ASTR + sq * 4) * 4;
            cp16(sa, Ah + gs);
            cp16(sa + A_PL * 4, Al + gs);
        }
#pragma unroll
        for (int i = 0; i < 2; i++) {
            int row = srow + 32 * i;
            size_t gs = (size_t)(n0 + row) * Kw + ktw + sq * 4;
            u32 sa = st + (2 * A_PL + row * ASTR + sq * 4) * 4;
            cp16(sa, Bh + gs);
            cp16(sa + B_PL * 4, Bl + gs);
        }
        asm volatile("cp.async.commit_group;");
    };

    // ldmatrix lane-address offsets (bytes, relative to stage base)
    const int lrow = lane & 15, lhalf = lane >> 4;
    u32 aOff[2];
#pragma unroll
    for (int mt = 0; mt < 2; mt++) {
        int row = wm * 32 + mt * 16 + lrow;
        aOff[mt] = (u32)((row * ASTR + lhalf * 4) * 4);
    }
    const int lr = lane & 7, lgr = lane >> 3;
    u32 bOff[2];
#pragma unroll
    for (int p = 0; p < 2; p++) {
        int nrow = wn * 32 + (2 * p + (lgr >> 1)) * 8 + lr;
        bOff[p] = (u32)((2 * A_PL + nrow * ASTR + (lgr & 1) * 4) * 4);
    }

    issue(0, 0);
    for (int kt = 0; kt < nkt; kt++) {
        asm volatile("cp.async.wait_group 0;");
        __syncthreads();
        if (kt + 1 < nkt) issue((kt + 1) & 1, kt + 1);

        const u32 st = smb + (kt & 1) * (STG_W * 4);
#pragma unroll
        for (int sel = 0; sel < 4; sel++) {
            const u32 kb = sel * 32;                  // 8 words = 32 bytes
            u32 ah[2][4], al[2][4], bhq[2][4], blq[2][4];
#pragma unroll
            for (int mt = 0; mt < 2; mt++) {
                ldm4(ah[mt], st + aOff[mt] + kb);
                ldm4(al[mt], st + aOff[mt] + A_PL * 4 + kb);
            }
#pragma unroll
            for (int p = 0; p < 2; p++) {
                ldm4(bhq[p], st + bOff[p] + kb);
                ldm4(blq[p], st + bOff[p] + B_PL * 4 + kb);
            }
            // term-major issue order: 8 independent accumulators between
            // successive MMAs on the same acc -> no RAW stalls.
#pragma unroll
            for (int term = 0; term < 3; term++) {
#pragma unroll
                for (int p = 0; p < 2; p++) {
#pragma unroll
                    for (int sub = 0; sub < 2; sub++) {
                        int nt = 2 * p + sub;
                        u32 bhf[2] = {bhq[p][2 * sub], bhq[p][2 * sub + 1]};
                        u32 blf[2] = {blq[p][2 * sub], blq[p][2 * sub + 1]};
#pragma unroll
                        for (int mt = 0; mt < 2; mt++) {
                            if (term == 0)      MMA16816(acc[mt][nt], ah[mt], bhf);
                            else if (term == 1) MMA16816(acc[mt][nt], ah[mt], blf);
                            else                MMA16816(acc[mt][nt], al[mt], bhf);
                        }
                    }
                }
            }
        }
    }

    // epilogue
    const float* bias = op.bias[zb];
    float* Cf = op.Cf[z];
    u32* Ch = op.Ch[z];
    u32* Cl = op.Cl[z];
#pragma unroll
    for (int mt = 0; mt < 2; mt++) {
#pragma unroll
        for (int nt = 0; nt < 4; nt++) {
            int col = n0 + wn * 32 + nt * 8 + 2 * t;
            float bia0 = 0.f, bia1 = 0.f;
            if (mode != 3) { bia0 = bias[col]; bia1 = bias[col + 1]; }
#pragma unroll
            for (int half = 0; half < 2; half++) {
                int row = m0 + wm * 32 + mt * 16 + g + half * 8;
                float c0 = acc[mt][nt][half * 2 + 0] + bia0;
                float c1 = acc[mt][nt][half * 2 + 1] + bia1;
                if (act == 1 && mode != 3) {
                    c0 = c0 / (1.f + expf(-c0)); c1 = c1 / (1.f + expf(-c1));
                } else if (act == 2 && mode != 3) {
                    c0 = c0 * normcdff(c0); c1 = c1 * normcdff(c1);
                }
                if (mode == 0 || mode == 3) {
                    *(float2*)(Cf + (size_t)row * N + col) = make_float2(c0, c1);
                } else {
                    u32 h, l; split_pair(c0, c1, h, l);
                    size_t w;
                    if (mode == 2)
                        w = (size_t)((row >> 8) * 16 + (col >> 5)) * 4096
                          + (size_t)(row & 255) * 16 + ((col & 31) >> 1);
                    else
                        w = ((size_t)row * N + col) >> 1;
                    Ch[w] = h; Cl[w] = l;
                }
            }
        }
    }
}

// ---------------- combine split-K partials + bias + silu -> planes -----------
__global__ __launch_bounds__(256) void combine_silu(
    const float* __restrict__ p0, const float* __restrict__ p1,
    const float* __restrict__ bias, u32* __restrict__ oh, u32* __restrict__ ol)
{
    int i = blockIdx.x * 256 + threadIdx.x;       // word over [ROWS][256]
    int col = (i & 255) * 2;
    float2 a = ((const float2*)p0)[i];
    float2 b = ((const float2*)p1)[i];
    float c0 = a.x + b.x + bias[col];
    float c1 = a.y + b.y + bias[col + 1];
    c0 = c0 / (1.f + expf(-c0));
    c1 = c1 / (1.f + expf(-c1));
    u32 h, l; split_pair(c0, c1, h, l);
    oh[i] = h; ol[i] = l;
}

// ---------------- fused multi-scale attention via HMMA -----------------------
// Grid (bh, tile): one 64-row q-tile per block, 512 blocks.
__global__ __launch_bounds__(256) void attn_mma(
    const u32* __restrict__ qh, const u32* __restrict__ ql,
    const u32* __restrict__ kh, const u32* __restrict__ kl,
    const u32* __restrict__ vh, const u32* __restrict__ vl,
    const float* __restrict__ bias, const u32* __restrict__ allow,
    u32* __restrict__ m2h, u32* __restrict__ m2l)
{
    extern __shared__ u32 smemU[];
    u32* Ksh = smemU;
    u32* Ksl = Ksh + 256 * 17;
    u32* vTh = Ksl + 256 * 17;
    u32* vTl = vTh + 32 * 129;
    float* comb = (float*)(vTl + 32 * 129);
    float* psum = comb + 2 * 64 * 33;

    const int bh = blockIdx.x;
    const int b = bh >> 4;
    const int hh = bh & 15;
    const int tid = threadIdx.x;
    const int lane = tid & 31;
    const int w = tid >> 5;
    const int g = lane >> 2, t = lane & 3;
    const int wm = w >> 1, wn = w & 1;
    const size_t base = (size_t)bh * 4096;

#pragma unroll
    for (int it = 0; it < 16; it++) {
        int idx = tid + 256 * it;
        int row = idx >> 4, wd = idx & 15;
        Ksh[row * 17 + wd] = kh[base + idx];
        Ksl[row * 17 + wd] = kl[base + idx];
    }
    {
        const unsigned short* vhp = (const unsigned short*)vh + base * 2;
        const unsigned short* vlp = (const unsigned short*)vl + base * 2;
#pragma unroll
        for (int it = 0; it < 16; it++) {
            int idx = tid + 256 * it;
            int n = idx & 31, wk = idx >> 5;
            vTh[n * 129 + wk] = (u32)vhp[(2 * wk) * 32 + n]
                              | ((u32)vhp[(2 * wk + 1) * 32 + n] << 16);
            vTl[n * 129 + wk] = (u32)vlp[(2 * wk) * 32 + n]
                              | ((u32)vlp[(2 * wk + 1) * 32 + n] << 16);
        }
    }
    __syncthreads();

    const float scale = 0.17677669529663687f;
    const int tile = blockIdx.y;
    {
        const int r0 = tile * 64 + wm * 16 + g;

        float acc[16][4];
#pragma unroll
        for (int nt = 0; nt < 16; nt++)
#pragma unroll
            for (int i = 0; i < 4; i++) acc[nt][i] = 0.f;

#pragma unroll
        for (int kc = 0; kc < 2; kc++) {
            int w0 = kc * 8 + t;
            u32 ah[4], al[4];
            ah[0] = qh[base + (size_t)r0 * 16 + w0];
            ah[1] = qh[base + (size_t)(r0 + 8) * 16 + w0];
            ah[2] = qh[base + (size_t)r0 * 16 + w0 + 4];
            ah[3] = qh[base + (size_t)(r0 + 8) * 16 + w0 + 4];
            al[0] = ql[base + (size_t)r0 * 16 + w0];
            al[1] = ql[base + (size_t)(r0 + 8) * 16 + w0];
            al[2] = ql[base + (size_t)r0 * 16 + w0 + 4];
            al[3] = ql[base + (size_t)(r0 + 8) * 16 + w0 + 4];
#pragma unroll
            for (int nt = 0; nt < 16; nt++) {
                int n = wn * 128 + nt * 8 + g;
                int bb = n * 17 + kc * 8 + t;
                u32 bhf[2] = {Ksh[bb], Ksh[bb + 4]};
                u32 blf[2] = {Ksl[bb], Ksl[bb + 4]};
                MMA16816(acc[nt], ah, bhf);
                MMA16816(acc[nt], ah, blf);
                MMA16816(acc[nt], al, bhf);
            }
        }

        for (int ks = 0; ks < 4; ks++) {
            float acc2[4][4];
#pragma unroll
            for (int vn = 0; vn < 4; vn++)
#pragma unroll
                for (int i = 0; i < 4; i++) acc2[vn][i] = 0.f;
            float s0 = 0.f, s1 = 0.f;

            const size_t abase = ((size_t)(b * 4 + ks) * 256);
            u32 aw0[4], aw1[4];
#pragma unroll
            for (int ww = 0; ww < 4; ww++) {
                aw0[ww] = allow[(abase + r0) * 8 + wn * 4 + ww];
                aw1[ww] = allow[(abase + r0 + 8) * 8 + wn * 4 + ww];
            }
            const float* bp0 = bias + (abase + r0) * 256 + wn * 128;
            const float* bp1 = bias + (abase + r0 + 8) * 256 + wn * 128;

#pragma unroll
            for (int kc = 0; kc < 8; kc++) {
                u32 pa_h[4], pa_l[4];
#pragma unroll
                for (int sub = 0; sub < 2; sub++) {
                    int nt = 2 * kc + sub;
                    int coff = nt * 8 + 2 * t;
                    float2 bv0 = *(const float2*)(bp0 + coff);
                    float2 bv1 = *(const float2*)(bp1 + coff);
                    int wi = kc >> 1;
                    int bit = (nt & 3) * 8 + 2 * t;
                    float p00 = 0.f, p01 = 0.f, p10 = 0.f, p11 = 0.f;
                    if ((aw0[wi] >> bit) & 1)
                        p00 = __expf(fmaf(acc[nt][0], scale, bv0.x));
                    if ((aw0[wi] >> (bit + 1)) & 1)
                        p01 = __expf(fmaf(acc[nt][1], scale, bv0.y));
                    if ((aw1[wi] >> bit) & 1)
                        p10 = __expf(fmaf(acc[nt][2], scale, bv1.x));
                    if ((aw1[wi] >> (bit + 1)) & 1)
                        p11 = __expf(fmaf(acc[nt][3], scale, bv1.y));
                    s0 += p00 + p01;
                    s1 += p10 + p11;
                    split_pair(p00, p01, pa_h[sub * 2], pa_l[sub * 2]);
                    split_pair(p10, p11, pa_h[sub * 2 + 1], pa_l[sub * 2 + 1]);
                }
                int kcg = wn * 8 + kc;
#pragma unroll
                for (int vn = 0; vn < 4; vn++) {
                    int n = vn * 8 + g;
                    int vb = n * 129 + kcg * 8 + t;
                    u32 bhf[2] = {vTh[vb], vTh[vb + 4]};
                    u32 blf[2] = {vTl[vb], vTl[vb + 4]};
                    MMA16816(acc2[vn], pa_h, bhf);
                    MMA16816(acc2[vn], pa_h, blf);
                    MMA16816(acc2[vn], pa_l, bhf);
                }
            }

            s0 += __shfl_xor_sync(0xffffffffu, s0, 1);
            s0 += __shfl_xor_sync(0xffffffffu, s0, 2);
            s1 += __shfl_xor_sync(0xffffffffu, s1, 1);
            s1 += __shfl_xor_sync(0xffffffffu, s1, 2);
            if (t == 0) {
                psum[(wm * 16 + g) * 2 + wn] = s0;
                psum[(wm * 16 + g + 8) * 2 + wn] = s1;
            }
            float* cw = comb + wn * 64 * 33;
#pragma unroll
            for (int vn = 0; vn < 4; vn++) {
                int c = vn * 8 + 2 * t;
                cw[(wm * 16 + g) * 33 + c]     = acc2[vn][0];
                cw[(wm * 16 + g) * 33 + c + 1] = acc2[vn][1];
                cw[(wm * 16 + g + 8) * 33 + c]     = acc2[vn][2];
                cw[(wm * 16 + g + 8) * 33 + c + 1] = acc2[vn][3];
            }
            __syncthreads();
            // msg2 row = b*256 + np, np = (ks*16+h)*4 + (d>>3); col = (d&7)*256 + n
            for (int i = tid; i < 1024; i += 256) {
                int pr = i >> 5;
                int c = i & 31;
                int rl0 = 2 * pr, rl1 = rl0 + 1;
                float v0 = (comb[rl0 * 33 + c] + comb[64 * 33 + rl0 * 33 + c])
                         / (psum[rl0 * 2] + psum[rl0 * 2 + 1]);
                float v1 = (comb[rl1 * 33 + c] + comb[64 * 33 + rl1 * 33 + c])
                         / (psum[rl1 * 2] + psum[rl1 * 2 + 1]);
                int row0 = tile * 64 + rl0;
                int np = (((ks << 4) | hh) << 2) | (c >> 3);
                size_t wI = ((size_t)b * 256 + np) * 1024
                          + ((c & 7) << 7) + (row0 >> 1);
                u32 hw, lw; split_pair(v0, v1, hw, lw);
                m2h[wI] = hw; m2l[wI] = lw;
            }
            __syncthreads();
        }
    }
}

// ---------------- residual + LayerNorm (2 partials + bias) -------------------
__global__ __launch_bounds__(256) void ln_kernel2(
    const float* __restrict__ a0, const float* __restrict__ a1,
    const float* __restrict__ bb, const float* __restrict__ res,
    const float* __restrict__ g, const float* __restrict__ be,
    float* __restrict__ out, u32* __restrict__ oh, u32* __restrict__ ol)
{
    const int row = blockIdx.x, tid = threadIdx.x;
    __shared__ float sred[8];
    float2 av = ((const float2*)(a0 + (size_t)row * 512))[tid];
    float2 a2 = ((const float2*)(a1 + (size_t)row * 512))[tid];
    float2 rv = ((const float2*)(res + (size_t)row * 512))[tid];
    float b0 = bb[2 * tid], b1 = bb[2 * tid + 1];
    float v0 = av.x + a2.x + b0 + rv.x;
    float v1 = av.y + a2.y + b1 + rv.y;

    float s = v0 + v1;
#pragma unroll
    for (int o = 16; o > 0; o >>= 1) s += __shfl_xor_sync(0xffffffffu, s, o);
    if ((tid & 31) == 0) sred[tid >> 5] = s;
    __syncthreads();
    float mean = 0.f;
#pragma unroll
    for (int i = 0; i < 8; i++) mean += sred[i];
    mean *= (1.f / 512.f);
    __syncthreads();

    float d0 = v0 - mean, d1 = v1 - mean;
    float vs = d0 * d0 + d1 * d1;
#pragma unroll
    for (int o = 16; o > 0; o >>= 1) vs += __shfl_xor_sync(0xffffffffu, vs, o);
    if ((tid & 31) == 0) sred[tid >> 5] = vs;
    __syncthreads();
    float var = 0.f;
#pragma unroll
    for (int i = 0; i < 8; i++) var += sred[i];
    var *= (1.f / 512.f);
    float inv = rsqrtf(var + 1e-6f);

    float2 gv = ((const float2*)g)[tid];
    float2 bv = ((const float2*)be)[tid];
    float o0 = d0 * inv * gv.x + bv.x;
    float o1 = d1 * inv * gv.y + bv.y;
    ((float2*)(out + (size_t)row * 512))[tid] = make_float2(o0, o1);
    if (oh) {
        u32 h, l; split_pair(o0, o1, h, l);
        oh[(size_t)row * 256 + tid] = h;
        ol[(size_t)row * 256 + tid] = l;
    }
}

// ---------------- launch ------------------------------------------------------
extern "C" void kernel_launch(void* const* d_in, const int* in_sizes, int n_in,
                              void* d_out, int out_size)
{
    const float* x         = (const float*)d_in[0];
    const float* dist      = (const float*)d_in[1];
    const float* dist_bar  = (const float*)d_in[2];
    const float* attn_bias = (const float*)d_in[3];
    const int*   mask      = (const int*)d_in[4];
    int wo = (n_in >= 24 && in_sizes[5] == 1) ? 6 : 5;
    const float* Wq  = (const float*)d_in[wo + 0];
    const float* bq  = (const float*)d_in[wo + 1];
    const float* Wk  = (const float*)d_in[wo + 2];
    const float* bk  = (const float*)d_in[wo + 3];
    const float* Wv  = (const float*)d_in[wo + 4];
    const float* bv  = (const float*)d_in[wo + 5];
    const float* W1  = (const float*)d_in[wo + 6];
    const float* b1  = (const float*)d_in[wo + 7];
    const float* W2  = (const float*)d_in[wo + 8];
    const float* b2  = (const float*)d_in[wo + 9];
    const float* g1  = (const float*)d_in[wo + 10];
    const float* be1 = (const float*)d_in[wo + 11];
    const float* Wf1 = (const float*)d_in[wo + 12];
    const float* bf1 = (const float*)d_in[wo + 13];
    const float* Wf2 = (const float*)d_in[wo + 14];
    const float* bf2 = (const float*)d_in[wo + 15];
    const float* g2  = (const float*)d_in[wo + 16];
    const float* be2 = (const float*)d_in[wo + 17];
    float* out = (float*)d_out;

#define SYM(p, s) cudaGetSymbolAddress((void**)&p, s)
    u32 *xw_h, *xw_l, *wqT_h, *wqT_l, *wkT_h, *wkT_l, *wvT_h, *wvT_l;
    u32 *w1T_h, *w1T_l, *w2T_h, *w2T_l, *wf1T_h, *wf1T_l, *wf2T_h, *wf2T_l;
    u32 *qp_h, *qp_l, *kp_h, *kp_l, *vp_h, *vp_l;
    u32 *m2_h, *m2_l, *h1_h, *h1_l, *y_h, *y_l, *f1_h, *f1_l, *allow;
    float *t, *t2, *y;
    SYM(xw_h, g_xw_h); SYM(xw_l, g_xw_l);
    SYM(wqT_h, g_wqT_h); SYM(wqT_l, g_wqT_l);
    SYM(wkT_h, g_wkT_h); SYM(wkT_l, g_wkT_l);
    SYM(wvT_h, g_wvT_h); SYM(wvT_l, g_wvT_l);
    SYM(w1T_h, g_w1T_h); SYM(w1T_l, g_w1T_l);
    SYM(w2T_h, g_w2T_h); SYM(w2T_l, g_w2T_l);
    SYM(wf1T_h, g_wf1T_h); SYM(wf1T_l, g_wf1T_l);
    SYM(wf2T_h, g_wf2T_h); SYM(wf2T_l, g_wf2T_l);
    SYM(qp_h, g_qp_h); SYM(qp_l, g_qp_l);
    SYM(kp_h, g_kp_h); SYM(kp_l, g_kp_l);
    SYM(vp_h, g_vp_h); SYM(vp_l, g_vp_l);
    SYM(m2_h, g_m2_h); SYM(m2_l, g_m2_l);
    SYM(h1_h, g_h1_h); SYM(h1_l, g_h1_l);
    SYM(y_h, g_y_h); SYM(y_l, g_y_l);
    SYM(f1_h, g_f1_h); SYM(f1_l, g_f1_l);
    SYM(allow, g_allow);
    SYM(t, g_t); SYM(t2, g_t2); SYM(y, g_y);

    const int smem_attn = (256 * 17 + 32 * 129) * 2 * 4 + (2 * 64 * 33 + 128) * 4;
    static int attrSet = 0;
    if (!attrSet) {
        cudaFuncSetAttribute(attn_mma,
                             cudaFuncAttributeMaxDynamicSharedMemorySize, smem_attn);
        cudaFuncSetAttribute(gemm_mma2,
                             cudaFuncAttributeMaxDynamicSharedMemorySize, GEMM_SMEM);
        attrSet = 1;
    }

    dim3 blk(256);

    // merged prep
    PrepArgs pa;
    const float* wsrc[7] = {Wq, Wk, Wv, W1, W2, Wf1, Wf2};
    u32* wdh[7] = {wqT_h, wkT_h, wvT_h, w1T_h, w2T_h, wf1T_h, wf2T_h};
    u32* wdl[7] = {wqT_l, wkT_l, wvT_l, w1T_l, w2T_l, wf1T_l, wf2T_l};
    int wK[7] = {512, 512, 512, 2048, 512, 512, 2048};
    int wN[7] = {512, 512, 512, 512, 512, 2048, 512};
    int tbase[8] = {0, 256, 512, 768, 1792, 2048, 3072, 4096};
    for (int i = 0; i < 7; i++) {
        pa.wsrc[i] = wsrc[i]; pa.wdh[i] = wdh[i]; pa.wdl[i] = wdl[i];
        pa.wK[i] = wK[i]; pa.wN[i] = wN[i];
    }
    for (int i = 0; i < 8; i++) pa.tbase[i] = tbase[i];
    pa.x = x; pa.xh = xw_h; pa.xl = xw_l;
    pa.mask = mask; pa.dist = dist; pa.dbar = dist_bar; pa.allow = allow;
    prep_all<<<6208, blk>>>(pa);

    auto mkop = [](const u32* Ah, const u32* Al, int N, int K, int act,
                   int mode, int ksplit) {
        GemmOp o;
        o.Ah = Ah; o.Al = Al; o.N = N; o.K = K; o.act = act;
        o.mode = mode; o.ksplit = ksplit;
        for (int i = 0; i < 3; i++) {
            o.Bh[i] = nullptr; o.Bl[i] = nullptr; o.bias[i] = nullptr;
            o.Cf[i] = nullptr; o.Ch[i] = nullptr; o.Cl[i] = nullptr;
        }
        return o;
    };

    // QKV fused: z = {q,k,v}
    {
        GemmOp o = mkop(xw_h, xw_l, 512, 512, 0, 2, 0);
        o.Bh[0] = wqT_h; o.Bl[0] = wqT_l; o.bias[0] = bq; o.Ch[0] = qp_h; o.Cl[0] = qp_l;
        o.Bh[1] = wkT_h; o.Bl[1] = wkT_l; o.bias[1] = bk; o.Ch[1] = kp_h; o.Cl[1] = kp_l;
        o.Bh[2] = wvT_h; o.Bl[2] = wvT_l; o.bias[2] = bv; o.Ch[2] = vp_h; o.Cl[2] = vp_l;
        gemm_mma2<<<dim3(8, 16, 3), blk, GEMM_SMEM>>>(o);
    }

    attn_mma<<<dim3(BH, 4), blk, smem_attn>>>(qp_h, qp_l, kp_h, kp_l, vp_h, vp_l,
                                              attn_bias, allow, m2_h, m2_l);

    // W1 split-K=2 -> raw partials -> combine(silu) -> h1 planes
    {
        GemmOp o = mkop(m2_h, m2_l, 512, 2048, 1, 3, 1);
        o.Bh[0] = w1T_h; o.Bl[0] = w1T_l;
        o.Cf[0] = t; o.Cf[1] = t2;
        gemm_mma2<<<dim3(8, 16, 2), blk, GEMM_SMEM>>>(o);
    }
    combine_silu<<<(ROWS * 256) / 256, blk>>>(t, t2, b1, h1_h, h1_l);

    // W2 split-K=2 -> raw partials -> ln2
    {
        GemmOp o = mkop(h1_h, h1_l, 512, 512, 0, 3, 1);
        o.Bh[0] = w2T_h; o.Bl[0] = w2T_l;
        o.Cf[0] = t; o.Cf[1] = t2;
        gemm_mma2<<<dim3(8, 16, 2), blk, GEMM_SMEM>>>(o);
    }
    ln_kernel2<<<ROWS, blk>>>(t, t2, b2, x, g1, be1, y, y_h, y_l);

    // FFN1 (N=2048, 512 blocks) -> gelu planes
    {
        GemmOp o = mkop(y_h, y_l, FFN, 512, 2, 1, 0);
        o.Bh[0] = wf1T_h; o.Bl[0] = wf1T_l; o.bias[0] = bf1;
        o.Ch[0] = f1_h; o.Cl[0] = f1_l;
        gemm_mma2<<<dim3(32, 16, 1), blk, GEMM_SMEM>>>(o);
    }

    // FFN2 split-K=2 -> raw partials -> ln2
    {
        GemmOp o = mkop(f1_h, f1_l, 512, 2048, 0, 3, 1);
        o.Bh[0] = wf2T_h; o.Bl[0] = wf2T_l;
        o.Cf[0] = t; o.Cf[1] = t2;
        gemm_mma2<<<dim3(8, 16, 2), blk, GEMM_SMEM>>>(o);
    }
    ln_kernel2<<<ROWS, blk>>>(t, t2, bf2, y, g2, be2, out, nullptr, nullptr);
}

// round 15
// speedup vs baseline: 1.3035x; 1.0326x over previous
#include <cuda_runtime.h>
#include <cuda_bf16.h>
#include <math.h>
#include <stdint.h>

typedef unsigned int u32;
typedef unsigned long long u64;

#define BB 8
#define NN 256
#define DD 512
#define HH 16
#define KK 4
#define FFN 2048
#define ROWS (BB*NN)          // 2048
#define BH (BB*HH)            // 128

// ---------------- scratch globals --------------------------------------------
__device__ u32 g_xw_h[ROWS*256],  g_xw_l[ROWS*256];
__device__ u32 g_wqT_h[512*256],  g_wqT_l[512*256];
__device__ u32 g_wkT_h[512*256],  g_wkT_l[512*256];
__device__ u32 g_wvT_h[512*256],  g_wvT_l[512*256];
__device__ u32 g_w1T_h[512*1024], g_w1T_l[512*1024];
__device__ u32 g_w2T_h[512*256],  g_w2T_l[512*256];
__device__ u32 g_wf1T_h[2048*256], g_wf1T_l[2048*256];
__device__ u32 g_wf2T_h[512*1024], g_wf2T_l[512*1024];
__device__ u32 g_qp_h[BH*4096], g_qp_l[BH*4096];
__device__ u32 g_kp_h[BH*4096], g_kp_l[BH*4096];
__device__ u32 g_vp_h[BH*4096], g_vp_l[BH*4096];
__device__ u32 g_m2_h[ROWS*1024], g_m2_l[ROWS*1024];
__device__ u32 g_h1_h[ROWS*256],  g_h1_l[ROWS*256];
__device__ float g_t[ROWS*DD];
__device__ float g_t2[ROWS*DD];
__device__ float g_y[ROWS*DD];
__device__ u32 g_y_h[ROWS*256],   g_y_l[ROWS*256];
__device__ u32 g_f1_h[ROWS*1024], g_f1_l[ROWS*1024];
__device__ u32 g_allow[BB*KK*NN*8];

// ---------------- helpers ----------------------------------------------------
__device__ __forceinline__ u32 packbf(float a, float b) {
    __nv_bfloat16 ha = __float2bfloat16_rn(a);
    __nv_bfloat16 hb = __float2bfloat16_rn(b);
    return (u32)__bfloat16_as_ushort(ha) | ((u32)__bfloat16_as_ushort(hb) << 16);
}
__device__ __forceinline__ float bfval(float x) {
    return __bfloat162float(__float2bfloat16_rn(x));
}
__device__ __forceinline__ void split_pair(float a, float b, u32& hi, u32& lo) {
    float ah = bfval(a), bh_ = bfval(b);
    hi = packbf(a, b);
    lo = packbf(a - ah, b - bh_);
}

#define MMA16816(d, a, b) \
    asm volatile("mma.sync.aligned.m16n8k16.row.col.f32.bf16.bf16.f32 " \
        "{%0,%1,%2,%3},{%4,%5,%6,%7},{%8,%9},{%0,%1,%2,%3};" \
        : "+f"(d[0]), "+f"(d[1]), "+f"(d[2]), "+f"(d[3]) \
        : "r"(a[0]), "r"(a[1]), "r"(a[2]), "r"(a[3]), "r"(b[0]), "r"(b[1]))

__device__ __forceinline__ void ldm4(u32* r, u32 saddr) {
    asm volatile("ldmatrix.sync.aligned.m8n8.x4.shared.b16 {%0,%1,%2,%3}, [%4];"
        : "=r"(r[0]), "=r"(r[1]), "=r"(r[2]), "=r"(r[3]) : "r"(saddr));
}

__device__ __forceinline__ u32 smem_u32(const void* p) {
    u32 a;
    asm("{ .reg .u64 t; cvta.to.shared.u64 t, %1; cvt.u32.u64 %0, t; }"
        : "=r"(a) : "l"(p));
    return a;
}
__device__ __forceinline__ void cp16(u32 saddr, const void* gptr) {
    asm volatile("cp.async.cg.shared.global [%0], [%1], 16;"
                 :: "r"(saddr), "l"(gptr));
}

// ---------------- merged prep kernel -----------------------------------------
struct PrepArgs {
    const float* wsrc[7];
    u32* wdh[7];
    u32* wdl[7];
    int wK[7], wN[7];
    int tbase[8];
    const float* x; u32* xh; u32* xl;
    const int* mask; const float* dist; const float* dbar; u32* allow;
};

__global__ __launch_bounds__(256) void prep_all(PrepArgs pa)
{
    const int bx = blockIdx.x;
    const int tid = threadIdx.x;
    if (bx < 4096) {
        int task = 0;
        while (bx >= pa.tbase[task + 1]) task++;
        int tIdx = bx - pa.tbase[task];
        int K = pa.wK[task], N = pa.wN[task];
        int ntx = N >> 5;
        int n0 = (tIdx % ntx) * 32, k0 = (tIdx / ntx) * 32;
        __shared__ float tile[32][33];
        int tx = tid & 31, ty = tid >> 5;
        const float* src = pa.wsrc[task];
#pragma unroll
        for (int r = 0; r < 32; r += 8)
            tile[ty + r][tx] = src[(size_t)(k0 + ty + r) * N + n0 + tx];
        __syncthreads();
        int Kw = K >> 1;
        u32* dh = pa.wdh[task];
        u32* dl = pa.wdl[task];
#pragma unroll
        for (int r = 0; r < 32; r += 8) {
            int n = ty + r;
            if (tx < 16) {
                float a = tile[2 * tx][n], b = tile[2 * tx + 1][n];
                u32 h, l; split_pair(a, b, h, l);
                dh[(size_t)(n0 + n) * Kw + (k0 >> 1) + tx] = h;
                dl[(size_t)(n0 + n) * Kw + (k0 >> 1) + tx] = l;
            }
        }
    } else if (bx < 6144) {
        int idx = (bx - 4096) * 256 + tid;
        float2 v = ((const float2*)pa.x)[idx];
        u32 h, l; split_pair(v.x, v.y, h, l);
        pa.xh[idx] = h; pa.xl[idx] = l;
    } else {
        int idx = (bx - 6144) * 256 + tid;            // [b][row][ww]
        int ww = idx & 7, row = (idx >> 3) & 255, b = idx >> 11;
        float d0 = pa.dbar[0], d1 = pa.dbar[1], d2 = pa.dbar[2], d3 = pa.dbar[3];
        u32 w0 = 0, w1 = 0, w2 = 0, w3 = 0;
        for (int bit = 0; bit < 32; bit++) {
            int col = ww * 32 + bit;
            bool pad = pa.mask[((size_t)b * 256 + row) * 256 + col] != 0;
            float nd = 0.f;
            if (row > 0 && col > 0)
                nd = pa.dist[((size_t)b * 255 + row - 1) * 255 + col - 1];
            if (pad) {
                if (nd < d0) w0 |= 1u << bit;
                if (nd < d1) w1 |= 1u << bit;
                if (nd < d2) w2 |= 1u << bit;
                if (nd < d3) w3 |= 1u << bit;
            }
        }
        size_t base = ((size_t)b * 4 * 256 + row) * 8 + ww;
        pa.allow[base] = w0;
        pa.allow[base + 2048] = w1;
        pa.allow[base + 4096] = w2;
        pa.allow[base + 6144] = w3;
    }
}

// ---------------- GEMM: 128x64, BK=64, cp.async 2-stage, ldmatrix frags ------
#define ASTR 36
#define A_PL (128*ASTR)                    // 4608 words per A plane
#define B_PL (64*ASTR)                     // 2304 words per B plane
#define STG_W (2*A_PL + 2*B_PL)            // 13824 words per stage
#define GEMM_SMEM (2 * STG_W * 4)          // 110592 B

struct GemmOp {
    const u32 *Ah, *Al;
    const u32 *Bh[3], *Bl[3];
    const float* bias[3];
    float* Cf[3];
    u32 *Ch[3], *Cl[3];
    int N, K, act, mode, ksplit;           // mode: 0 f32+bias, 1 planes, 2 head planes, 3 raw f32
};

__global__ __launch_bounds__(256, 2) void gemm_mma2(GemmOp op)
{
    extern __shared__ u32 sm[];
    const u32 smb = smem_u32(sm);
    const int z = blockIdx.z;
    const int zb = op.ksplit ? 0 : z;
    const u32* __restrict__ Ah = op.Ah;
    const u32* __restrict__ Al = op.Al;
    const u32* __restrict__ Bh = op.Bh[zb];
    const u32* __restrict__ Bl = op.Bl[zb];
    const int N = op.N, K = op.K, act = op.act, mode = op.mode;
    const int Kw = K >> 1;
    const int Keff = op.ksplit ? (K >> 1) : K;
    const int koffw = op.ksplit ? z * (K >> 2) : 0;
    const int nkt = Keff >> 6;

    const int tid = threadIdx.x;
    const int lane = tid & 31, wid = tid >> 5;
    const int wm = wid & 3, wn = wid >> 2;
    const int g = lane >> 2, t = lane & 3;
    const int m0 = blockIdx.y * 128, n0 = blockIdx.x * 64;

    float acc[2][4][4];
#pragma unroll
    for (int mt = 0; mt < 2; mt++)
#pragma unroll
        for (int nt = 0; nt < 4; nt++)
#pragma unroll
            for (int i = 0; i < 4; i++) acc[mt][nt][i] = 0.f;

    const int srow = tid >> 3, sq = tid & 7;   // base row/quad for async copies

    auto issue = [&](int s, int kt) {
        const u32 st = smb + s * (STG_W * 4);
        const int ktw = koffw + kt * 32;
#pragma unroll
        for (int i = 0; i < 4; i++) {
            int row = srow + 32 * i;
            size_t gs = (size_t)(m0 + row) * Kw + ktw + sq * 4;
            u32 sa = st + (row * ASTR + sq * 4) * 4;
            cp16(sa, Ah + gs);
            cp16(sa + A_PL * 4, Al + gs);
        }
#pragma unroll
        for (int i = 0; i < 2; i++) {
            int row = srow + 32 * i;
            size_t gs = (size_t)(n0 + row) * Kw + ktw + sq * 4;
            u32 sa = st + (2 * A_PL + row * ASTR + sq * 4) * 4;
            cp16(sa, Bh + gs);
            cp16(sa + B_PL * 4, Bl + gs);
        }
        asm volatile("cp.async.commit_group;");
    };

    // ldmatrix lane-address offsets (bytes, relative to stage base)
    const int lrow = lane & 15, lhalf = lane >> 4;
    u32 aOff[2];
#pragma unroll
    for (int mt = 0; mt < 2; mt++) {
        int row = wm * 32 + mt * 16 + lrow;
        aOff[mt] = (u32)((row * ASTR + lhalf * 4) * 4);
    }
    const int lr = lane & 7, lgr = lane >> 3;
    u32 bOff[2];
#pragma unroll
    for (int p = 0; p < 2; p++) {
        int nrow = wn * 32 + (2 * p + (lgr >> 1)) * 8 + lr;
        bOff[p] = (u32)((2 * A_PL + nrow * ASTR + (lgr & 1) * 4) * 4);
    }

    issue(0, 0);
    for (int kt = 0; kt < nkt; kt++) {
        asm volatile("cp.async.wait_group 0;");
        __syncthreads();
        if (kt + 1 < nkt) issue((kt + 1) & 1, kt + 1);

        const u32 st = smb + (kt & 1) * (STG_W * 4);
#pragma unroll
        for (int sel = 0; sel < 4; sel++) {
            const u32 kb = sel * 32;                  // 8 words = 32 bytes
            u32 ah[2][4], al[2][4], bhq[2][4], blq[2][4];
#pragma unroll
            for (int mt = 0; mt < 2; mt++) {
                ldm4(ah[mt], st + aOff[mt] + kb);
                ldm4(al[mt], st + aOff[mt] + A_PL * 4 + kb);
            }
#pragma unroll
            for (int p = 0; p < 2; p++) {
                ldm4(bhq[p], st + bOff[p] + kb);
                ldm4(blq[p], st + bOff[p] + B_PL * 4 + kb);
            }
            // term-major issue order: 8 independent accumulators between
            // successive MMAs on the same acc -> no RAW stalls.
#pragma unroll
            for (int term = 0; term < 3; term++) {
#pragma unroll
                for (int p = 0; p < 2; p++) {
#pragma unroll
                    for (int sub = 0; sub < 2; sub++) {
                        int nt = 2 * p + sub;
                        u32 bhf[2] = {bhq[p][2 * sub], bhq[p][2 * sub + 1]};
                        u32 blf[2] = {blq[p][2 * sub], blq[p][2 * sub + 1]};
#pragma unroll
                        for (int mt = 0; mt < 2; mt++) {
                            if (term == 0)      MMA16816(acc[mt][nt], ah[mt], bhf);
                            else if (term == 1) MMA16816(acc[mt][nt], ah[mt], blf);
                            else                MMA16816(acc[mt][nt], al[mt], bhf);
                        }
                    }
                }
            }
        }
    }

    // epilogue
    const float* bias = op.bias[zb];
    float* Cf = op.Cf[z];
    u32* Ch = op.Ch[z];
    u32* Cl = op.Cl[z];
#pragma unroll
    for (int mt = 0; mt < 2; mt++) {
#pragma unroll
        for (int nt = 0; nt < 4; nt++) {
            int col = n0 + wn * 32 + nt * 8 + 2 * t;
            float bia0 = 0.f, bia1 = 0.f;
            if (mode != 3) { bia0 = bias[col]; bia1 = bias[col + 1]; }
#pragma unroll
            for (int half = 0; half < 2; half++) {
                int row = m0 + wm * 32 + mt * 16 + g + half * 8;
                float c0 = acc[mt][nt][half * 2 + 0] + bia0;
                float c1 = acc[mt][nt][half * 2 + 1] + bia1;
                if (act == 1 && mode != 3) {
                    c0 = c0 / (1.f + expf(-c0)); c1 = c1 / (1.f + expf(-c1));
                } else if (act == 2 && mode != 3) {
                    c0 = c0 * normcdff(c0); c1 = c1 * normcdff(c1);
                }
                if (mode == 0 || mode == 3) {
                    *(float2*)(Cf + (size_t)row * N + col) = make_float2(c0, c1);
                } else {
                    u32 h, l; split_pair(c0, c1, h, l);
                    size_t w;
                    if (mode == 2)
                        w = (size_t)((row >> 8) * 16 + (col >> 5)) * 4096
                          + (size_t)(row & 255) * 16 + ((col & 31) >> 1);
                    else
                        w = ((size_t)row * N + col) >> 1;
                    Ch[w] = h; Cl[w] = l;
                }
            }
        }
    }
}

// ---------------- combine split-K partials + bias + silu -> planes -----------
__global__ __launch_bounds__(256) void combine_silu(
    const float* __restrict__ p0, const float* __restrict__ p1,
    const float* __restrict__ bias, u32* __restrict__ oh, u32* __restrict__ ol)
{
    int i = blockIdx.x * 256 + threadIdx.x;       // word over [ROWS][256]
    int col = (i & 255) * 2;
    float2 a = ((const float2*)p0)[i];
    float2 b = ((const float2*)p1)[i];
    float c0 = a.x + b.x + bias[col];
    float c1 = a.y + b.y + bias[col + 1];
    c0 = c0 / (1.f + expf(-c0));
    c1 = c1 / (1.f + expf(-c1));
    u32 h, l; split_pair(c0, c1, h, l);
    oh[i] = h; ol[i] = l;
}

// ---------------- fused multi-scale attention via HMMA -----------------------
// Grid (bh, tile). K/V fragments via ldmatrix (16B-aligned strides).
#define KSTR 20     // words per K row (80 B, 16B multiple)
#define VSTR 132    // words per vT row (528 B, 16B multiple)

__global__ __launch_bounds__(256) void attn_mma(
    const u32* __restrict__ qh, const u32* __restrict__ ql,
    const u32* __restrict__ kh, const u32* __restrict__ kl,
    const u32* __restrict__ vh, const u32* __restrict__ vl,
    const float* __restrict__ bias, const u32* __restrict__ allow,
    u32* __restrict__ m2h, u32* __restrict__ m2l)
{
    extern __shared__ u32 smemU[];
    u32* Ksh = smemU;                         // [256][KSTR]
    u32* Ksl = Ksh + 256 * KSTR;
    u32* vTh = Ksl + 256 * KSTR;              // [32][VSTR]
    u32* vTl = vTh + 32 * VSTR;
    float* comb = (float*)(vTl + 32 * VSTR);  // [2][64][33]
    float* psum = comb + 2 * 64 * 33;

    const int bh = blockIdx.x;
    const int b = bh >> 4;
    const int hh = bh & 15;
    const int tid = threadIdx.x;
    const int lane = tid & 31;
    const int w = tid >> 5;
    const int g = lane >> 2, t = lane & 3;
    const int wm = w >> 1, wn = w & 1;
    const size_t base = (size_t)bh * 4096;

#pragma unroll
    for (int it = 0; it < 16; it++) {
        int idx = tid + 256 * it;
        int row = idx >> 4, wd = idx & 15;
        Ksh[row * KSTR + wd] = kh[base + idx];
        Ksl[row * KSTR + wd] = kl[base + idx];
    }
    {
        const unsigned short* vhp = (const unsigned short*)vh + base * 2;
        const unsigned short* vlp = (const unsigned short*)vl + base * 2;
#pragma unroll
        for (int it = 0; it < 16; it++) {
            int idx = tid + 256 * it;
            int n = idx & 31, wk = idx >> 5;
            vTh[n * VSTR + wk] = (u32)vhp[(2 * wk) * 32 + n]
                               | ((u32)vhp[(2 * wk + 1) * 32 + n] << 16);
            vTl[n * VSTR + wk] = (u32)vlp[(2 * wk) * 32 + n]
                               | ((u32)vlp[(2 * wk + 1) * 32 + n] << 16);
        }
    }
    __syncthreads();

    // ldmatrix lane offsets (all 16B aligned: KSTR*4=80, VSTR*4=528)
    const int lr = lane & 7, lgr = lane >> 3;
    const u32 KshA = smem_u32(Ksh), KslA = smem_u32(Ksl);
    const u32 vThA = smem_u32(vTh), vTlA = smem_u32(vTl);
    u32 qkOff[8];
#pragma unroll
    for (int q = 0; q < 8; q++) {
        int row = wn * 128 + q * 16 + (lgr >> 1) * 8 + lr;
        qkOff[q] = (u32)((row * KSTR + (lgr & 1) * 4) * 4);
    }
    u32 pvOff[2];
#pragma unroll
    for (int v = 0; v < 2; v++) {
        int n = v * 16 + (lgr >> 1) * 8 + lr;
        pvOff[v] = (u32)((n * VSTR + (lgr & 1) * 4) * 4);
    }

    const float scale = 0.17677669529663687f;
    const int tile = blockIdx.y;
    {
        const int r0 = tile * 64 + wm * 16 + g;

        float acc[16][4];
#pragma unroll
        for (int nt = 0; nt < 16; nt++)
#pragma unroll
            for (int i = 0; i < 4; i++) acc[nt][i] = 0.f;

#pragma unroll
        for (int kc = 0; kc < 2; kc++) {
            int w0 = kc * 8 + t;
            u32 ah[4], al[4];
            ah[0] = qh[base + (size_t)r0 * 16 + w0];
            ah[1] = qh[base + (size_t)(r0 + 8) * 16 + w0];
            ah[2] = qh[base + (size_t)r0 * 16 + w0 + 4];
            ah[3] = qh[base + (size_t)(r0 + 8) * 16 + w0 + 4];
            al[0] = ql[base + (size_t)r0 * 16 + w0];
            al[1] = ql[base + (size_t)(r0 + 8) * 16 + w0];
            al[2] = ql[base + (size_t)r0 * 16 + w0 + 4];
            al[3] = ql[base + (size_t)(r0 + 8) * 16 + w0 + 4];
#pragma unroll
            for (int q = 0; q < 8; q++) {
                u32 bh4[4], bl4[4];
                ldm4(bh4, KshA + qkOff[q] + kc * 32);
                ldm4(bl4, KslA + qkOff[q] + kc * 32);
                u32 bhf0[2] = {bh4[0], bh4[1]}, blf0[2] = {bl4[0], bl4[1]};
                u32 bhf1[2] = {bh4[2], bh4[3]}, blf1[2] = {bl4[2], bl4[3]};
                MMA16816(acc[2 * q],     ah, bhf0);
                MMA16816(acc[2 * q + 1], ah, bhf1);
                MMA16816(acc[2 * q],     ah, blf0);
                MMA16816(acc[2 * q + 1], ah, blf1);
                MMA16816(acc[2 * q],     al, bhf0);
                MMA16816(acc[2 * q + 1], al, bhf1);
            }
        }

        for (int ks = 0; ks < 4; ks++) {
            float acc2[4][4];
#pragma unroll
            for (int vn = 0; vn < 4; vn++)
#pragma unroll
                for (int i = 0; i < 4; i++) acc2[vn][i] = 0.f;
            float s0 = 0.f, s1 = 0.f;

            const size_t abase = ((size_t)(b * 4 + ks) * 256);
            u32 aw0[4], aw1[4];
#pragma unroll
            for (int ww = 0; ww < 4; ww++) {
                aw0[ww] = allow[(abase + r0) * 8 + wn * 4 + ww];
                aw1[ww] = allow[(abase + r0 + 8) * 8 + wn * 4 + ww];
            }
            const float* bp0 = bias + (abase + r0) * 256 + wn * 128;
            const float* bp1 = bias + (abase + r0 + 8) * 256 + wn * 128;

#pragma unroll
            for (int kc = 0; kc < 8; kc++) {
                u32 pa_h[4], pa_l[4];
#pragma unroll
                for (int sub = 0; sub < 2; sub++) {
                    int nt = 2 * kc + sub;
                    int coff = nt * 8 + 2 * t;
                    float2 bv0 = *(const float2*)(bp0 + coff);
                    float2 bv1 = *(const float2*)(bp1 + coff);
                    int wi = kc >> 1;
                    int bit = (nt & 3) * 8 + 2 * t;
                    float p00 = 0.f, p01 = 0.f, p10 = 0.f, p11 = 0.f;
                    if ((aw0[wi] >> bit) & 1)
                        p00 = __expf(fmaf(acc[nt][0], scale, bv0.x));
                    if ((aw0[wi] >> (bit + 1)) & 1)
                        p01 = __expf(fmaf(acc[nt][1], scale, bv0.y));
                    if ((aw1[wi] >> bit) & 1)
                        p10 = __expf(fmaf(acc[nt][2], scale, bv1.x));
                    if ((aw1[wi] >> (bit + 1)) & 1)
                        p11 = __expf(fmaf(acc[nt][3], scale, bv1.y));
                    s0 += p00 + p01;
                    s1 += p10 + p11;
                    split_pair(p00, p01, pa_h[sub * 2], pa_l[sub * 2]);
                    split_pair(p10, p11, pa_h[sub * 2 + 1], pa_l[sub * 2 + 1]);
                }
                int kcg = wn * 8 + kc;
#pragma unroll
                for (int v = 0; v < 2; v++) {
                    u32 vh4[4], vl4[4];
                    ldm4(vh4, vThA + pvOff[v] + kcg * 32);
                    ldm4(vl4, vTlA + pvOff[v] + kcg * 32);
                    u32 vhf0[2] = {vh4[0], vh4[1]}, vlf0[2] = {vl4[0], vl4[1]};
                    u32 vhf1[2] = {vh4[2], vh4[3]}, vlf1[2] = {vl4[2], vl4[3]};
                    MMA16816(acc2[2 * v],     pa_h, vhf0);
                    MMA16816(acc2[2 * v + 1], pa_h, vhf1);
                    MMA16816(acc2[2 * v],     pa_h, vlf0);
                    MMA16816(acc2[2 * v + 1], pa_h, vlf1);
                    MMA16816(acc2[2 * v],     pa_l, vhf0);
                    MMA16816(acc2[2 * v + 1], pa_l, vhf1);
                }
            }

            s0 += __shfl_xor_sync(0xffffffffu, s0, 1);
            s0 += __shfl_xor_sync(0xffffffffu, s0, 2);
            s1 += __shfl_xor_sync(0xffffffffu, s1, 1);
            s1 += __shfl_xor_sync(0xffffffffu, s1, 2);
            if (t == 0) {
                psum[(wm * 16 + g) * 2 + wn] = s0;
                psum[(wm * 16 + g + 8) * 2 + wn] = s1;
            }
            float* cw = comb + wn * 64 * 33;
#pragma unroll
            for (int vn = 0; vn < 4; vn++) {
                int c = vn * 8 + 2 * t;
                cw[(wm * 16 + g) * 33 + c]     = acc2[vn][0];
                cw[(wm * 16 + g) * 33 + c + 1] = acc2[vn][1];
                cw[(wm * 16 + g + 8) * 33 + c]     = acc2[vn][2];
                cw[(wm * 16 + g + 8) * 33 + c + 1] = acc2[vn][3];
            }
            __syncthreads();
            // msg2 row = b*256 + np, np = (ks*16+h)*4 + (d>>3); col = (d&7)*256 + n
            for (int i = tid; i < 1024; i += 256) {
                int pr = i >> 5;
                int c = i & 31;
                int rl0 = 2 * pr, rl1 = rl0 + 1;
                float v0 = (comb[rl0 * 33 + c] + comb[64 * 33 + rl0 * 33 + c])
                         / (psum[rl0 * 2] + psum[rl0 * 2 + 1]);
                float v1 = (comb[rl1 * 33 + c] + comb[64 * 33 + rl1 * 33 + c])
                         / (psum[rl1 * 2] + psum[rl1 * 2 + 1]);
                int row0 = tile * 64 + rl0;
                int np = (((ks << 4) | hh) << 2) | (c >> 3);
                size_t wI = ((size_t)b * 256 + np) * 1024
                          + ((c & 7) << 7) + (row0 >> 1);
                u32 hw, lw; split_pair(v0, v1, hw, lw);
                m2h[wI] = hw; m2l[wI] = lw;
            }
            __syncthreads();
        }
    }
}

// ---------------- residual + LayerNorm (2 partials + bias) -------------------
__global__ __launch_bounds__(256) void ln_kernel2(
    const float* __restrict__ a0, const float* __restrict__ a1,
    const float* __restrict__ bb, const float* __restrict__ res,
    const float* __restrict__ g, const float* __restrict__ be,
    float* __restrict__ out, u32* __restrict__ oh, u32* __restrict__ ol)
{
    const int row = blockIdx.x, tid = threadIdx.x;
    __shared__ float sred[8];
    float2 av = ((const float2*)(a0 + (size_t)row * 512))[tid];
    float2 a2 = ((const float2*)(a1 + (size_t)row * 512))[tid];
    float2 rv = ((const float2*)(res + (size_t)row * 512))[tid];
    float b0 = bb[2 * tid], b1 = bb[2 * tid + 1];
    float v0 = av.x + a2.x + b0 + rv.x;
    float v1 = av.y + a2.y + b1 + rv.y;

    float s = v0 + v1;
#pragma unroll
    for (int o = 16; o > 0; o >>= 1) s += __shfl_xor_sync(0xffffffffu, s, o);
    if ((tid & 31) == 0) sred[tid >> 5] = s;
    __syncthreads();
    float mean = 0.f;
#pragma unroll
    for (int i = 0; i < 8; i++) mean += sred[i];
    mean *= (1.f / 512.f);
    __syncthreads();

    float d0 = v0 - mean, d1 = v1 - mean;
    float vs = d0 * d0 + d1 * d1;
#pragma unroll
    for (int o = 16; o > 0; o >>= 1) vs += __shfl_xor_sync(0xffffffffu, vs, o);
    if ((tid & 31) == 0) sred[tid >> 5] = vs;
    __syncthreads();
    float var = 0.f;
#pragma unroll
    for (int i = 0; i < 8; i++) var += sred[i];
    var *= (1.f / 512.f);
    float inv = rsqrtf(var + 1e-6f);

    float2 gv = ((const float2*)g)[tid];
    float2 bv = ((const float2*)be)[tid];
    float o0 = d0 * inv * gv.x + bv.x;
    float o1 = d1 * inv * gv.y + bv.y;
    ((float2*)(out + (size_t)row * 512))[tid] = make_float2(o0, o1);
    if (oh) {
        u32 h, l; split_pair(o0, o1, h, l);
        oh[(size_t)row * 256 + tid] = h;
        ol[(size_t)row * 256 + tid] = l;
    }
}

// ---------------- launch ------------------------------------------------------
extern "C" void kernel_launch(void* const* d_in, const int* in_sizes, int n_in,
                              void* d_out, int out_size)
{
    const float* x         = (const float*)d_in[0];
    const float* dist      = (const float*)d_in[1];
    const float* dist_bar  = (const float*)d_in[2];
    const float* attn_bias = (const float*)d_in[3];
    const int*   mask      = (const int*)d_in[4];
    int wo = (n_in >= 24 && in_sizes[5] == 1) ? 6 : 5;
    const float* Wq  = (const float*)d_in[wo + 0];
    const float* bq  = (const float*)d_in[wo + 1];
    const float* Wk  = (const float*)d_in[wo + 2];
    const float* bk  = (const float*)d_in[wo + 3];
    const float* Wv  = (const float*)d_in[wo + 4];
    const float* bv  = (const float*)d_in[wo + 5];
    const float* W1  = (const float*)d_in[wo + 6];
    const float* b1  = (const float*)d_in[wo + 7];
    const float* W2  = (const float*)d_in[wo + 8];
    const float* b2  = (const float*)d_in[wo + 9];
    const float* g1  = (const float*)d_in[wo + 10];
    const float* be1 = (const float*)d_in[wo + 11];
    const float* Wf1 = (const float*)d_in[wo + 12];
    const float* bf1 = (const float*)d_in[wo + 13];
    const float* Wf2 = (const float*)d_in[wo + 14];
    const float* bf2 = (const float*)d_in[wo + 15];
    const float* g2  = (const float*)d_in[wo + 16];
    const float* be2 = (const float*)d_in[wo + 17];
    float* out = (float*)d_out;

#define SYM(p, s) cudaGetSymbolAddress((void**)&p, s)
    u32 *xw_h, *xw_l, *wqT_h, *wqT_l, *wkT_h, *wkT_l, *wvT_h, *wvT_l;
    u32 *w1T_h, *w1T_l, *w2T_h, *w2T_l, *wf1T_h, *wf1T_l, *wf2T_h, *wf2T_l;
    u32 *qp_h, *qp_l, *kp_h, *kp_l, *vp_h, *vp_l;
    u32 *m2_h, *m2_l, *h1_h, *h1_l, *y_h, *y_l, *f1_h, *f1_l, *allow;
    float *t, *t2, *y;
    SYM(xw_h, g_xw_h); SYM(xw_l, g_xw_l);
    SYM(wqT_h, g_wqT_h); SYM(wqT_l, g_wqT_l);
    SYM(wkT_h, g_wkT_h); SYM(wkT_l, g_wkT_l);
    SYM(wvT_h, g_wvT_h); SYM(wvT_l, g_wvT_l);
    SYM(w1T_h, g_w1T_h); SYM(w1T_l, g_w1T_l);
    SYM(w2T_h, g_w2T_h); SYM(w2T_l, g_w2T_l);
    SYM(wf1T_h, g_wf1T_h); SYM(wf1T_l, g_wf1T_l);
    SYM(wf2T_h, g_wf2T_h); SYM(wf2T_l, g_wf2T_l);
    SYM(qp_h, g_qp_h); SYM(qp_l, g_qp_l);
    SYM(kp_h, g_kp_h); SYM(kp_l, g_kp_l);
    SYM(vp_h, g_vp_h); SYM(vp_l, g_vp_l);
    SYM(m2_h, g_m2_h); SYM(m2_l, g_m2_l);
    SYM(h1_h, g_h1_h); SYM(h1_l, g_h1_l);
    SYM(y_h, g_y_h); SYM(y_l, g_y_l);
    SYM(f1_h, g_f1_h); SYM(f1_l, g_f1_l);
    SYM(allow, g_allow);
    SYM(t, g_t); SYM(t2, g_t2); SYM(y, g_y);

    const int smem_attn = (256 * KSTR + 32 * VSTR) * 2 * 4 + (2 * 64 * 33 + 128) * 4;
    static int attrSet = 0;
    if (!attrSet) {
        cudaFuncSetAttribute(attn_mma,
                             cudaFuncAttributeMaxDynamicSharedMemorySize, smem_attn);
        cudaFuncSetAttribute(gemm_mma2,
                             cudaFuncAttributeMaxDynamicSharedMemorySize, GEMM_SMEM);
        attrSet = 1;
    }

    dim3 blk(256);

    // merged prep
    PrepArgs pa;
    const float* wsrc[7] = {Wq, Wk, Wv, W1, W2, Wf1, Wf2};
    u32* wdh[7] = {wqT_h, wkT_h, wvT_h, w1T_h, w2T_h, wf1T_h, wf2T_h};
    u32* wdl[7] = {wqT_l, wkT_l, wvT_l, w1T_l, w2T_l, wf1T_l, wf2T_l};
    int wK[7] = {512, 512, 512, 2048, 512, 512, 2048};
    int wN[7] = {512, 512, 512, 512, 512, 2048, 512};
    int tbase[8] = {0, 256, 512, 768, 1792, 2048, 3072, 4096};
    for (int i = 0; i < 7; i++) {
        pa.wsrc[i] = wsrc[i]; pa.wdh[i] = wdh[i]; pa.wdl[i] = wdl[i];
        pa.wK[i] = wK[i]; pa.wN[i] = wN[i];
    }
    for (int i = 0; i < 8; i++) pa.tbase[i] = tbase[i];
    pa.x = x; pa.xh = xw_h; pa.xl = xw_l;
    pa.mask = mask; pa.dist = dist; pa.dbar = dist_bar; pa.allow = allow;
    prep_all<<<6208, blk>>>(pa);

    auto mkop = [](const u32* Ah, const u32* Al, int N, int K, int act,
                   int mode, int ksplit) {
        GemmOp o;
        o.Ah = Ah; o.Al = Al; o.N = N; o.K = K; o.act = act;
        o.mode = mode; o.ksplit = ksplit;
        for (int i = 0; i < 3; i++) {
            o.Bh[i] = nullptr; o.Bl[i] = nullptr; o.bias[i] = nullptr;
            o.Cf[i] = nullptr; o.Ch[i] = nullptr; o.Cl[i] = nullptr;
        }
        return o;
    };

    // QKV fused: z = {q,k,v}
    {
        GemmOp o = mkop(xw_h, xw_l, 512, 512, 0, 2, 0);
        o.Bh[0] = wqT_h; o.Bl[0] = wqT_l; o.bias[0] = bq; o.Ch[0] = qp_h; o.Cl[0] = qp_l;
        o.Bh[1] = wkT_h; o.Bl[1] = wkT_l; o.bias[1] = bk; o.Ch[1] = kp_h; o.Cl[1] = kp_l;
        o.Bh[2] = wvT_h; o.Bl[2] = wvT_l; o.bias[2] = bv; o.Ch[2] = vp_h; o.Cl[2] = vp_l;
        gemm_mma2<<<dim3(8, 16, 3), blk, GEMM_SMEM>>>(o);
    }

    attn_mma<<<dim3(BH, 4), blk, smem_attn>>>(qp_h, qp_l, kp_h, kp_l, vp_h, vp_l,
                                              attn_bias, allow, m2_h, m2_l);

    // W1 split-K=2 -> raw partials -> combine(silu) -> h1 planes
    {
        GemmOp o = mkop(m2_h, m2_l, 512, 2048, 1, 3, 1);
        o.Bh[0] = w1T_h; o.Bl[0] = w1T_l;
        o.Cf[0] = t; o.Cf[1] = t2;
        gemm_mma2<<<dim3(8, 16, 2), blk, GEMM_SMEM>>>(o);
    }
    combine_silu<<<(ROWS * 256) / 256, blk>>>(t, t2, b1, h1_h, h1_l);

    // W2 split-K=2 -> raw partials -> ln2
    {
        GemmOp o = mkop(h1_h, h1_l, 512, 512, 0, 3, 1);
        o.Bh[0] = w2T_h; o.Bl[0] = w2T_l;
        o.Cf[0] = t; o.Cf[1] = t2;
        gemm_mma2<<<dim3(8, 16, 2), blk, GEMM_SMEM>>>(o);
    }
    ln_kernel2<<<ROWS, blk>>>(t, t2, b2, x, g1, be1, y, y_h, y_l);

    // FFN1 (N=2048, 512 blocks) -> gelu planes
    {
        GemmOp o = mkop(y_h, y_l, FFN, 512, 2, 1, 0);
        o.Bh[0] = wf1T_h; o.Bl[0] = wf1T_l; o.bias[0] = bf1;
        o.Ch[0] = f1_h; o.Cl[0] = f1_l;
        gemm_mma2<<<dim3(32, 16, 1), blk, GEMM_SMEM>>>(o);
    }

    // FFN2 split-K=2 -> raw partials -> ln2
    {
        GemmOp o = mkop(f1_h, f1_l, 512, 2048, 0, 3, 1);
        o.Bh[0] = wf2T_h; o.Bl[0] = wf2T_l;
        o.Cf[0] = t; o.Cf[1] = t2;
        gemm_mma2<<<dim3(8, 16, 2), blk, GEMM_SMEM>>>(o);
    }
    ln_kernel2<<<ROWS, blk>>>(t, t2, bf2, y, g2, be2, out, nullptr, nullptr);
}